// round 11
// baseline (speedup 1.0000x reference)
#include <cuda_runtime.h>
#include <cuda_bf16.h>
#include <cuda_fp16.h>
#include <cstdint>

// Problem constants
#define BB 2
#define NN 2048
#define HH 16
#define DH 64
#define DD 1024          // HH*DH
#define D3 3072          // 3*DD
#define MM 4096          // BB*NN

// Scratch: QKV laid out [part(q/k/v)][B][H][N][Dh], fp32
__device__ float g_qkv[3u * BB * HH * NN * DH];
// GEMM operands: fp16 hi/lo, b32-pair order per k16 block: [p0,p4,p1,p5,p2,p6,p3,p7]
__device__ __half g_xhi[(size_t)MM * DD];
__device__ __half g_xlo[(size_t)MM * DD];
__device__ __half g_whiT[(size_t)D3 * DD];   // pre-scaled x32
__device__ __half g_wloT[(size_t)D3 * DD];
// Attention operands (fp16 hi/lo, pair-permuted)
__device__ __half g_qh[(size_t)BB * HH * NN * DH];   // [bh][n][d] (unscaled)
__device__ __half g_ql[(size_t)BB * HH * NN * DH];
__device__ __half g_kh[(size_t)BB * HH * NN * DH];   // [bh][n][d]
__device__ __half g_kl[(size_t)BB * HH * NN * DH];
__device__ __half g_vh[(size_t)BB * HH * DH * NN];   // [bh][d][n] (transposed)
__device__ __half g_vl[(size_t)BB * HH * DH * NN];

// ---------------------------------------------------------------------------
// helpers
// ---------------------------------------------------------------------------
#define CP_ASYNC16(dst_u32, gptr)                                              \
    asm volatile("cp.async.cg.shared.global [%0], [%1], 16;"                    \
                 :: "r"(dst_u32), "l"(__cvta_generic_to_global(gptr)))
#define CP_COMMIT() asm volatile("cp.async.commit_group;" ::: "memory")
#define CP_WAIT1()  asm volatile("cp.async.wait_group 1;" ::: "memory")
#define CP_WAIT0()  asm volatile("cp.async.wait_group 0;" ::: "memory")

__device__ __forceinline__ uint32_t smem_u32(const void* p) {
    uint32_t a;
    asm("{ .reg .u64 t; cvta.to.shared.u64 t, %1; cvt.u32.u64 %0, t; }"
        : "=r"(a) : "l"(p));
    return a;
}

// mma.sync m16n8k16 fp16 inputs, fp32 accumulate: d += a * b
__device__ __forceinline__ void mma_f16f32(float* d,
                                           uint32_t a0, uint32_t a1, uint32_t a2, uint32_t a3,
                                           uint32_t b0, uint32_t b1) {
    asm volatile(
        "mma.sync.aligned.m16n8k16.row.col.f32.f16.f16.f32 "
        "{%0,%1,%2,%3}, {%4,%5,%6,%7}, {%8,%9}, {%0,%1,%2,%3};"
        : "+f"(d[0]), "+f"(d[1]), "+f"(d[2]), "+f"(d[3])
        : "r"(a0), "r"(a1), "r"(a2), "r"(a3), "r"(b0), "r"(b1));
}

// mma.sync m16n8k16 fp16 inputs, fp16 accumulate (2x rate path): d += a * b
__device__ __forceinline__ void mma_f16f16(uint32_t* d,
                                           uint32_t a0, uint32_t a1, uint32_t a2, uint32_t a3,
                                           uint32_t b0, uint32_t b1) {
    asm volatile(
        "mma.sync.aligned.m16n8k16.row.col.f16.f16.f16.f16 "
        "{%0,%1}, {%2,%3,%4,%5}, {%6,%7}, {%0,%1};"
        : "+r"(d[0]), "+r"(d[1])
        : "r"(a0), "r"(a1), "r"(a2), "r"(a3), "r"(b0), "r"(b1));
}

__device__ __forceinline__ uint32_t pack_f16(float x0, float x1) {
    __half2 h = __floats2half2_rn(x0, x1);
    return *(uint32_t*)&h;
}

// split a float pair into packed fp16 hi and lo words
__device__ __forceinline__ void split2h(float x0, float x1, uint32_t& h, uint32_t& l) {
    __half h0 = __float2half_rn(x0);
    __half h1 = __float2half_rn(x1);
    __half2 hh = __halves2half2(h0, h1);
    h = *(uint32_t*)&hh;
    l = pack_f16(x0 - __half2float(h0), x1 - __half2float(h1));
}

__device__ __forceinline__ int dpos8(int p) {   // dest slot of source pair p in 8-block
    return ((p & 3) << 1) | (p >> 2);
}

// ---------------------------------------------------------------------------
// GEMM prep: fp16 hi/lo split, pair-permutation (+ transpose & x32 for W)
// ---------------------------------------------------------------------------
__global__ __launch_bounds__(256)
void prep_x(const float* __restrict__ X)
{
    const size_t n16 = (size_t)MM * DD / 16;
    for (size_t i = (size_t)blockIdx.x * 256 + threadIdx.x; i < n16;
         i += (size_t)gridDim.x * 256) {
        const float* src = X + i * 16;
        float s[16];
        *(float4*)(s)      = ((const float4*)src)[0];
        *(float4*)(s + 4)  = ((const float4*)src)[1];
        *(float4*)(s + 8)  = ((const float4*)src)[2];
        *(float4*)(s + 12) = ((const float4*)src)[3];
        const int pp[8] = {0, 4, 1, 5, 2, 6, 3, 7};
        uint32_t ph[8], pl[8];
#pragma unroll
        for (int d = 0; d < 8; ++d) {
            int p = pp[d];
            split2h(s[2 * p], s[2 * p + 1], ph[d], pl[d]);
        }
        uint32_t* dh = (uint32_t*)g_xhi + i * 8;
        uint32_t* dl = (uint32_t*)g_xlo + i * 8;
        *(uint4*)(dh)     = make_uint4(ph[0], ph[1], ph[2], ph[3]);
        *(uint4*)(dh + 4) = make_uint4(ph[4], ph[5], ph[6], ph[7]);
        *(uint4*)(dl)     = make_uint4(pl[0], pl[1], pl[2], pl[3]);
        *(uint4*)(dl + 4) = make_uint4(pl[4], pl[5], pl[6], pl[7]);
    }
}

__device__ __forceinline__ int kperm16(int k) {
    int p = (k >> 1) & 7;
    int d = ((p & 3) << 1) | (p >> 2);
    return (k & ~15) | (d * 2) | (k & 1);
}

__global__ __launch_bounds__(256)
void prep_w(const float* __restrict__ W)
{
    __shared__ float t[32][33];
    const int n0 = blockIdx.x * 32;
    const int k0 = blockIdx.y * 32;
    const int tx = threadIdx.x, ty = threadIdx.y;   // (32, 8)
#pragma unroll
    for (int rr = 0; rr < 32; rr += 8)
        t[ty + rr][tx] = W[(size_t)(k0 + ty + rr) * D3 + n0 + tx];
    __syncthreads();
#pragma unroll
    for (int rr = 0; rr < 32; rr += 8) {
        float v  = t[tx][ty + rr] * 32.0f;    // scale to keep lo in normal range
        __half h = __float2half_rn(v);
        __half l = __float2half_rn(v - __half2float(h));
        size_t base = (size_t)(n0 + ty + rr) * DD + k0 + kperm16(tx);
        g_whiT[base] = h;
        g_wloT[base] = l;
    }
}

// ---------------------------------------------------------------------------
// fp16x3 QKV GEMM via mma.sync m16n8k16 (main term f32-acc, corrections f16-acc).
// CTA 128x128, 256 threads, k-chunk 32, cp.async double buffer, ROWW=20 pad.
// ---------------------------------------------------------------------------
#define ROWW 20
#define OAHI 0
#define OALO 2560
#define OBHI 5120
#define OBLO 7680
#define ST_B32 10240
#define GEMM_SMEM_TOTAL (2 * ST_B32 * 4)

__device__ __forceinline__ void gemm_load(int kt, uint32_t st_u32,
                                          int m0, int n0, int tid)
{
    const int k0 = kt * 32;
#pragma unroll
    for (int it = 0; it < 2; ++it) {
        int j   = it * 256 + tid;
        int row = j >> 2;
        int q   = (j & 3);
        uint32_t doff = (uint32_t)(row * ROWW + q * 4) * 4;
        CP_ASYNC16(st_u32 + OAHI * 4 + doff, g_xhi  + (size_t)(m0 + row) * DD + k0 + q * 8);
        CP_ASYNC16(st_u32 + OALO * 4 + doff, g_xlo  + (size_t)(m0 + row) * DD + k0 + q * 8);
        CP_ASYNC16(st_u32 + OBHI * 4 + doff, g_whiT + (size_t)(n0 + row) * DD + k0 + q * 8);
        CP_ASYNC16(st_u32 + OBLO * 4 + doff, g_wloT + (size_t)(n0 + row) * DD + k0 + q * 8);
    }
}

__global__ __launch_bounds__(256, 1)
void qkv_gemm_mma()
{
    extern __shared__ float sm[];
    const int tid   = threadIdx.x;
    const int wid   = tid >> 5;
    const int lane  = tid & 31;
    const int warpm = wid & 3;
    const int warpn = wid >> 2;
    const int c     = lane & 3;
    const int g     = lane >> 2;
    const int n0    = blockIdx.x * 128;
    const int m0    = blockIdx.y * 128;

    const uint32_t* st[2] = {(const uint32_t*)sm, (const uint32_t*)sm + ST_B32};
    uint32_t stu[2] = {smem_u32(sm), smem_u32(sm + ST_B32)};

    float acc[2][8][4];
    uint32_t accC[2][8][2];
#pragma unroll
    for (int mt = 0; mt < 2; ++mt)
#pragma unroll
        for (int nt = 0; nt < 8; ++nt) {
#pragma unroll
            for (int v = 0; v < 4; ++v) acc[mt][nt][v] = 0.0f;
            accC[mt][nt][0] = 0u; accC[mt][nt][1] = 0u;
        }

    gemm_load(0, stu[0], m0, n0, tid); CP_COMMIT();
    gemm_load(1, stu[1], m0, n0, tid); CP_COMMIT();

    for (int kt = 0; kt < 32; ++kt) {
        const int buf = kt & 1;
        if (kt < 30) { CP_WAIT1(); } else { CP_WAIT0(); }
        __syncthreads();

        const uint32_t* S = st[buf];
#pragma unroll
        for (int ks = 0; ks < 2; ++ks) {
            const int kc = ks * 8 + 2 * c;
            uint2 ah[2][2], al[2][2];
#pragma unroll
            for (int mt = 0; mt < 2; ++mt) {
                int rbase = warpm * 32 + mt * 16 + g;
                ah[mt][0] = *(const uint2*)&S[OAHI + rbase * ROWW + kc];
                ah[mt][1] = *(const uint2*)&S[OAHI + (rbase + 8) * ROWW + kc];
                al[mt][0] = *(const uint2*)&S[OALO + rbase * ROWW + kc];
                al[mt][1] = *(const uint2*)&S[OALO + (rbase + 8) * ROWW + kc];
            }
#pragma unroll
            for (int nt = 0; nt < 8; ++nt) {
                int nb = (warpn * 64 + nt * 8 + g) * ROWW + kc;
                uint2 bh = *(const uint2*)&S[OBHI + nb];
                uint2 bl = *(const uint2*)&S[OBLO + nb];
#pragma unroll
                for (int mt = 0; mt < 2; ++mt) {
                    mma_f16f32(acc[mt][nt], ah[mt][0].x, ah[mt][1].x,
                               ah[mt][0].y, ah[mt][1].y, bh.x, bh.y);
                    mma_f16f16(accC[mt][nt], ah[mt][0].x, ah[mt][1].x,
                               ah[mt][0].y, ah[mt][1].y, bl.x, bl.y);
                    mma_f16f16(accC[mt][nt], al[mt][0].x, al[mt][1].x,
                               al[mt][0].y, al[mt][1].y, bh.x, bh.y);
                }
            }
        }
        __syncthreads();
        if (kt + 2 < 32) {
            gemm_load(kt + 2, stu[buf], m0, n0, tid);
            CP_COMMIT();
        }
    }

    // merge corrections + undo W x32 scaling, scatter into g_qkv
    const float osc = 1.0f / 32.0f;
#pragma unroll
    for (int mt = 0; mt < 2; ++mt) {
#pragma unroll
        for (int nt = 0; nt < 8; ++nt) {
            float2 f01 = __half22float2(*(__half2*)&accC[mt][nt][0]);
            float2 f23 = __half22float2(*(__half2*)&accC[mt][nt][1]);
            float r0 = (acc[mt][nt][0] + f01.x) * osc;
            float r1 = (acc[mt][nt][1] + f01.y) * osc;
            float r2 = (acc[mt][nt][2] + f23.x) * osc;
            float r3 = (acc[mt][nt][3] + f23.y) * osc;
            int colg = n0 + warpn * 64 + nt * 8 + 2 * c;
            int part = colg >> 10;
            int pc   = colg & 1023;
            int h    = pc >> 6;
            int dh   = pc & 63;
            int mg0  = m0 + warpm * 32 + mt * 16 + g;
            int b    = mg0 >> 11;
            int seq  = mg0 & 2047;
            float* dst = g_qkv + ((size_t)((part * BB + b) * HH + h) * NN + seq) * DH + dh;
            *(float2*)dst = make_float2(r0, r1);
            *(float2*)(dst + (size_t)8 * DH) = make_float2(r2, r3);
        }
    }
}

// ---------------------------------------------------------------------------
// Attention prep: Q/K rows -> fp16 hi/lo pair-permuted (no prescale);
// V -> transposed [d][n] fp16 hi/lo pair-permuted along n.
// ---------------------------------------------------------------------------
__global__ __launch_bounds__(256)
void prep_attn_qk()
{
    int cidx = blockIdx.x * 256 + threadIdx.x;       // 0..524287
    int row  = cidx >> 2;                            // 0..131071 (Q rows then K rows)
    int ch   = cidx & 3;                             // 16-elem chunk within row
    int part = row >> 16;                            // 0 = Q, 1 = K
    const float* src = g_qkv + (size_t)row * 64 + ch * 16;
    float s[16];
    *(float4*)(s)      = ((const float4*)src)[0];
    *(float4*)(s + 4)  = ((const float4*)src)[1];
    *(float4*)(s + 8)  = ((const float4*)src)[2];
    *(float4*)(s + 12) = ((const float4*)src)[3];
    const int pp[8] = {0, 4, 1, 5, 2, 6, 3, 7};
    uint32_t ph[8], pl[8];
#pragma unroll
    for (int d = 0; d < 8; ++d) {
        int p = pp[d];
        split2h(s[2 * p], s[2 * p + 1], ph[d], pl[d]);
    }
    size_t off = ((size_t)(row & 65535) * 32) + ch * 8;   // b32 units
    uint32_t* dh = (part ? (uint32_t*)g_kh : (uint32_t*)g_qh) + off;
    uint32_t* dl = (part ? (uint32_t*)g_kl : (uint32_t*)g_ql) + off;
    *(uint4*)(dh)     = make_uint4(ph[0], ph[1], ph[2], ph[3]);
    *(uint4*)(dh + 4) = make_uint4(ph[4], ph[5], ph[6], ph[7]);
    *(uint4*)(dl)     = make_uint4(pl[0], pl[1], pl[2], pl[3]);
    *(uint4*)(dl + 4) = make_uint4(pl[4], pl[5], pl[6], pl[7]);
}

__global__ __launch_bounds__(256)
void prep_attn_v()
{
    __shared__ float t[64][65];
    const int n0 = blockIdx.x * 64;
    const int h  = blockIdx.y;
    const int b  = blockIdx.z;
    const int bh = b * HH + h;
    const int tid = threadIdx.x;
    const float* Vg = g_qkv + (size_t)((2 * BB + b) * HH + h) * NN * DH;
#pragma unroll
    for (int i = 0; i < 16; ++i) {
        int lin = i * 256 + tid;
        int r = lin >> 6, d = lin & 63;
        t[r][d] = Vg[(size_t)(n0 + r) * 64 + d];
    }
    __syncthreads();
    const int d  = tid >> 2;
    const int qq = tid & 3;
    uint32_t* vh = (uint32_t*)g_vh + ((size_t)bh * 64 + d) * 1024;
    uint32_t* vl = (uint32_t*)g_vl + ((size_t)bh * 64 + d) * 1024;
#pragma unroll
    for (int i = 0; i < 8; ++i) {
        int npl = qq * 8 + i;
        float p0 = t[2 * npl][d];
        float p1 = t[2 * npl + 1][d];
        uint32_t hw, lw;
        split2h(p0, p1, hw, lw);
        int npg = (n0 >> 1) + npl;
        int dst = (npg & ~7) + dpos8(npg & 7);
        vh[dst] = hw;
        vl[dst] = lw;
    }
}

// ---------------------------------------------------------------------------
// fp16x3 causal flash attention via mma.sync m16n8k16
// (main terms f32-acc, corrections f16-acc). CTA=256 thr, q-tile 128.
// ---------------------------------------------------------------------------
#define ROWK 36
#define ROWV 68
#define KSTG (128 * ROWK)
#define VSTG (64 * ROWV)
#define ATT_SMEM_B32 (4 * KSTG + 4 * VSTG)
#define ATT_SMEM_BYTES (ATT_SMEM_B32 * 4)

__device__ __forceinline__ void attn_load_kv(
    int kt, int s, int tid, uint32_t sbase,
    const __half* khg, const __half* klg,
    const __half* vhg, const __half* vlg)
{
    const uint32_t okh = (s ? KSTG : 0) * 4;
    const uint32_t okl = (2 * KSTG + (s ? KSTG : 0)) * 4;
    const uint32_t ovh = (4 * KSTG + (s ? VSTG : 0)) * 4;
    const uint32_t ovl = (4 * KSTG + 2 * VSTG + (s ? VSTG : 0)) * 4;
#pragma unroll
    for (int it = 0; it < 4; ++it) {
        int idx = it * 256 + tid;
        int row = idx >> 3, ch = idx & 7;
        uint32_t doff = (uint32_t)(row * ROWK + ch * 4) * 4;
        size_t so = (size_t)(kt * 128 + row) * 64 + ch * 8;
        CP_ASYNC16(sbase + okh + doff, khg + so);
        CP_ASYNC16(sbase + okl + doff, klg + so);
    }
#pragma unroll
    for (int it = 0; it < 4; ++it) {
        int idx = it * 256 + tid;
        int row = idx >> 4, ch = idx & 15;
        uint32_t doff = (uint32_t)(row * ROWV + ch * 4) * 4;
        size_t so = (size_t)row * NN + kt * 128 + ch * 8;
        CP_ASYNC16(sbase + ovh + doff, vhg + so);
        CP_ASYNC16(sbase + ovl + doff, vlg + so);
    }
}

__global__ __launch_bounds__(256, 1)
void attn_mma(float* __restrict__ out)
{
    extern __shared__ float smf[];
    uint32_t* su = (uint32_t*)smf;
    const uint32_t sbase = smem_u32(smf);
    const int tid  = threadIdx.x;
    const int w    = tid >> 5;
    const int lane = tid & 31;
    const int g    = lane >> 2;
    const int c    = lane & 3;
    const int qb   = (int)gridDim.x - 1 - blockIdx.x;   // heavy tiles first
    const int h    = blockIdx.y;
    const int b    = blockIdx.z;
    const int bh   = b * HH + h;

    const __half* khg = g_kh + (size_t)bh * NN * DH;
    const __half* klg = g_kl + (size_t)bh * NN * DH;
    const __half* vhg = g_vh + (size_t)bh * DH * NN;
    const __half* vlg = g_vl + (size_t)bh * DH * NN;

    // Q fragments, register-resident for the whole CTA lifetime
    uint2 qfh[4][2], qfl[4][2];
    {
        const uint32_t* qh32 = (const uint32_t*)g_qh;
        const uint32_t* ql32 = (const uint32_t*)g_ql;
        size_t r0 = (size_t)bh * NN + qb * 128 + w * 16 + g;
#pragma unroll
        for (int kd = 0; kd < 4; ++kd) {
            qfh[kd][0] = *(const uint2*)&qh32[r0 * 32 + kd * 8 + 2 * c];
            qfh[kd][1] = *(const uint2*)&qh32[(r0 + 8) * 32 + kd * 8 + 2 * c];
            qfl[kd][0] = *(const uint2*)&ql32[r0 * 32 + kd * 8 + 2 * c];
            qfl[kd][1] = *(const uint2*)&ql32[(r0 + 8) * 32 + kd * 8 + 2 * c];
        }
    }

    float oa[8][4];
    uint2 oc[8];
#pragma unroll
    for (int nt = 0; nt < 8; ++nt) {
#pragma unroll
        for (int v = 0; v < 4; ++v) oa[nt][v] = 0.0f;
        oc[nt] = make_uint2(0u, 0u);
    }
    float m0 = -1e30f, m1 = -1e30f, l0 = 0.0f, l1 = 0.0f;

    attn_load_kv(0, 0, tid, sbase, khg, klg, vhg, vlg);
    CP_COMMIT();
    if (qb >= 1) attn_load_kv(1, 1, tid, sbase, khg, klg, vhg, vlg);
    CP_COMMIT();

    for (int kt = 0; kt <= qb; ++kt) {
        if (kt < qb) { CP_WAIT1(); } else { CP_WAIT0(); }
        __syncthreads();
        const int s = kt & 1;
        const uint32_t* KH = su + (s ? KSTG : 0);
        const uint32_t* KL = su + 2 * KSTG + (s ? KSTG : 0);
        const uint32_t* VH = su + 4 * KSTG + (s ? VSTG : 0);
        const uint32_t* VL = su + 4 * KSTG + 2 * VSTG + (s ? VSTG : 0);

        // S = Q @ K^T: main f32-acc, corrections f16-acc
        float sa[16][4];
        uint2 sc[16];
#pragma unroll
        for (int nt = 0; nt < 16; ++nt) {
            sa[nt][0] = 0.0f; sa[nt][1] = 0.0f; sa[nt][2] = 0.0f; sa[nt][3] = 0.0f;
            sc[nt] = make_uint2(0u, 0u);
        }
#pragma unroll
        for (int kd = 0; kd < 4; ++kd) {
#pragma unroll
            for (int nt = 0; nt < 16; ++nt) {
                int a = (8 * nt + g) * ROWK + 8 * kd + 2 * c;
                uint2 kh2 = *(const uint2*)&KH[a];
                uint2 kl2 = *(const uint2*)&KL[a];
                mma_f16f32(sa[nt], qfh[kd][0].x, qfh[kd][1].x,
                           qfh[kd][0].y, qfh[kd][1].y, kh2.x, kh2.y);
                mma_f16f16((uint32_t*)&sc[nt], qfh[kd][0].x, qfh[kd][1].x,
                           qfh[kd][0].y, qfh[kd][1].y, kl2.x, kl2.y);
                mma_f16f16((uint32_t*)&sc[nt], qfl[kd][0].x, qfl[kd][1].x,
                           qfl[kd][0].y, qfl[kd][1].y, kh2.x, kh2.y);
            }
        }
        // merge corrections + 1/sqrt(Dh) scaling
#pragma unroll
        for (int nt = 0; nt < 16; ++nt) {
            float2 f01 = __half22float2(*(__half2*)&sc[nt].x);
            float2 f23 = __half22float2(*(__half2*)&sc[nt].y);
            sa[nt][0] = (sa[nt][0] + f01.x) * 0.125f;
            sa[nt][1] = (sa[nt][1] + f01.y) * 0.125f;
            sa[nt][2] = (sa[nt][2] + f23.x) * 0.125f;
            sa[nt][3] = (sa[nt][3] + f23.y) * 0.125f;
        }

        // causal mask on the diagonal tile
        if (kt == qb) {
            int r0 = 16 * w + g, r1 = r0 + 8;
#pragma unroll
            for (int nt = 0; nt < 16; ++nt) {
                int c0 = 8 * nt + 2 * c, c1 = c0 + 1;
                if (c0 > r0) sa[nt][0] = -1e30f;
                if (c1 > r0) sa[nt][1] = -1e30f;
                if (c0 > r1) sa[nt][2] = -1e30f;
                if (c1 > r1) sa[nt][3] = -1e30f;
            }
        }

        // warp-local online softmax
        float mx0 = -1e30f, mx1 = -1e30f;
#pragma unroll
        for (int nt = 0; nt < 16; ++nt) {
            mx0 = fmaxf(mx0, fmaxf(sa[nt][0], sa[nt][1]));
            mx1 = fmaxf(mx1, fmaxf(sa[nt][2], sa[nt][3]));
        }
        mx0 = fmaxf(mx0, __shfl_xor_sync(0xffffffffu, mx0, 1));
        mx0 = fmaxf(mx0, __shfl_xor_sync(0xffffffffu, mx0, 2));
        mx1 = fmaxf(mx1, __shfl_xor_sync(0xffffffffu, mx1, 1));
        mx1 = fmaxf(mx1, __shfl_xor_sync(0xffffffffu, mx1, 2));
        float mn0 = fmaxf(m0, mx0), mn1 = fmaxf(m1, mx1);
        float cr0 = __expf(m0 - mn0), cr1 = __expf(m1 - mn1);
        m0 = mn0; m1 = mn1;
        float rs0 = 0.0f, rs1 = 0.0f;
#pragma unroll
        for (int nt = 0; nt < 16; ++nt) {
            sa[nt][0] = __expf(sa[nt][0] - mn0); rs0 += sa[nt][0];
            sa[nt][1] = __expf(sa[nt][1] - mn0); rs0 += sa[nt][1];
            sa[nt][2] = __expf(sa[nt][2] - mn1); rs1 += sa[nt][2];
            sa[nt][3] = __expf(sa[nt][3] - mn1); rs1 += sa[nt][3];
        }
        rs0 += __shfl_xor_sync(0xffffffffu, rs0, 1);
        rs0 += __shfl_xor_sync(0xffffffffu, rs0, 2);
        rs1 += __shfl_xor_sync(0xffffffffu, rs1, 1);
        rs1 += __shfl_xor_sync(0xffffffffu, rs1, 2);
        l0 = l0 * cr0 + rs0;
        l1 = l1 * cr1 + rs1;
#pragma unroll
        for (int nt = 0; nt < 8; ++nt) {
            oa[nt][0] *= cr0; oa[nt][1] *= cr0;
            oa[nt][2] *= cr1; oa[nt][3] *= cr1;
        }

        // O += P @ V: main f32-acc, corrections f16-acc (merged per kt)
#pragma unroll
        for (int kb = 0; kb < 8; ++kb) {
            uint32_t ah0, ah1, ah2, ah3, al0, al1, al2, al3;
            split2h(sa[2 * kb][0],     sa[2 * kb][1],     ah0, al0);
            split2h(sa[2 * kb][2],     sa[2 * kb][3],     ah1, al1);
            split2h(sa[2 * kb + 1][0], sa[2 * kb + 1][1], ah2, al2);
            split2h(sa[2 * kb + 1][2], sa[2 * kb + 1][3], ah3, al3);
#pragma unroll
            for (int nt = 0; nt < 8; ++nt) {
                int a = (8 * nt + g) * ROWV + 8 * kb + 2 * c;
                uint2 vh2 = *(const uint2*)&VH[a];
                uint2 vl2 = *(const uint2*)&VL[a];
                mma_f16f32(oa[nt], ah0, ah1, ah2, ah3, vh2.x, vh2.y);
                mma_f16f16((uint32_t*)&oc[nt], al0, al1, al2, al3, vh2.x, vh2.y);
                mma_f16f16((uint32_t*)&oc[nt], ah0, ah1, ah2, ah3, vl2.x, vl2.y);
            }
        }
        // merge PV corrections (pre-scaled history handled by fresh-per-kt merge)
#pragma unroll
        for (int nt = 0; nt < 8; ++nt) {
            float2 f01 = __half22float2(*(__half2*)&oc[nt].x);
            float2 f23 = __half22float2(*(__half2*)&oc[nt].y);
            oa[nt][0] += f01.x; oa[nt][1] += f01.y;
            oa[nt][2] += f23.x; oa[nt][3] += f23.y;
            oc[nt] = make_uint2(0u, 0u);
        }

        __syncthreads();
        if (kt + 2 <= qb) {
            attn_load_kv(kt + 2, s, tid, sbase, khg, klg, vhg, vlg);
            CP_COMMIT();
        }
    }

    // epilogue: out[b][n][h*64 + d]
    float i0 = 1.0f / l0, i1 = 1.0f / l1;
    int r0 = qb * 128 + 16 * w + g;
    float* o0 = out + ((size_t)b * NN + r0) * DD + h * 64;
    float* o1 = o0 + (size_t)8 * DD;
#pragma unroll
    for (int nt = 0; nt < 8; ++nt) {
        *(float2*)&o0[8 * nt + 2 * c] = make_float2(oa[nt][0] * i0, oa[nt][1] * i0);
        *(float2*)&o1[8 * nt + 2 * c] = make_float2(oa[nt][2] * i1, oa[nt][3] * i1);
    }
}

// ---------------------------------------------------------------------------
extern "C" void kernel_launch(void* const* d_in, const int* in_sizes, int n_in,
                              void* d_out, int out_size)
{
    const float* x = (const float*)d_in[0];   // [2,2048,1024] fp32
    const float* w = (const float*)d_in[1];   // [1024,3072] fp32
    float* out = (float*)d_out;               // [2,2048,1024] fp32
    (void)in_sizes; (void)n_in; (void)out_size;

    // GEMM operand prep (fp16 hi/lo)
    prep_x<<<1024, 256>>>(x);
    prep_w<<<dim3(D3 / 32, DD / 32), dim3(32, 8)>>>(w);

    // fp16x3 QKV GEMM
    cudaFuncSetAttribute(qkv_gemm_mma,
                         cudaFuncAttributeMaxDynamicSharedMemorySize,
                         GEMM_SMEM_TOTAL);
    qkv_gemm_mma<<<dim3(D3 / 128, MM / 128), 256, GEMM_SMEM_TOTAL>>>();

    // attention operand prep (Q/K rows, V transpose)
    prep_attn_qk<<<2048, 256>>>();
    prep_attn_v<<<dim3(NN / 64, HH, BB), 256>>>();

    // fp16x3 mma flash attention
    cudaFuncSetAttribute(attn_mma,
                         cudaFuncAttributeMaxDynamicSharedMemorySize,
                         ATT_SMEM_BYTES);
    attn_mma<<<dim3(NN / 128, HH, BB), 256, ATT_SMEM_BYTES>>>(out);
}

// round 12
// speedup vs baseline: 1.0001x; 1.0001x over previous
#include <cuda_runtime.h>
#include <cuda_bf16.h>
#include <cuda_fp16.h>
#include <cstdint>

// Problem constants
#define BB 2
#define NN 2048
#define HH 16
#define DH 64
#define DD 1024          // HH*DH
#define D3 3072          // 3*DD
#define MM 4096          // BB*NN

// Scratch: QKV laid out [part(q/k/v)][B][H][N][Dh], fp32
__device__ float g_qkv[3u * BB * HH * NN * DH];
// GEMM operands: fp16 hi/lo, b32-pair order per k16 block: [p0,p4,p1,p5,p2,p6,p3,p7]
__device__ __half g_xhi[(size_t)MM * DD];
__device__ __half g_xlo[(size_t)MM * DD];
__device__ __half g_whiT[(size_t)D3 * DD];   // pre-scaled x32
__device__ __half g_wloT[(size_t)D3 * DD];
// Attention operands (fp16 hi/lo, pair-permuted)
__device__ __half g_qh[(size_t)BB * HH * NN * DH];   // [bh][n][d] (unscaled)
__device__ __half g_ql[(size_t)BB * HH * NN * DH];
__device__ __half g_kh[(size_t)BB * HH * NN * DH];   // [bh][n][d]
__device__ __half g_kl[(size_t)BB * HH * NN * DH];
__device__ __half g_vh[(size_t)BB * HH * DH * NN];   // [bh][d][n] (transposed)
__device__ __half g_vl[(size_t)BB * HH * DH * NN];

// ---------------------------------------------------------------------------
// helpers
// ---------------------------------------------------------------------------
#define CP_ASYNC16(dst_u32, gptr)                                              \
    asm volatile("cp.async.cg.shared.global [%0], [%1], 16;"                    \
                 :: "r"(dst_u32), "l"(__cvta_generic_to_global(gptr)))
#define CP_COMMIT() asm volatile("cp.async.commit_group;" ::: "memory")
#define CP_WAIT1()  asm volatile("cp.async.wait_group 1;" ::: "memory")
#define CP_WAIT0()  asm volatile("cp.async.wait_group 0;" ::: "memory")

__device__ __forceinline__ uint32_t smem_u32(const void* p) {
    uint32_t a;
    asm("{ .reg .u64 t; cvta.to.shared.u64 t, %1; cvt.u32.u64 %0, t; }"
        : "=r"(a) : "l"(p));
    return a;
}

// mma.sync m16n8k16 fp16 inputs, fp32 accumulate: d += a * b
__device__ __forceinline__ void mma_f16f32(float* d,
                                           uint32_t a0, uint32_t a1, uint32_t a2, uint32_t a3,
                                           uint32_t b0, uint32_t b1) {
    asm volatile(
        "mma.sync.aligned.m16n8k16.row.col.f32.f16.f16.f32 "
        "{%0,%1,%2,%3}, {%4,%5,%6,%7}, {%8,%9}, {%0,%1,%2,%3};"
        : "+f"(d[0]), "+f"(d[1]), "+f"(d[2]), "+f"(d[3])
        : "r"(a0), "r"(a1), "r"(a2), "r"(a3), "r"(b0), "r"(b1));
}

// mma.sync m16n8k16 fp16 inputs, fp16 accumulate (2x rate path): d += a * b
__device__ __forceinline__ void mma_f16f16(uint32_t* d,
                                           uint32_t a0, uint32_t a1, uint32_t a2, uint32_t a3,
                                           uint32_t b0, uint32_t b1) {
    asm volatile(
        "mma.sync.aligned.m16n8k16.row.col.f16.f16.f16.f16 "
        "{%0,%1}, {%2,%3,%4,%5}, {%6,%7}, {%0,%1};"
        : "+r"(d[0]), "+r"(d[1])
        : "r"(a0), "r"(a1), "r"(a2), "r"(a3), "r"(b0), "r"(b1));
}

__device__ __forceinline__ uint32_t pack_f16(float x0, float x1) {
    __half2 h = __floats2half2_rn(x0, x1);
    return *(uint32_t*)&h;
}

// split a float pair into packed fp16 hi and lo words
__device__ __forceinline__ void split2h(float x0, float x1, uint32_t& h, uint32_t& l) {
    __half h0 = __float2half_rn(x0);
    __half h1 = __float2half_rn(x1);
    __half2 hh = __halves2half2(h0, h1);
    h = *(uint32_t*)&hh;
    l = pack_f16(x0 - __half2float(h0), x1 - __half2float(h1));
}

__device__ __forceinline__ int dpos8(int p) {   // dest slot of source pair p in 8-block
    return ((p & 3) << 1) | (p >> 2);
}

// ---------------------------------------------------------------------------
// GEMM prep: fp16 hi/lo split, pair-permutation (+ transpose & x32 for W)
// ---------------------------------------------------------------------------
__global__ __launch_bounds__(256)
void prep_x(const float* __restrict__ X)
{
    const size_t n16 = (size_t)MM * DD / 16;
    for (size_t i = (size_t)blockIdx.x * 256 + threadIdx.x; i < n16;
         i += (size_t)gridDim.x * 256) {
        const float* src = X + i * 16;
        float s[16];
        *(float4*)(s)      = ((const float4*)src)[0];
        *(float4*)(s + 4)  = ((const float4*)src)[1];
        *(float4*)(s + 8)  = ((const float4*)src)[2];
        *(float4*)(s + 12) = ((const float4*)src)[3];
        const int pp[8] = {0, 4, 1, 5, 2, 6, 3, 7};
        uint32_t ph[8], pl[8];
#pragma unroll
        for (int d = 0; d < 8; ++d) {
            int p = pp[d];
            split2h(s[2 * p], s[2 * p + 1], ph[d], pl[d]);
        }
        uint32_t* dh = (uint32_t*)g_xhi + i * 8;
        uint32_t* dl = (uint32_t*)g_xlo + i * 8;
        *(uint4*)(dh)     = make_uint4(ph[0], ph[1], ph[2], ph[3]);
        *(uint4*)(dh + 4) = make_uint4(ph[4], ph[5], ph[6], ph[7]);
        *(uint4*)(dl)     = make_uint4(pl[0], pl[1], pl[2], pl[3]);
        *(uint4*)(dl + 4) = make_uint4(pl[4], pl[5], pl[6], pl[7]);
    }
}

__device__ __forceinline__ int kperm16(int k) {
    int p = (k >> 1) & 7;
    int d = ((p & 3) << 1) | (p >> 2);
    return (k & ~15) | (d * 2) | (k & 1);
}

__global__ __launch_bounds__(256)
void prep_w(const float* __restrict__ W)
{
    __shared__ float t[32][33];
    const int n0 = blockIdx.x * 32;
    const int k0 = blockIdx.y * 32;
    const int tx = threadIdx.x, ty = threadIdx.y;   // (32, 8)
#pragma unroll
    for (int rr = 0; rr < 32; rr += 8)
        t[ty + rr][tx] = W[(size_t)(k0 + ty + rr) * D3 + n0 + tx];
    __syncthreads();
#pragma unroll
    for (int rr = 0; rr < 32; rr += 8) {
        float v  = t[tx][ty + rr] * 32.0f;    // scale to keep lo in normal range
        __half h = __float2half_rn(v);
        __half l = __float2half_rn(v - __half2float(h));
        size_t base = (size_t)(n0 + ty + rr) * DD + k0 + kperm16(tx);
        g_whiT[base] = h;
        g_wloT[base] = l;
    }
}

// ---------------------------------------------------------------------------
// fp16x3 QKV GEMM via mma.sync m16n8k16 (main term f32-acc, corrections f16-acc).
// CTA 128x128, 256 threads, k-chunk 32, cp.async double buffer, ROWW=20 pad.
// ---------------------------------------------------------------------------
#define ROWW 20
#define OAHI 0
#define OALO 2560
#define OBHI 5120
#define OBLO 7680
#define ST_B32 10240
#define GEMM_SMEM_TOTAL (2 * ST_B32 * 4)

__device__ __forceinline__ void gemm_load(int kt, uint32_t st_u32,
                                          int m0, int n0, int tid)
{
    const int k0 = kt * 32;
#pragma unroll
    for (int it = 0; it < 2; ++it) {
        int j   = it * 256 + tid;
        int row = j >> 2;
        int q   = (j & 3);
        uint32_t doff = (uint32_t)(row * ROWW + q * 4) * 4;
        CP_ASYNC16(st_u32 + OAHI * 4 + doff, g_xhi  + (size_t)(m0 + row) * DD + k0 + q * 8);
        CP_ASYNC16(st_u32 + OALO * 4 + doff, g_xlo  + (size_t)(m0 + row) * DD + k0 + q * 8);
        CP_ASYNC16(st_u32 + OBHI * 4 + doff, g_whiT + (size_t)(n0 + row) * DD + k0 + q * 8);
        CP_ASYNC16(st_u32 + OBLO * 4 + doff, g_wloT + (size_t)(n0 + row) * DD + k0 + q * 8);
    }
}

__global__ __launch_bounds__(256, 1)
void qkv_gemm_mma()
{
    extern __shared__ float sm[];
    const int tid   = threadIdx.x;
    const int wid   = tid >> 5;
    const int lane  = tid & 31;
    const int warpm = wid & 3;
    const int warpn = wid >> 2;
    const int c     = lane & 3;
    const int g     = lane >> 2;
    const int n0    = blockIdx.x * 128;
    const int m0    = blockIdx.y * 128;

    const uint32_t* st[2] = {(const uint32_t*)sm, (const uint32_t*)sm + ST_B32};
    uint32_t stu[2] = {smem_u32(sm), smem_u32(sm + ST_B32)};

    float acc[2][8][4];
    uint32_t accC[2][8][2];
#pragma unroll
    for (int mt = 0; mt < 2; ++mt)
#pragma unroll
        for (int nt = 0; nt < 8; ++nt) {
#pragma unroll
            for (int v = 0; v < 4; ++v) acc[mt][nt][v] = 0.0f;
            accC[mt][nt][0] = 0u; accC[mt][nt][1] = 0u;
        }

    gemm_load(0, stu[0], m0, n0, tid); CP_COMMIT();
    gemm_load(1, stu[1], m0, n0, tid); CP_COMMIT();

    for (int kt = 0; kt < 32; ++kt) {
        const int buf = kt & 1;
        if (kt < 30) { CP_WAIT1(); } else { CP_WAIT0(); }
        __syncthreads();

        const uint32_t* S = st[buf];
#pragma unroll
        for (int ks = 0; ks < 2; ++ks) {
            const int kc = ks * 8 + 2 * c;
            uint2 ah[2][2], al[2][2];
#pragma unroll
            for (int mt = 0; mt < 2; ++mt) {
                int rbase = warpm * 32 + mt * 16 + g;
                ah[mt][0] = *(const uint2*)&S[OAHI + rbase * ROWW + kc];
                ah[mt][1] = *(const uint2*)&S[OAHI + (rbase + 8) * ROWW + kc];
                al[mt][0] = *(const uint2*)&S[OALO + rbase * ROWW + kc];
                al[mt][1] = *(const uint2*)&S[OALO + (rbase + 8) * ROWW + kc];
            }
#pragma unroll
            for (int nt = 0; nt < 8; ++nt) {
                int nb = (warpn * 64 + nt * 8 + g) * ROWW + kc;
                uint2 bh = *(const uint2*)&S[OBHI + nb];
                uint2 bl = *(const uint2*)&S[OBLO + nb];
#pragma unroll
                for (int mt = 0; mt < 2; ++mt) {
                    mma_f16f32(acc[mt][nt], ah[mt][0].x, ah[mt][1].x,
                               ah[mt][0].y, ah[mt][1].y, bh.x, bh.y);
                    mma_f16f16(accC[mt][nt], ah[mt][0].x, ah[mt][1].x,
                               ah[mt][0].y, ah[mt][1].y, bl.x, bl.y);
                    mma_f16f16(accC[mt][nt], al[mt][0].x, al[mt][1].x,
                               al[mt][0].y, al[mt][1].y, bh.x, bh.y);
                }
            }
        }
        __syncthreads();
        if (kt + 2 < 32) {
            gemm_load(kt + 2, stu[buf], m0, n0, tid);
            CP_COMMIT();
        }
    }

    // merge corrections + undo W x32 scaling, scatter into g_qkv
    const float osc = 1.0f / 32.0f;
#pragma unroll
    for (int mt = 0; mt < 2; ++mt) {
#pragma unroll
        for (int nt = 0; nt < 8; ++nt) {
            float2 f01 = __half22float2(*(__half2*)&accC[mt][nt][0]);
            float2 f23 = __half22float2(*(__half2*)&accC[mt][nt][1]);
            float r0 = (acc[mt][nt][0] + f01.x) * osc;
            float r1 = (acc[mt][nt][1] + f01.y) * osc;
            float r2 = (acc[mt][nt][2] + f23.x) * osc;
            float r3 = (acc[mt][nt][3] + f23.y) * osc;
            int colg = n0 + warpn * 64 + nt * 8 + 2 * c;
            int part = colg >> 10;
            int pc   = colg & 1023;
            int h    = pc >> 6;
            int dh   = pc & 63;
            int mg0  = m0 + warpm * 32 + mt * 16 + g;
            int b    = mg0 >> 11;
            int seq  = mg0 & 2047;
            float* dst = g_qkv + ((size_t)((part * BB + b) * HH + h) * NN + seq) * DH + dh;
            *(float2*)dst = make_float2(r0, r1);
            *(float2*)(dst + (size_t)8 * DH) = make_float2(r2, r3);
        }
    }
}

// ---------------------------------------------------------------------------
// Attention prep: Q/K rows -> fp16 hi/lo pair-permuted (no prescale);
// V -> transposed [d][n] fp16 hi/lo pair-permuted along n.
// ---------------------------------------------------------------------------
__global__ __launch_bounds__(256)
void prep_attn_qk()
{
    int cidx = blockIdx.x * 256 + threadIdx.x;       // 0..524287
    int row  = cidx >> 2;                            // 0..131071 (Q rows then K rows)
    int ch   = cidx & 3;                             // 16-elem chunk within row
    int part = row >> 16;                            // 0 = Q, 1 = K
    const float* src = g_qkv + (size_t)row * 64 + ch * 16;
    float s[16];
    *(float4*)(s)      = ((const float4*)src)[0];
    *(float4*)(s + 4)  = ((const float4*)src)[1];
    *(float4*)(s + 8)  = ((const float4*)src)[2];
    *(float4*)(s + 12) = ((const float4*)src)[3];
    const int pp[8] = {0, 4, 1, 5, 2, 6, 3, 7};
    uint32_t ph[8], pl[8];
#pragma unroll
    for (int d = 0; d < 8; ++d) {
        int p = pp[d];
        split2h(s[2 * p], s[2 * p + 1], ph[d], pl[d]);
    }
    size_t off = ((size_t)(row & 65535) * 32) + ch * 8;   // b32 units
    uint32_t* dh = (part ? (uint32_t*)g_kh : (uint32_t*)g_qh) + off;
    uint32_t* dl = (part ? (uint32_t*)g_kl : (uint32_t*)g_ql) + off;
    *(uint4*)(dh)     = make_uint4(ph[0], ph[1], ph[2], ph[3]);
    *(uint4*)(dh + 4) = make_uint4(ph[4], ph[5], ph[6], ph[7]);
    *(uint4*)(dl)     = make_uint4(pl[0], pl[1], pl[2], pl[3]);
    *(uint4*)(dl + 4) = make_uint4(pl[4], pl[5], pl[6], pl[7]);
}

__global__ __launch_bounds__(256)
void prep_attn_v()
{
    __shared__ float t[64][65];
    const int n0 = blockIdx.x * 64;
    const int h  = blockIdx.y;
    const int b  = blockIdx.z;
    const int bh = b * HH + h;
    const int tid = threadIdx.x;
    const float* Vg = g_qkv + (size_t)((2 * BB + b) * HH + h) * NN * DH;
#pragma unroll
    for (int i = 0; i < 16; ++i) {
        int lin = i * 256 + tid;
        int r = lin >> 6, d = lin & 63;
        t[r][d] = Vg[(size_t)(n0 + r) * 64 + d];
    }
    __syncthreads();
    const int d  = tid >> 2;
    const int qq = tid & 3;
    uint32_t* vh = (uint32_t*)g_vh + ((size_t)bh * 64 + d) * 1024;
    uint32_t* vl = (uint32_t*)g_vl + ((size_t)bh * 64 + d) * 1024;
#pragma unroll
    for (int i = 0; i < 8; ++i) {
        int npl = qq * 8 + i;
        float p0 = t[2 * npl][d];
        float p1 = t[2 * npl + 1][d];
        uint32_t hw, lw;
        split2h(p0, p1, hw, lw);
        int npg = (n0 >> 1) + npl;
        int dst = (npg & ~7) + dpos8(npg & 7);
        vh[dst] = hw;
        vl[dst] = lw;
    }
}

// ---------------------------------------------------------------------------
// fp16x3 causal flash attention via mma.sync m16n8k16
// (main terms f32-acc, corrections f16-acc). CTA=256 thr, q-tile 128.
// ---------------------------------------------------------------------------
#define ROWK 36
#define ROWV 68
#define KSTG (128 * ROWK)
#define VSTG (64 * ROWV)
#define ATT_SMEM_B32 (4 * KSTG + 4 * VSTG)
#define ATT_SMEM_BYTES (ATT_SMEM_B32 * 4)

__device__ __forceinline__ void attn_load_kv(
    int kt, int s, int tid, uint32_t sbase,
    const __half* khg, const __half* klg,
    const __half* vhg, const __half* vlg)
{
    const uint32_t okh = (s ? KSTG : 0) * 4;
    const uint32_t okl = (2 * KSTG + (s ? KSTG : 0)) * 4;
    const uint32_t ovh = (4 * KSTG + (s ? VSTG : 0)) * 4;
    const uint32_t ovl = (4 * KSTG + 2 * VSTG + (s ? VSTG : 0)) * 4;
#pragma unroll
    for (int it = 0; it < 4; ++it) {
        int idx = it * 256 + tid;
        int row = idx >> 3, ch = idx & 7;
        uint32_t doff = (uint32_t)(row * ROWK + ch * 4) * 4;
        size_t so = (size_t)(kt * 128 + row) * 64 + ch * 8;
        CP_ASYNC16(sbase + okh + doff, khg + so);
        CP_ASYNC16(sbase + okl + doff, klg + so);
    }
#pragma unroll
    for (int it = 0; it < 4; ++it) {
        int idx = it * 256 + tid;
        int row = idx >> 4, ch = idx & 15;
        uint32_t doff = (uint32_t)(row * ROWV + ch * 4) * 4;
        size_t so = (size_t)row * NN + kt * 128 + ch * 8;
        CP_ASYNC16(sbase + ovh + doff, vhg + so);
        CP_ASYNC16(sbase + ovl + doff, vlg + so);
    }
}

__global__ __launch_bounds__(256, 1)
void attn_mma(float* __restrict__ out)
{
    extern __shared__ float smf[];
    uint32_t* su = (uint32_t*)smf;
    const uint32_t sbase = smem_u32(smf);
    const int tid  = threadIdx.x;
    const int w    = tid >> 5;
    const int lane = tid & 31;
    const int g    = lane >> 2;
    const int c    = lane & 3;
    const int qb   = (int)gridDim.x - 1 - blockIdx.x;   // heavy tiles first
    const int h    = blockIdx.y;
    const int b    = blockIdx.z;
    const int bh   = b * HH + h;

    const __half* khg = g_kh + (size_t)bh * NN * DH;
    const __half* klg = g_kl + (size_t)bh * NN * DH;
    const __half* vhg = g_vh + (size_t)bh * DH * NN;
    const __half* vlg = g_vl + (size_t)bh * DH * NN;

    // Q fragments, register-resident for the whole CTA lifetime
    uint2 qfh[4][2], qfl[4][2];
    {
        const uint32_t* qh32 = (const uint32_t*)g_qh;
        const uint32_t* ql32 = (const uint32_t*)g_ql;
        size_t r0 = (size_t)bh * NN + qb * 128 + w * 16 + g;
#pragma unroll
        for (int kd = 0; kd < 4; ++kd) {
            qfh[kd][0] = *(const uint2*)&qh32[r0 * 32 + kd * 8 + 2 * c];
            qfh[kd][1] = *(const uint2*)&qh32[(r0 + 8) * 32 + kd * 8 + 2 * c];
            qfl[kd][0] = *(const uint2*)&ql32[r0 * 32 + kd * 8 + 2 * c];
            qfl[kd][1] = *(const uint2*)&ql32[(r0 + 8) * 32 + kd * 8 + 2 * c];
        }
    }

    float oa[8][4];
    uint2 oc[8];
#pragma unroll
    for (int nt = 0; nt < 8; ++nt) {
#pragma unroll
        for (int v = 0; v < 4; ++v) oa[nt][v] = 0.0f;
        oc[nt] = make_uint2(0u, 0u);
    }
    float m0 = -1e30f, m1 = -1e30f, l0 = 0.0f, l1 = 0.0f;

    attn_load_kv(0, 0, tid, sbase, khg, klg, vhg, vlg);
    CP_COMMIT();
    if (qb >= 1) attn_load_kv(1, 1, tid, sbase, khg, klg, vhg, vlg);
    CP_COMMIT();

    for (int kt = 0; kt <= qb; ++kt) {
        if (kt < qb) { CP_WAIT1(); } else { CP_WAIT0(); }
        __syncthreads();
        const int s = kt & 1;
        const uint32_t* KH = su + (s ? KSTG : 0);
        const uint32_t* KL = su + 2 * KSTG + (s ? KSTG : 0);
        const uint32_t* VH = su + 4 * KSTG + (s ? VSTG : 0);
        const uint32_t* VL = su + 4 * KSTG + 2 * VSTG + (s ? VSTG : 0);

        // S = Q @ K^T: main f32-acc, corrections f16-acc
        float sa[16][4];
        uint2 sc[16];
#pragma unroll
        for (int nt = 0; nt < 16; ++nt) {
            sa[nt][0] = 0.0f; sa[nt][1] = 0.0f; sa[nt][2] = 0.0f; sa[nt][3] = 0.0f;
            sc[nt] = make_uint2(0u, 0u);
        }
#pragma unroll
        for (int kd = 0; kd < 4; ++kd) {
#pragma unroll
            for (int nt = 0; nt < 16; ++nt) {
                int a = (8 * nt + g) * ROWK + 8 * kd + 2 * c;
                uint2 kh2 = *(const uint2*)&KH[a];
                uint2 kl2 = *(const uint2*)&KL[a];
                mma_f16f32(sa[nt], qfh[kd][0].x, qfh[kd][1].x,
                           qfh[kd][0].y, qfh[kd][1].y, kh2.x, kh2.y);
                mma_f16f16((uint32_t*)&sc[nt], qfh[kd][0].x, qfh[kd][1].x,
                           qfh[kd][0].y, qfh[kd][1].y, kl2.x, kl2.y);
                mma_f16f16((uint32_t*)&sc[nt], qfl[kd][0].x, qfl[kd][1].x,
                           qfl[kd][0].y, qfl[kd][1].y, kh2.x, kh2.y);
            }
        }
        // merge corrections + 1/sqrt(Dh) scaling
#pragma unroll
        for (int nt = 0; nt < 16; ++nt) {
            float2 f01 = __half22float2(*(__half2*)&sc[nt].x);
            float2 f23 = __half22float2(*(__half2*)&sc[nt].y);
            sa[nt][0] = (sa[nt][0] + f01.x) * 0.125f;
            sa[nt][1] = (sa[nt][1] + f01.y) * 0.125f;
            sa[nt][2] = (sa[nt][2] + f23.x) * 0.125f;
            sa[nt][3] = (sa[nt][3] + f23.y) * 0.125f;
        }

        // causal mask on the diagonal tile
        if (kt == qb) {
            int r0 = 16 * w + g, r1 = r0 + 8;
#pragma unroll
            for (int nt = 0; nt < 16; ++nt) {
                int c0 = 8 * nt + 2 * c, c1 = c0 + 1;
                if (c0 > r0) sa[nt][0] = -1e30f;
                if (c1 > r0) sa[nt][1] = -1e30f;
                if (c0 > r1) sa[nt][2] = -1e30f;
                if (c1 > r1) sa[nt][3] = -1e30f;
            }
        }

        // warp-local online softmax
        float mx0 = -1e30f, mx1 = -1e30f;
#pragma unroll
        for (int nt = 0; nt < 16; ++nt) {
            mx0 = fmaxf(mx0, fmaxf(sa[nt][0], sa[nt][1]));
            mx1 = fmaxf(mx1, fmaxf(sa[nt][2], sa[nt][3]));
        }
        mx0 = fmaxf(mx0, __shfl_xor_sync(0xffffffffu, mx0, 1));
        mx0 = fmaxf(mx0, __shfl_xor_sync(0xffffffffu, mx0, 2));
        mx1 = fmaxf(mx1, __shfl_xor_sync(0xffffffffu, mx1, 1));
        mx1 = fmaxf(mx1, __shfl_xor_sync(0xffffffffu, mx1, 2));
        float mn0 = fmaxf(m0, mx0), mn1 = fmaxf(m1, mx1);
        float cr0 = __expf(m0 - mn0), cr1 = __expf(m1 - mn1);
        m0 = mn0; m1 = mn1;
        float rs0 = 0.0f, rs1 = 0.0f;
#pragma unroll
        for (int nt = 0; nt < 16; ++nt) {
            sa[nt][0] = __expf(sa[nt][0] - mn0); rs0 += sa[nt][0];
            sa[nt][1] = __expf(sa[nt][1] - mn0); rs0 += sa[nt][1];
            sa[nt][2] = __expf(sa[nt][2] - mn1); rs1 += sa[nt][2];
            sa[nt][3] = __expf(sa[nt][3] - mn1); rs1 += sa[nt][3];
        }
        rs0 += __shfl_xor_sync(0xffffffffu, rs0, 1);
        rs0 += __shfl_xor_sync(0xffffffffu, rs0, 2);
        rs1 += __shfl_xor_sync(0xffffffffu, rs1, 1);
        rs1 += __shfl_xor_sync(0xffffffffu, rs1, 2);
        l0 = l0 * cr0 + rs0;
        l1 = l1 * cr1 + rs1;
#pragma unroll
        for (int nt = 0; nt < 8; ++nt) {
            oa[nt][0] *= cr0; oa[nt][1] *= cr0;
            oa[nt][2] *= cr1; oa[nt][3] *= cr1;
        }

        // O += P @ V: main f32-acc, corrections f16-acc (merged per kt)
#pragma unroll
        for (int kb = 0; kb < 8; ++kb) {
            uint32_t ah0, ah1, ah2, ah3, al0, al1, al2, al3;
            split2h(sa[2 * kb][0],     sa[2 * kb][1],     ah0, al0);
            split2h(sa[2 * kb][2],     sa[2 * kb][3],     ah1, al1);
            split2h(sa[2 * kb + 1][0], sa[2 * kb + 1][1], ah2, al2);
            split2h(sa[2 * kb + 1][2], sa[2 * kb + 1][3], ah3, al3);
#pragma unroll
            for (int nt = 0; nt < 8; ++nt) {
                int a = (8 * nt + g) * ROWV + 8 * kb + 2 * c;
                uint2 vh2 = *(const uint2*)&VH[a];
                uint2 vl2 = *(const uint2*)&VL[a];
                mma_f16f32(oa[nt], ah0, ah1, ah2, ah3, vh2.x, vh2.y);
                mma_f16f16((uint32_t*)&oc[nt], al0, al1, al2, al3, vh2.x, vh2.y);
                mma_f16f16((uint32_t*)&oc[nt], ah0, ah1, ah2, ah3, vl2.x, vl2.y);
            }
        }
        // merge PV corrections (pre-scaled history handled by fresh-per-kt merge)
#pragma unroll
        for (int nt = 0; nt < 8; ++nt) {
            float2 f01 = __half22float2(*(__half2*)&oc[nt].x);
            float2 f23 = __half22float2(*(__half2*)&oc[nt].y);
            oa[nt][0] += f01.x; oa[nt][1] += f01.y;
            oa[nt][2] += f23.x; oa[nt][3] += f23.y;
            oc[nt] = make_uint2(0u, 0u);
        }

        __syncthreads();
        if (kt + 2 <= qb) {
            attn_load_kv(kt + 2, s, tid, sbase, khg, klg, vhg, vlg);
            CP_COMMIT();
        }
    }

    // epilogue: out[b][n][h*64 + d]
    float i0 = 1.0f / l0, i1 = 1.0f / l1;
    int r0 = qb * 128 + 16 * w + g;
    float* o0 = out + ((size_t)b * NN + r0) * DD + h * 64;
    float* o1 = o0 + (size_t)8 * DD;
#pragma unroll
    for (int nt = 0; nt < 8; ++nt) {
        *(float2*)&o0[8 * nt + 2 * c] = make_float2(oa[nt][0] * i0, oa[nt][1] * i0);
        *(float2*)&o1[8 * nt + 2 * c] = make_float2(oa[nt][2] * i1, oa[nt][3] * i1);
    }
}

// ---------------------------------------------------------------------------
extern "C" void kernel_launch(void* const* d_in, const int* in_sizes, int n_in,
                              void* d_out, int out_size)
{
    const float* x = (const float*)d_in[0];   // [2,2048,1024] fp32
    const float* w = (const float*)d_in[1];   // [1024,3072] fp32
    float* out = (float*)d_out;               // [2,2048,1024] fp32
    (void)in_sizes; (void)n_in; (void)out_size;

    // GEMM operand prep (fp16 hi/lo)
    prep_x<<<1024, 256>>>(x);
    prep_w<<<dim3(D3 / 32, DD / 32), dim3(32, 8)>>>(w);

    // fp16x3 QKV GEMM
    cudaFuncSetAttribute(qkv_gemm_mma,
                         cudaFuncAttributeMaxDynamicSharedMemorySize,
                         GEMM_SMEM_TOTAL);
    qkv_gemm_mma<<<dim3(D3 / 128, MM / 128), 256, GEMM_SMEM_TOTAL>>>();

    // attention operand prep (Q/K rows, V transpose)
    prep_attn_qk<<<2048, 256>>>();
    prep_attn_v<<<dim3(NN / 64, HH, BB), 256>>>();

    // fp16x3 mma flash attention
    cudaFuncSetAttribute(attn_mma,
                         cudaFuncAttributeMaxDynamicSharedMemorySize,
                         ATT_SMEM_BYTES);
    attn_mma<<<dim3(NN / 128, HH, BB), 256, ATT_SMEM_BYTES>>>(out);
}

// round 13
// speedup vs baseline: 1.3045x; 1.3044x over previous
#include <cuda_runtime.h>
#include <cuda_bf16.h>
#include <cstdint>

// Problem constants
#define BB 2
#define NN 2048
#define HH 16
#define DH 64
#define DD 1024          // HH*DH
#define D3 3072          // 3*DD
#define MM 4096          // BB*NN

// Scratch: QKV laid out [part(q/k/v)][B][H][N][Dh], fp32
__device__ float g_qkv[3u * BB * HH * NN * DH];
// int8 GEMM operands: A = 128*a1 + a2 fixed point, quad-permuted per 32-k block
__device__ float  g_sx[MM];                  // per-row scale of X
__device__ float  g_sw[D3];                  // per-col scale of W
__device__ int8_t g_xa[(size_t)MM * DD];     // a1 (high word)
__device__ int8_t g_xb[(size_t)MM * DD];     // a2 (low word)
__device__ int8_t g_wa[(size_t)D3 * DD];     // [n][k'] b1
__device__ int8_t g_wb[(size_t)D3 * DD];     // [n][k'] b2
// Attention operands (bf16 hi/lo, pair-permuted) — R10 proven config
__device__ __nv_bfloat16 g_qh[(size_t)BB * HH * NN * DH];   // [bh][n][d], prescaled 1/8
__device__ __nv_bfloat16 g_ql[(size_t)BB * HH * NN * DH];
__device__ __nv_bfloat16 g_kh[(size_t)BB * HH * NN * DH];   // [bh][n][d]
__device__ __nv_bfloat16 g_kl[(size_t)BB * HH * NN * DH];
__device__ __nv_bfloat16 g_vh[(size_t)BB * HH * DH * NN];   // [bh][d][n] (transposed)
__device__ __nv_bfloat16 g_vl[(size_t)BB * HH * DH * NN];

// ---------------------------------------------------------------------------
// helpers
// ---------------------------------------------------------------------------
#define CP_ASYNC16(dst_u32, gptr)                                              \
    asm volatile("cp.async.cg.shared.global [%0], [%1], 16;"                    \
                 :: "r"(dst_u32), "l"(__cvta_generic_to_global(gptr)))
#define CP_COMMIT() asm volatile("cp.async.commit_group;" ::: "memory")
#define CP_WAIT1()  asm volatile("cp.async.wait_group 1;" ::: "memory")
#define CP_WAIT0()  asm volatile("cp.async.wait_group 0;" ::: "memory")

__device__ __forceinline__ uint32_t smem_u32(const void* p) {
    uint32_t a;
    asm("{ .reg .u64 t; cvta.to.shared.u64 t, %1; cvt.u32.u64 %0, t; }"
        : "=r"(a) : "l"(p));
    return a;
}

// mma.sync m16n8k32 s8: d += a * b  (exact s32 accumulate)
__device__ __forceinline__ void mma_s8(int* d,
                                       uint32_t a0, uint32_t a1, uint32_t a2, uint32_t a3,
                                       uint32_t b0, uint32_t b1) {
    asm volatile(
        "mma.sync.aligned.m16n8k32.row.col.s32.s8.s8.s32 "
        "{%0,%1,%2,%3}, {%4,%5,%6,%7}, {%8,%9}, {%0,%1,%2,%3};"
        : "+r"(d[0]), "+r"(d[1]), "+r"(d[2]), "+r"(d[3])
        : "r"(a0), "r"(a1), "r"(a2), "r"(a3), "r"(b0), "r"(b1));
}

// mma.sync m16n8k16 bf16: d += a * b  (f32 accumulate) — attention
__device__ __forceinline__ void mma_bf16(float* d,
                                         uint32_t a0, uint32_t a1, uint32_t a2, uint32_t a3,
                                         uint32_t b0, uint32_t b1) {
    asm volatile(
        "mma.sync.aligned.m16n8k16.row.col.f32.bf16.bf16.f32 "
        "{%0,%1,%2,%3}, {%4,%5,%6,%7}, {%8,%9}, {%0,%1,%2,%3};"
        : "+f"(d[0]), "+f"(d[1]), "+f"(d[2]), "+f"(d[3])
        : "r"(a0), "r"(a1), "r"(a2), "r"(a3), "r"(b0), "r"(b1));
}

__device__ __forceinline__ uint32_t pack_bf16(float x0, float x1) {
    __nv_bfloat16 h0 = __float2bfloat16_rn(x0);
    __nv_bfloat16 h1 = __float2bfloat16_rn(x1);
    return (uint32_t)__bfloat16_as_ushort(h0) |
           ((uint32_t)__bfloat16_as_ushort(h1) << 16);
}

__device__ __forceinline__ void split2(float x0, float x1, uint32_t& h, uint32_t& l) {
    __nv_bfloat16 h0 = __float2bfloat16_rn(x0);
    __nv_bfloat16 h1 = __float2bfloat16_rn(x1);
    h = (uint32_t)__bfloat16_as_ushort(h0) |
        ((uint32_t)__bfloat16_as_ushort(h1) << 16);
    l = pack_bf16(x0 - __bfloat162float(h0), x1 - __bfloat162float(h1));
}

__device__ __forceinline__ int dpos8(int p) {   // dest slot of source pair/quad p
    return ((p & 3) << 1) | (p >> 2);
}

// quantize x*inv_s into 2 int8 words: A = rn(x*inv_s) = 128*a1 + a2
__device__ __forceinline__ void quant2(float x, float inv_s, int& a1, int& a2) {
    int A = __float2int_rn(x * inv_s);
    a1 = __float2int_rn((float)A * (1.0f / 128.0f));
    a2 = A - (a1 << 7);
}

// ---------------------------------------------------------------------------
// int8 GEMM prep
// ---------------------------------------------------------------------------
// one block per X row: rowmax scale + quantize + quad-permute pack
__global__ __launch_bounds__(256)
void prep_xi(const float* __restrict__ X)
{
    __shared__ float red[8];
    __shared__ float s_sh;
    const int row = blockIdx.x;
    const int t   = threadIdx.x;          // quad index 0..255
    float4 v = *(const float4*)(X + (size_t)row * DD + t * 4);
    float mx = fmaxf(fmaxf(fabsf(v.x), fabsf(v.y)), fmaxf(fabsf(v.z), fabsf(v.w)));
#pragma unroll
    for (int o = 16; o > 0; o >>= 1)
        mx = fmaxf(mx, __shfl_xor_sync(0xffffffffu, mx, o));
    if ((t & 31) == 0) red[t >> 5] = mx;
    __syncthreads();
    if (t == 0) {
        float m = red[0];
#pragma unroll
        for (int i = 1; i < 8; ++i) m = fmaxf(m, red[i]);
        s_sh = fmaxf(m, 1e-20f);
        g_sx[row] = s_sh;
    }
    __syncthreads();
    const float inv_s = 16256.0f / s_sh;

    int a1[4], a2[4];
    quant2(v.x, inv_s, a1[0], a2[0]);
    quant2(v.y, inv_s, a1[1], a2[1]);
    quant2(v.z, inv_s, a1[2], a2[2]);
    quant2(v.w, inv_s, a1[3], a2[3]);
    uint32_t pa = (uint32_t)(uint8_t)(int8_t)a1[0] | ((uint32_t)(uint8_t)(int8_t)a1[1] << 8) |
                  ((uint32_t)(uint8_t)(int8_t)a1[2] << 16) | ((uint32_t)(uint8_t)(int8_t)a1[3] << 24);
    uint32_t pb = (uint32_t)(uint8_t)(int8_t)a2[0] | ((uint32_t)(uint8_t)(int8_t)a2[1] << 8) |
                  ((uint32_t)(uint8_t)(int8_t)a2[2] << 16) | ((uint32_t)(uint8_t)(int8_t)a2[3] << 24);
    int widx = row * 256 + (t & ~7) + dpos8(t & 7);
    ((uint32_t*)g_xa)[widx] = pa;
    ((uint32_t*)g_xb)[widx] = pb;
}

// per-column |W| max (coalesced: consecutive threads -> consecutive columns)
__global__ __launch_bounds__(256)
void w_absmax(const float* __restrict__ W)
{
    int n = blockIdx.x * 256 + threadIdx.x;
    float m = 0.0f;
    for (int k = 0; k < DD; ++k)
        m = fmaxf(m, fabsf(W[(size_t)k * D3 + n]));
    g_sw[n] = fmaxf(m, 1e-20f);
}

__device__ __forceinline__ int kpermq(int k) {   // k in 0..31, quad permutation
    return ((dpos8((k >> 2) & 7)) << 2) | (k & 3);
}

// quantize + transpose W -> g_wa/g_wb [n][k']
__global__ __launch_bounds__(256)
void prep_wq(const float* __restrict__ W)
{
    __shared__ float t[32][33];
    const int n0 = blockIdx.x * 32;
    const int k0 = blockIdx.y * 32;
    const int tx = threadIdx.x, ty = threadIdx.y;   // (32, 8)
#pragma unroll
    for (int rr = 0; rr < 32; rr += 8)
        t[ty + rr][tx] = W[(size_t)(k0 + ty + rr) * D3 + n0 + tx];   // t[kk][nn]
    __syncthreads();
#pragma unroll
    for (int rr = 0; rr < 32; rr += 8) {
        int n = n0 + ty + rr;
        float inv_s = 16256.0f / g_sw[n];
        float v = t[tx][ty + rr];          // kk = tx
        int b1, b2;
        quant2(v, inv_s, b1, b2);
        size_t base = (size_t)n * DD + k0 + kpermq(tx);
        g_wa[base] = (int8_t)b1;
        g_wb[base] = (int8_t)b2;
    }
}

// ---------------------------------------------------------------------------
// int8x3 QKV GEMM via mma.sync m16n8k32 (exact s32 accumulate).
// CTA 128x128, 256 threads (warps 4m x 2n, warp tile 32x64), k-chunk 64,
// cp.async double buffer. Row stride 80 bytes (64 data + 16 pad): fragment
// LDS.64s tile the 16 bank-pairs exactly 2-deep.
// ---------------------------------------------------------------------------
#define ROWW 20                 // row stride in b32 (80 bytes)
#define OA1 0
#define OA2 2560
#define OB1 5120
#define OB2 7680
#define ST_B32 10240            // 40KB per stage
#define GEMM_SMEM_TOTAL (2 * ST_B32 * 4)

__device__ __forceinline__ void gemm_load(int kt, uint32_t st_u32,
                                          int m0, int n0, int tid)
{
    const int k0 = kt * 64;     // int8 element offset
#pragma unroll
    for (int it = 0; it < 2; ++it) {
        int j   = it * 256 + tid;
        int row = j >> 2;
        int ch  = (j & 3);                        // 16B chunk within 64B row
        uint32_t doff = (uint32_t)(row * ROWW + ch * 4) * 4;
        CP_ASYNC16(st_u32 + OA1 * 4 + doff, g_xa + (size_t)(m0 + row) * DD + k0 + ch * 16);
        CP_ASYNC16(st_u32 + OA2 * 4 + doff, g_xb + (size_t)(m0 + row) * DD + k0 + ch * 16);
        CP_ASYNC16(st_u32 + OB1 * 4 + doff, g_wa + (size_t)(n0 + row) * DD + k0 + ch * 16);
        CP_ASYNC16(st_u32 + OB2 * 4 + doff, g_wb + (size_t)(n0 + row) * DD + k0 + ch * 16);
    }
}

__global__ __launch_bounds__(256, 1)
void qkv_gemm_imma()
{
    extern __shared__ float sm[];
    const int tid   = threadIdx.x;
    const int wid   = tid >> 5;
    const int lane  = tid & 31;
    const int warpm = wid & 3;
    const int warpn = wid >> 2;
    const int c     = lane & 3;
    const int g     = lane >> 2;
    const int n0    = blockIdx.x * 128;
    const int m0    = blockIdx.y * 128;

    const uint32_t* st[2] = {(const uint32_t*)sm, (const uint32_t*)sm + ST_B32};
    uint32_t stu[2] = {smem_u32(sm), smem_u32(sm + ST_B32)};

    int accH[2][8][4];   // a1*b1 (scale 16384)
    int accM[2][8][4];   // a1*b2 + a2*b1 (scale 128)
#pragma unroll
    for (int mt = 0; mt < 2; ++mt)
#pragma unroll
        for (int nt = 0; nt < 8; ++nt)
#pragma unroll
            for (int v = 0; v < 4; ++v) { accH[mt][nt][v] = 0; accM[mt][nt][v] = 0; }

    gemm_load(0, stu[0], m0, n0, tid); CP_COMMIT();
    gemm_load(1, stu[1], m0, n0, tid); CP_COMMIT();

    for (int kt = 0; kt < 16; ++kt) {
        const int buf = kt & 1;
        if (kt < 14) { CP_WAIT1(); } else { CP_WAIT0(); }
        __syncthreads();

        const uint32_t* S = st[buf];
#pragma unroll
        for (int ks = 0; ks < 2; ++ks) {
            const int kc = ks * 8 + 2 * c;        // b32 index within row
            uint2 a1f[2][2], a2f[2][2];           // [mt][rowhalf] -> (quad c, quad c+4)
#pragma unroll
            for (int mt = 0; mt < 2; ++mt) {
                int rbase = warpm * 32 + mt * 16 + g;
                a1f[mt][0] = *(const uint2*)&S[OA1 + rbase * ROWW + kc];
                a1f[mt][1] = *(const uint2*)&S[OA1 + (rbase + 8) * ROWW + kc];
                a2f[mt][0] = *(const uint2*)&S[OA2 + rbase * ROWW + kc];
                a2f[mt][1] = *(const uint2*)&S[OA2 + (rbase + 8) * ROWW + kc];
            }
#pragma unroll
            for (int nt = 0; nt < 8; ++nt) {
                int nb = (warpn * 64 + nt * 8 + g) * ROWW + kc;
                uint2 b1 = *(const uint2*)&S[OB1 + nb];
                uint2 b2 = *(const uint2*)&S[OB2 + nb];
#pragma unroll
                for (int mt = 0; mt < 2; ++mt) {
                    mma_s8(accH[mt][nt], a1f[mt][0].x, a1f[mt][1].x,
                           a1f[mt][0].y, a1f[mt][1].y, b1.x, b1.y);
                    mma_s8(accM[mt][nt], a1f[mt][0].x, a1f[mt][1].x,
                           a1f[mt][0].y, a1f[mt][1].y, b2.x, b2.y);
                    mma_s8(accM[mt][nt], a2f[mt][0].x, a2f[mt][1].x,
                           a2f[mt][0].y, a2f[mt][1].y, b1.x, b1.y);
                }
            }
        }
        __syncthreads();
        if (kt + 2 < 16) {
            gemm_load(kt + 2, stu[buf], m0, n0, tid);
            CP_COMMIT();
        }
    }

    // epilogue: rescale (s_x*s_w/16256^2) and scatter into g_qkv
    const float qs = 1.0f / (16256.0f * 16256.0f);
#pragma unroll
    for (int mt = 0; mt < 2; ++mt) {
        int mg0 = m0 + warpm * 32 + mt * 16 + g;
        float sx0 = g_sx[mg0] * qs;
        float sx1 = g_sx[mg0 + 8] * qs;
#pragma unroll
        for (int nt = 0; nt < 8; ++nt) {
            int colg = n0 + warpn * 64 + nt * 8 + 2 * c;
            float sw0 = g_sw[colg];
            float sw1 = g_sw[colg + 1];
            float r0 = ((float)accH[mt][nt][0] * 16384.0f + (float)accM[mt][nt][0] * 128.0f) * sx0 * sw0;
            float r1 = ((float)accH[mt][nt][1] * 16384.0f + (float)accM[mt][nt][1] * 128.0f) * sx0 * sw1;
            float r2 = ((float)accH[mt][nt][2] * 16384.0f + (float)accM[mt][nt][2] * 128.0f) * sx1 * sw0;
            float r3 = ((float)accH[mt][nt][3] * 16384.0f + (float)accM[mt][nt][3] * 128.0f) * sx1 * sw1;
            int part = colg >> 10;
            int pc   = colg & 1023;
            int h    = pc >> 6;
            int dh   = pc & 63;
            int b    = mg0 >> 11;
            int seq  = mg0 & 2047;
            float* dst = g_qkv + ((size_t)((part * BB + b) * HH + h) * NN + seq) * DH + dh;
            *(float2*)dst = make_float2(r0, r1);
            *(float2*)(dst + (size_t)8 * DH) = make_float2(r2, r3);
        }
    }
}

// ---------------------------------------------------------------------------
// Attention prep (R10 proven): Q/K -> bf16 hi/lo pair-permuted (Q prescaled 1/8);
// V -> transposed [d][n] bf16 hi/lo pair-permuted along n.
// ---------------------------------------------------------------------------
__global__ __launch_bounds__(256)
void prep_attn_qk()
{
    int cidx = blockIdx.x * 256 + threadIdx.x;       // 0..524287
    int row  = cidx >> 2;                            // 0..131071 (Q rows then K rows)
    int ch   = cidx & 3;                             // 16-elem chunk within row
    int part = row >> 16;                            // 0 = Q, 1 = K
    const float* src = g_qkv + (size_t)row * 64 + ch * 16;
    float sc = part ? 1.0f : 0.125f;
    float s[16];
    *(float4*)(s)      = ((const float4*)src)[0];
    *(float4*)(s + 4)  = ((const float4*)src)[1];
    *(float4*)(s + 8)  = ((const float4*)src)[2];
    *(float4*)(s + 12) = ((const float4*)src)[3];
#pragma unroll
    for (int k = 0; k < 16; ++k) s[k] *= sc;
    const int pp[8] = {0, 4, 1, 5, 2, 6, 3, 7};
    uint32_t ph[8], pl[8];
#pragma unroll
    for (int d = 0; d < 8; ++d) {
        int p = pp[d];
        split2(s[2 * p], s[2 * p + 1], ph[d], pl[d]);
    }
    size_t off = ((size_t)(row & 65535) * 32) + ch * 8;   // b32 units
    uint32_t* dh = (part ? (uint32_t*)g_kh : (uint32_t*)g_qh) + off;
    uint32_t* dl = (part ? (uint32_t*)g_kl : (uint32_t*)g_ql) + off;
    *(uint4*)(dh)     = make_uint4(ph[0], ph[1], ph[2], ph[3]);
    *(uint4*)(dh + 4) = make_uint4(ph[4], ph[5], ph[6], ph[7]);
    *(uint4*)(dl)     = make_uint4(pl[0], pl[1], pl[2], pl[3]);
    *(uint4*)(dl + 4) = make_uint4(pl[4], pl[5], pl[6], pl[7]);
}

__global__ __launch_bounds__(256)
void prep_attn_v()
{
    __shared__ float t[64][65];
    const int n0 = blockIdx.x * 64;
    const int h  = blockIdx.y;
    const int b  = blockIdx.z;
    const int bh = b * HH + h;
    const int tid = threadIdx.x;
    const float* Vg = g_qkv + (size_t)((2 * BB + b) * HH + h) * NN * DH;
#pragma unroll
    for (int i = 0; i < 16; ++i) {
        int lin = i * 256 + tid;
        int r = lin >> 6, d = lin & 63;
        t[r][d] = Vg[(size_t)(n0 + r) * 64 + d];
    }
    __syncthreads();
    const int d  = tid >> 2;
    const int qq = tid & 3;
    uint32_t* vh = (uint32_t*)g_vh + ((size_t)bh * 64 + d) * 1024;
    uint32_t* vl = (uint32_t*)g_vl + ((size_t)bh * 64 + d) * 1024;
#pragma unroll
    for (int i = 0; i < 8; ++i) {
        int npl = qq * 8 + i;
        float p0 = t[2 * npl][d];
        float p1 = t[2 * npl + 1][d];
        uint32_t hw, lw;
        split2(p0, p1, hw, lw);
        int npg = (n0 >> 1) + npl;
        int dst = (npg & ~7) + dpos8(npg & 7);
        vh[dst] = hw;
        vl[dst] = lw;
    }
}

// ---------------------------------------------------------------------------
// bf16x3 causal flash attention via mma.sync m16n8k16 (R10 proven).
// CTA = 256 thr (8 warps), q-tile 128 (16 rows per warp -> warp-local softmax).
// ---------------------------------------------------------------------------
#define ROWK 36
#define ROWV 68
#define KSTG (128 * ROWK)
#define VSTG (64 * ROWV)
#define ATT_SMEM_B32 (4 * KSTG + 4 * VSTG)
#define ATT_SMEM_BYTES (ATT_SMEM_B32 * 4)

__device__ __forceinline__ void attn_load_kv(
    int kt, int s, int tid, uint32_t sbase,
    const __nv_bfloat16* khg, const __nv_bfloat16* klg,
    const __nv_bfloat16* vhg, const __nv_bfloat16* vlg)
{
    const uint32_t okh = (s ? KSTG : 0) * 4;
    const uint32_t okl = (2 * KSTG + (s ? KSTG : 0)) * 4;
    const uint32_t ovh = (4 * KSTG + (s ? VSTG : 0)) * 4;
    const uint32_t ovl = (4 * KSTG + 2 * VSTG + (s ? VSTG : 0)) * 4;
#pragma unroll
    for (int it = 0; it < 4; ++it) {
        int idx = it * 256 + tid;
        int row = idx >> 3, ch = idx & 7;
        uint32_t doff = (uint32_t)(row * ROWK + ch * 4) * 4;
        size_t so = (size_t)(kt * 128 + row) * 64 + ch * 8;
        CP_ASYNC16(sbase + okh + doff, khg + so);
        CP_ASYNC16(sbase + okl + doff, klg + so);
    }
#pragma unroll
    for (int it = 0; it < 4; ++it) {
        int idx = it * 256 + tid;
        int row = idx >> 4, ch = idx & 15;
        uint32_t doff = (uint32_t)(row * ROWV + ch * 4) * 4;
        size_t so = (size_t)row * NN + kt * 128 + ch * 8;
        CP_ASYNC16(sbase + ovh + doff, vhg + so);
        CP_ASYNC16(sbase + ovl + doff, vlg + so);
    }
}

__global__ __launch_bounds__(256, 1)
void attn_mma(float* __restrict__ out)
{
    extern __shared__ float smf[];
    uint32_t* su = (uint32_t*)smf;
    const uint32_t sbase = smem_u32(smf);
    const int tid  = threadIdx.x;
    const int w    = tid >> 5;
    const int lane = tid & 31;
    const int g    = lane >> 2;
    const int c    = lane & 3;
    const int qb   = (int)gridDim.x - 1 - blockIdx.x;   // heavy tiles first
    const int h    = blockIdx.y;
    const int b    = blockIdx.z;
    const int bh   = b * HH + h;

    const __nv_bfloat16* khg = g_kh + (size_t)bh * NN * DH;
    const __nv_bfloat16* klg = g_kl + (size_t)bh * NN * DH;
    const __nv_bfloat16* vhg = g_vh + (size_t)bh * DH * NN;
    const __nv_bfloat16* vlg = g_vl + (size_t)bh * DH * NN;

    // Q fragments, register-resident for the whole CTA lifetime
    uint2 qfh[4][2], qfl[4][2];
    {
        const uint32_t* qh32 = (const uint32_t*)g_qh;
        const uint32_t* ql32 = (const uint32_t*)g_ql;
        size_t r0 = (size_t)bh * NN + qb * 128 + w * 16 + g;
#pragma unroll
        for (int kd = 0; kd < 4; ++kd) {
            qfh[kd][0] = *(const uint2*)&qh32[r0 * 32 + kd * 8 + 2 * c];
            qfh[kd][1] = *(const uint2*)&qh32[(r0 + 8) * 32 + kd * 8 + 2 * c];
            qfl[kd][0] = *(const uint2*)&ql32[r0 * 32 + kd * 8 + 2 * c];
            qfl[kd][1] = *(const uint2*)&ql32[(r0 + 8) * 32 + kd * 8 + 2 * c];
        }
    }

    float oa[8][4];
#pragma unroll
    for (int nt = 0; nt < 8; ++nt)
#pragma unroll
        for (int v = 0; v < 4; ++v) oa[nt][v] = 0.0f;
    float m0 = -1e30f, m1 = -1e30f, l0 = 0.0f, l1 = 0.0f;

    attn_load_kv(0, 0, tid, sbase, khg, klg, vhg, vlg);
    CP_COMMIT();
    if (qb >= 1) attn_load_kv(1, 1, tid, sbase, khg, klg, vhg, vlg);
    CP_COMMIT();

    for (int kt = 0; kt <= qb; ++kt) {
        if (kt < qb) { CP_WAIT1(); } else { CP_WAIT0(); }
        __syncthreads();
        const int s = kt & 1;
        const uint32_t* KH = su + (s ? KSTG : 0);
        const uint32_t* KL = su + 2 * KSTG + (s ? KSTG : 0);
        const uint32_t* VH = su + 4 * KSTG + (s ? VSTG : 0);
        const uint32_t* VL = su + 4 * KSTG + 2 * VSTG + (s ? VSTG : 0);

        // S = Q @ K^T (bf16x3)
        float sa[16][4];
#pragma unroll
        for (int nt = 0; nt < 16; ++nt) {
            sa[nt][0] = 0.0f; sa[nt][1] = 0.0f; sa[nt][2] = 0.0f; sa[nt][3] = 0.0f;
        }
#pragma unroll
        for (int kd = 0; kd < 4; ++kd) {
#pragma unroll
            for (int nt = 0; nt < 16; ++nt) {
                int a = (8 * nt + g) * ROWK + 8 * kd + 2 * c;
                uint2 kh2 = *(const uint2*)&KH[a];
                uint2 kl2 = *(const uint2*)&KL[a];
                mma_bf16(sa[nt], qfh[kd][0].x, qfh[kd][1].x,
                         qfh[kd][0].y, qfh[kd][1].y, kh2.x, kh2.y);
                mma_bf16(sa[nt], qfh[kd][0].x, qfh[kd][1].x,
                         qfh[kd][0].y, qfh[kd][1].y, kl2.x, kl2.y);
                mma_bf16(sa[nt], qfl[kd][0].x, qfl[kd][1].x,
                         qfl[kd][0].y, qfl[kd][1].y, kh2.x, kh2.y);
            }
        }

        if (kt == qb) {
            int r0 = 16 * w + g, r1 = r0 + 8;
#pragma unroll
            for (int nt = 0; nt < 16; ++nt) {
                int c0 = 8 * nt + 2 * c, c1 = c0 + 1;
                if (c0 > r0) sa[nt][0] = -1e30f;
                if (c1 > r0) sa[nt][1] = -1e30f;
                if (c0 > r1) sa[nt][2] = -1e30f;
                if (c1 > r1) sa[nt][3] = -1e30f;
            }
        }

        // warp-local online softmax
        float mx0 = -1e30f, mx1 = -1e30f;
#pragma unroll
        for (int nt = 0; nt < 16; ++nt) {
            mx0 = fmaxf(mx0, fmaxf(sa[nt][0], sa[nt][1]));
            mx1 = fmaxf(mx1, fmaxf(sa[nt][2], sa[nt][3]));
        }
        mx0 = fmaxf(mx0, __shfl_xor_sync(0xffffffffu, mx0, 1));
        mx0 = fmaxf(mx0, __shfl_xor_sync(0xffffffffu, mx0, 2));
        mx1 = fmaxf(mx1, __shfl_xor_sync(0xffffffffu, mx1, 1));
        mx1 = fmaxf(mx1, __shfl_xor_sync(0xffffffffu, mx1, 2));
        float mn0 = fmaxf(m0, mx0), mn1 = fmaxf(m1, mx1);
        float cr0 = __expf(m0 - mn0), cr1 = __expf(m1 - mn1);
        m0 = mn0; m1 = mn1;
        float rs0 = 0.0f, rs1 = 0.0f;
#pragma unroll
        for (int nt = 0; nt < 16; ++nt) {
            sa[nt][0] = __expf(sa[nt][0] - mn0); rs0 += sa[nt][0];
            sa[nt][1] = __expf(sa[nt][1] - mn0); rs0 += sa[nt][1];
            sa[nt][2] = __expf(sa[nt][2] - mn1); rs1 += sa[nt][2];
            sa[nt][3] = __expf(sa[nt][3] - mn1); rs1 += sa[nt][3];
        }
        rs0 += __shfl_xor_sync(0xffffffffu, rs0, 1);
        rs0 += __shfl_xor_sync(0xffffffffu, rs0, 2);
        rs1 += __shfl_xor_sync(0xffffffffu, rs1, 1);
        rs1 += __shfl_xor_sync(0xffffffffu, rs1, 2);
        l0 = l0 * cr0 + rs0;
        l1 = l1 * cr1 + rs1;
#pragma unroll
        for (int nt = 0; nt < 8; ++nt) {
            oa[nt][0] *= cr0; oa[nt][1] *= cr0;
            oa[nt][2] *= cr1; oa[nt][3] *= cr1;
        }

        // O += P @ V (bf16x3); P fragments packed straight from sa registers
#pragma unroll
        for (int kb = 0; kb < 8; ++kb) {
            uint32_t ah0, ah1, ah2, ah3, al0, al1, al2, al3;
            split2(sa[2 * kb][0],     sa[2 * kb][1],     ah0, al0);
            split2(sa[2 * kb][2],     sa[2 * kb][3],     ah1, al1);
            split2(sa[2 * kb + 1][0], sa[2 * kb + 1][1], ah2, al2);
            split2(sa[2 * kb + 1][2], sa[2 * kb + 1][3], ah3, al3);
#pragma unroll
            for (int nt = 0; nt < 8; ++nt) {
                int a = (8 * nt + g) * ROWV + 8 * kb + 2 * c;
                uint2 vh2 = *(const uint2*)&VH[a];
                uint2 vl2 = *(const uint2*)&VL[a];
                mma_bf16(oa[nt], ah0, ah1, ah2, ah3, vh2.x, vh2.y);
                mma_bf16(oa[nt], al0, al1, al2, al3, vh2.x, vh2.y);
                mma_bf16(oa[nt], ah0, ah1, ah2, ah3, vl2.x, vl2.y);
            }
        }

        __syncthreads();
        if (kt + 2 <= qb) {
            attn_load_kv(kt + 2, s, tid, sbase, khg, klg, vhg, vlg);
            CP_COMMIT();
        }
    }

    // epilogue: out[b][n][h*64 + d]
    float i0 = 1.0f / l0, i1 = 1.0f / l1;
    int r0 = qb * 128 + 16 * w + g;
    float* o0 = out + ((size_t)b * NN + r0) * DD + h * 64;
    float* o1 = o0 + (size_t)8 * DD;
#pragma unroll
    for (int nt = 0; nt < 8; ++nt) {
        *(float2*)&o0[8 * nt + 2 * c] = make_float2(oa[nt][0] * i0, oa[nt][1] * i0);
        *(float2*)&o1[8 * nt + 2 * c] = make_float2(oa[nt][2] * i1, oa[nt][3] * i1);
    }
}

// ---------------------------------------------------------------------------
extern "C" void kernel_launch(void* const* d_in, const int* in_sizes, int n_in,
                              void* d_out, int out_size)
{
    const float* x = (const float*)d_in[0];   // [2,2048,1024] fp32
    const float* w = (const float*)d_in[1];   // [1024,3072] fp32
    float* out = (float*)d_out;               // [2,2048,1024] fp32
    (void)in_sizes; (void)n_in; (void)out_size;

    // int8 GEMM operand prep
    prep_xi<<<MM, 256>>>(x);
    w_absmax<<<D3 / 256, 256>>>(w);
    prep_wq<<<dim3(D3 / 32, DD / 32), dim3(32, 8)>>>(w);

    // int8x3 IMMA QKV GEMM
    cudaFuncSetAttribute(qkv_gemm_imma,
                         cudaFuncAttributeMaxDynamicSharedMemorySize,
                         GEMM_SMEM_TOTAL);
    qkv_gemm_imma<<<dim3(D3 / 128, MM / 128), 256, GEMM_SMEM_TOTAL>>>();

    // attention operand prep (Q/K rows, V transpose) — bf16 (R10)
    prep_attn_qk<<<2048, 256>>>();
    prep_attn_v<<<dim3(NN / 64, HH, BB), 256>>>();

    // bf16x3 mma flash attention (R10)
    cudaFuncSetAttribute(attn_mma,
                         cudaFuncAttributeMaxDynamicSharedMemorySize,
                         ATT_SMEM_BYTES);
    attn_mma<<<dim3(NN / 128, HH, BB), 256, ATT_SMEM_BYTES>>>(out);
}

// round 14
// speedup vs baseline: 1.3436x; 1.0300x over previous
#include <cuda_runtime.h>
#include <cuda_bf16.h>
#include <cstdint>

// Problem constants
#define BB 2
#define NN 2048
#define HH 16
#define DH 64
#define DD 1024          // HH*DH
#define D3 3072          // 3*DD
#define MM 4096          // BB*NN
#define BHND ((size_t)BB * HH * NN * DH)

// Scratch: QKV laid out [part(q/k/v)][B][H][N][Dh], fp32
__device__ float g_qkv[3u * BB * HH * NN * DH];
// int8 GEMM operands: A = 128*a1 + a2 fixed point, quad-permuted per 32-k block
__device__ float  g_sx[MM];                  // per-row scale of X
__device__ float  g_sw[D3];                  // per-col scale of W
__device__ int8_t g_xa[(size_t)MM * DD];     // a1 (high word)
__device__ int8_t g_xb[(size_t)MM * DD];     // a2 (low word)
__device__ int8_t g_wa[(size_t)D3 * DD];     // [n][k'] b1
__device__ int8_t g_wb[(size_t)D3 * DD];     // [n][k'] b2
// int8 attention Q/K (2-word, quad-permuted), global scales
__device__ int    g_gqi;                     // max|Q| as float bits
__device__ int    g_gki;                     // max|K| as float bits
__device__ int8_t g_qa[BHND];                // [bh][n][d] a1
__device__ int8_t g_qb[BHND];                // a2
__device__ int8_t g_ka[BHND];
__device__ int8_t g_kb[BHND];
// V stays bf16 hi/lo transposed [bh][d][n], pair-permuted
__device__ __nv_bfloat16 g_vh[(size_t)BB * HH * DH * NN];
__device__ __nv_bfloat16 g_vl[(size_t)BB * HH * DH * NN];

// ---------------------------------------------------------------------------
// helpers
// ---------------------------------------------------------------------------
#define CP_ASYNC16(dst_u32, gptr)                                              \
    asm volatile("cp.async.cg.shared.global [%0], [%1], 16;"                    \
                 :: "r"(dst_u32), "l"(__cvta_generic_to_global(gptr)))
#define CP_COMMIT() asm volatile("cp.async.commit_group;" ::: "memory")
#define CP_WAIT1()  asm volatile("cp.async.wait_group 1;" ::: "memory")
#define CP_WAIT0()  asm volatile("cp.async.wait_group 0;" ::: "memory")

__device__ __forceinline__ uint32_t smem_u32(const void* p) {
    uint32_t a;
    asm("{ .reg .u64 t; cvta.to.shared.u64 t, %1; cvt.u32.u64 %0, t; }"
        : "=r"(a) : "l"(p));
    return a;
}

// mma.sync m16n8k32 s8: d += a * b  (exact s32 accumulate)
__device__ __forceinline__ void mma_s8(int* d,
                                       uint32_t a0, uint32_t a1, uint32_t a2, uint32_t a3,
                                       uint32_t b0, uint32_t b1) {
    asm volatile(
        "mma.sync.aligned.m16n8k32.row.col.s32.s8.s8.s32 "
        "{%0,%1,%2,%3}, {%4,%5,%6,%7}, {%8,%9}, {%0,%1,%2,%3};"
        : "+r"(d[0]), "+r"(d[1]), "+r"(d[2]), "+r"(d[3])
        : "r"(a0), "r"(a1), "r"(a2), "r"(a3), "r"(b0), "r"(b1));
}

// mma.sync m16n8k16 bf16: d += a * b  (f32 accumulate) — PV
__device__ __forceinline__ void mma_bf16(float* d,
                                         uint32_t a0, uint32_t a1, uint32_t a2, uint32_t a3,
                                         uint32_t b0, uint32_t b1) {
    asm volatile(
        "mma.sync.aligned.m16n8k16.row.col.f32.bf16.bf16.f32 "
        "{%0,%1,%2,%3}, {%4,%5,%6,%7}, {%8,%9}, {%0,%1,%2,%3};"
        : "+f"(d[0]), "+f"(d[1]), "+f"(d[2]), "+f"(d[3])
        : "r"(a0), "r"(a1), "r"(a2), "r"(a3), "r"(b0), "r"(b1));
}

__device__ __forceinline__ uint32_t pack_bf16(float x0, float x1) {
    __nv_bfloat16 h0 = __float2bfloat16_rn(x0);
    __nv_bfloat16 h1 = __float2bfloat16_rn(x1);
    return (uint32_t)__bfloat16_as_ushort(h0) |
           ((uint32_t)__bfloat16_as_ushort(h1) << 16);
}

__device__ __forceinline__ void split2(float x0, float x1, uint32_t& h, uint32_t& l) {
    __nv_bfloat16 h0 = __float2bfloat16_rn(x0);
    __nv_bfloat16 h1 = __float2bfloat16_rn(x1);
    h = (uint32_t)__bfloat16_as_ushort(h0) |
        ((uint32_t)__bfloat16_as_ushort(h1) << 16);
    l = pack_bf16(x0 - __bfloat162float(h0), x1 - __bfloat162float(h1));
}

__device__ __forceinline__ int dpos8(int p) {   // dest slot of source pair/quad p
    return ((p & 3) << 1) | (p >> 2);
}

// quantize x*inv_s into 2 int8 words: A = rn(x*inv_s) = 128*a1 + a2
__device__ __forceinline__ void quant2(float x, float inv_s, int& a1, int& a2) {
    int A = __float2int_rn(x * inv_s);
    a1 = __float2int_rn((float)A * (1.0f / 128.0f));
    a2 = A - (a1 << 7);
}

__device__ __forceinline__ uint32_t packq(int a0, int a1, int a2, int a3) {
    return (uint32_t)(uint8_t)(int8_t)a0 | ((uint32_t)(uint8_t)(int8_t)a1 << 8) |
           ((uint32_t)(uint8_t)(int8_t)a2 << 16) | ((uint32_t)(uint8_t)(int8_t)a3 << 24);
}

// ---------------------------------------------------------------------------
// int8 GEMM prep (unchanged, R13 proven)
// ---------------------------------------------------------------------------
__global__ __launch_bounds__(256)
void prep_xi(const float* __restrict__ X)
{
    __shared__ float red[8];
    __shared__ float s_sh;
    const int row = blockIdx.x;
    const int t   = threadIdx.x;
    float4 v = *(const float4*)(X + (size_t)row * DD + t * 4);
    float mx = fmaxf(fmaxf(fabsf(v.x), fabsf(v.y)), fmaxf(fabsf(v.z), fabsf(v.w)));
#pragma unroll
    for (int o = 16; o > 0; o >>= 1)
        mx = fmaxf(mx, __shfl_xor_sync(0xffffffffu, mx, o));
    if ((t & 31) == 0) red[t >> 5] = mx;
    __syncthreads();
    if (t == 0) {
        float m = red[0];
#pragma unroll
        for (int i = 1; i < 8; ++i) m = fmaxf(m, red[i]);
        s_sh = fmaxf(m, 1e-20f);
        g_sx[row] = s_sh;
    }
    __syncthreads();
    const float inv_s = 16256.0f / s_sh;

    int a1[4], a2[4];
    quant2(v.x, inv_s, a1[0], a2[0]);
    quant2(v.y, inv_s, a1[1], a2[1]);
    quant2(v.z, inv_s, a1[2], a2[2]);
    quant2(v.w, inv_s, a1[3], a2[3]);
    int widx = row * 256 + (t & ~7) + dpos8(t & 7);
    ((uint32_t*)g_xa)[widx] = packq(a1[0], a1[1], a1[2], a1[3]);
    ((uint32_t*)g_xb)[widx] = packq(a2[0], a2[1], a2[2], a2[3]);
}

__global__ __launch_bounds__(256)
void w_absmax(const float* __restrict__ W)
{
    int n = blockIdx.x * 256 + threadIdx.x;
    float m = 0.0f;
    for (int k = 0; k < DD; ++k)
        m = fmaxf(m, fabsf(W[(size_t)k * D3 + n]));
    g_sw[n] = fmaxf(m, 1e-20f);
}

__device__ __forceinline__ int kpermq(int k) {   // k in 0..31, quad permutation
    return ((dpos8((k >> 2) & 7)) << 2) | (k & 3);
}

__global__ __launch_bounds__(256)
void prep_wq(const float* __restrict__ W)
{
    __shared__ float t[32][33];
    const int n0 = blockIdx.x * 32;
    const int k0 = blockIdx.y * 32;
    const int tx = threadIdx.x, ty = threadIdx.y;   // (32, 8)
#pragma unroll
    for (int rr = 0; rr < 32; rr += 8)
        t[ty + rr][tx] = W[(size_t)(k0 + ty + rr) * D3 + n0 + tx];
    __syncthreads();
#pragma unroll
    for (int rr = 0; rr < 32; rr += 8) {
        int n = n0 + ty + rr;
        float inv_s = 16256.0f / g_sw[n];
        float v = t[tx][ty + rr];
        int b1, b2;
        quant2(v, inv_s, b1, b2);
        size_t base = (size_t)n * DD + k0 + kpermq(tx);
        g_wa[base] = (int8_t)b1;
        g_wb[base] = (int8_t)b2;
    }
}

// ---------------------------------------------------------------------------
// int8x3 QKV GEMM via mma.sync m16n8k32, 512 threads (16 warps 4m x 4n,
// warp tile 32x32) for latency hiding. CTA 128x128, k-chunk 64, 2-stage.
// ---------------------------------------------------------------------------
#define ROWW 20                 // row stride in b32 (80 bytes)
#define OA1 0
#define OA2 2560
#define OB1 5120
#define OB2 7680
#define ST_B32 10240            // 40KB per stage
#define GEMM_SMEM_TOTAL (2 * ST_B32 * 4)

__device__ __forceinline__ void gemm_load(int kt, uint32_t st_u32,
                                          int m0, int n0, int tid)
{
    const int k0 = kt * 64;
    int row = tid >> 2;
    int ch  = tid & 3;
    uint32_t doff = (uint32_t)(row * ROWW + ch * 4) * 4;
    CP_ASYNC16(st_u32 + OA1 * 4 + doff, g_xa + (size_t)(m0 + row) * DD + k0 + ch * 16);
    CP_ASYNC16(st_u32 + OA2 * 4 + doff, g_xb + (size_t)(m0 + row) * DD + k0 + ch * 16);
    CP_ASYNC16(st_u32 + OB1 * 4 + doff, g_wa + (size_t)(n0 + row) * DD + k0 + ch * 16);
    CP_ASYNC16(st_u32 + OB2 * 4 + doff, g_wb + (size_t)(n0 + row) * DD + k0 + ch * 16);
}

__global__ __launch_bounds__(512, 1)
void qkv_gemm_imma()
{
    extern __shared__ float sm[];
    const int tid   = threadIdx.x;
    const int wid   = tid >> 5;
    const int lane  = tid & 31;
    const int warpm = wid & 3;        // 4 warps over m (32 rows each)
    const int warpn = wid >> 2;       // 4 warps over n (32 cols each)
    const int c     = lane & 3;
    const int g     = lane >> 2;
    const int n0    = blockIdx.x * 128;
    const int m0    = blockIdx.y * 128;

    const uint32_t* st[2] = {(const uint32_t*)sm, (const uint32_t*)sm + ST_B32};
    uint32_t stu[2] = {smem_u32(sm), smem_u32(sm + ST_B32)};

    int accH[2][4][4];   // a1*b1 (scale 16384)
    int accM[2][4][4];   // a1*b2 + a2*b1 (scale 128)
#pragma unroll
    for (int mt = 0; mt < 2; ++mt)
#pragma unroll
        for (int nt = 0; nt < 4; ++nt)
#pragma unroll
            for (int v = 0; v < 4; ++v) { accH[mt][nt][v] = 0; accM[mt][nt][v] = 0; }

    gemm_load(0, stu[0], m0, n0, tid); CP_COMMIT();
    gemm_load(1, stu[1], m0, n0, tid); CP_COMMIT();

    for (int kt = 0; kt < 16; ++kt) {
        const int buf = kt & 1;
        if (kt < 14) { CP_WAIT1(); } else { CP_WAIT0(); }
        __syncthreads();

        const uint32_t* S = st[buf];
#pragma unroll
        for (int ks = 0; ks < 2; ++ks) {
            const int kc = ks * 8 + 2 * c;
            uint2 a1f[2][2], a2f[2][2];
#pragma unroll
            for (int mt = 0; mt < 2; ++mt) {
                int rbase = warpm * 32 + mt * 16 + g;
                a1f[mt][0] = *(const uint2*)&S[OA1 + rbase * ROWW + kc];
                a1f[mt][1] = *(const uint2*)&S[OA1 + (rbase + 8) * ROWW + kc];
                a2f[mt][0] = *(const uint2*)&S[OA2 + rbase * ROWW + kc];
                a2f[mt][1] = *(const uint2*)&S[OA2 + (rbase + 8) * ROWW + kc];
            }
#pragma unroll
            for (int nt = 0; nt < 4; ++nt) {
                int nb = (warpn * 32 + nt * 8 + g) * ROWW + kc;
                uint2 b1 = *(const uint2*)&S[OB1 + nb];
                uint2 b2 = *(const uint2*)&S[OB2 + nb];
#pragma unroll
                for (int mt = 0; mt < 2; ++mt) {
                    mma_s8(accH[mt][nt], a1f[mt][0].x, a1f[mt][1].x,
                           a1f[mt][0].y, a1f[mt][1].y, b1.x, b1.y);
                    mma_s8(accM[mt][nt], a1f[mt][0].x, a1f[mt][1].x,
                           a1f[mt][0].y, a1f[mt][1].y, b2.x, b2.y);
                    mma_s8(accM[mt][nt], a2f[mt][0].x, a2f[mt][1].x,
                           a2f[mt][0].y, a2f[mt][1].y, b1.x, b1.y);
                }
            }
        }
        __syncthreads();
        if (kt + 2 < 16) {
            gemm_load(kt + 2, stu[buf], m0, n0, tid);
            CP_COMMIT();
        }
    }

    // epilogue: rescale and scatter into g_qkv
    const float qs = 1.0f / (16256.0f * 16256.0f);
#pragma unroll
    for (int mt = 0; mt < 2; ++mt) {
        int mg0 = m0 + warpm * 32 + mt * 16 + g;
        float sx0 = g_sx[mg0] * qs;
        float sx1 = g_sx[mg0 + 8] * qs;
#pragma unroll
        for (int nt = 0; nt < 4; ++nt) {
            int colg = n0 + warpn * 32 + nt * 8 + 2 * c;
            float sw0 = g_sw[colg];
            float sw1 = g_sw[colg + 1];
            float r0 = ((float)accH[mt][nt][0] * 16384.0f + (float)accM[mt][nt][0] * 128.0f) * sx0 * sw0;
            float r1 = ((float)accH[mt][nt][1] * 16384.0f + (float)accM[mt][nt][1] * 128.0f) * sx0 * sw1;
            float r2 = ((float)accH[mt][nt][2] * 16384.0f + (float)accM[mt][nt][2] * 128.0f) * sx1 * sw0;
            float r3 = ((float)accH[mt][nt][3] * 16384.0f + (float)accM[mt][nt][3] * 128.0f) * sx1 * sw1;
            int part = colg >> 10;
            int pc   = colg & 1023;
            int h    = pc >> 6;
            int dh   = pc & 63;
            int b    = mg0 >> 11;
            int seq  = mg0 & 2047;
            float* dst = g_qkv + ((size_t)((part * BB + b) * HH + h) * NN + seq) * DH + dh;
            *(float2*)dst = make_float2(r0, r1);
            *(float2*)(dst + (size_t)8 * DH) = make_float2(r2, r3);
        }
    }
}

// ---------------------------------------------------------------------------
// Attention prep: global |max| of Q and K regions, then int8 2-word quantize
// (quad-permuted). V -> transposed bf16 hi/lo (unchanged, proven).
// ---------------------------------------------------------------------------
__global__ __launch_bounds__(256)
void qk_absmax()
{
    size_t idx = (size_t)blockIdx.x * 256 + threadIdx.x;
    const float* src = g_qkv + idx * 16;
    float mx = 0.0f;
#pragma unroll
    for (int i = 0; i < 4; ++i) {
        float4 v = ((const float4*)src)[i];
        mx = fmaxf(mx, fmaxf(fmaxf(fabsf(v.x), fabsf(v.y)), fmaxf(fabsf(v.z), fabsf(v.w))));
    }
#pragma unroll
    for (int o = 16; o > 0; o >>= 1)
        mx = fmaxf(mx, __shfl_xor_sync(0xffffffffu, mx, o));
    if ((threadIdx.x & 31) == 0) {
        int* dst = (idx * 16 >= BHND) ? &g_gki : &g_gqi;
        atomicMax(dst, __float_as_int(mx));
    }
}

__global__ __launch_bounds__(256)
void prep_attn_qki8()
{
    int cidx = blockIdx.x * 256 + threadIdx.x;       // 0..524287
    int row  = cidx >> 2;                            // Q rows then K rows
    int ch   = cidx & 3;                             // 16-elem chunk within row
    int part = row >> 16;                            // 0 = Q, 1 = K
    float gs = __int_as_float(part ? g_gki : g_gqi);
    float inv_s = 16256.0f / fmaxf(gs, 1e-20f);
    const float* src = g_qkv + (size_t)row * 64 + ch * 16;
    float s[16];
    *(float4*)(s)      = ((const float4*)src)[0];
    *(float4*)(s + 4)  = ((const float4*)src)[1];
    *(float4*)(s + 8)  = ((const float4*)src)[2];
    *(float4*)(s + 12) = ((const float4*)src)[3];
    uint32_t* da = (part ? (uint32_t*)g_ka : (uint32_t*)g_qa);
    uint32_t* db = (part ? (uint32_t*)g_kb : (uint32_t*)g_qb);
    int rbase = (row & 65535) * 16 + (ch >> 1) * 8 + (ch & 1);
#pragma unroll
    for (int i = 0; i < 4; ++i) {
        int a1[4], a2[4];
        quant2(s[4 * i + 0], inv_s, a1[0], a2[0]);
        quant2(s[4 * i + 1], inv_s, a1[1], a2[1]);
        quant2(s[4 * i + 2], inv_s, a1[2], a2[2]);
        quant2(s[4 * i + 3], inv_s, a1[3], a2[3]);
        int dst = rbase + 2 * i;
        da[dst] = packq(a1[0], a1[1], a1[2], a1[3]);
        db[dst] = packq(a2[0], a2[1], a2[2], a2[3]);
    }
}

__global__ __launch_bounds__(256)
void prep_attn_v()
{
    __shared__ float t[64][65];
    const int n0 = blockIdx.x * 64;
    const int h  = blockIdx.y;
    const int b  = blockIdx.z;
    const int bh = b * HH + h;
    const int tid = threadIdx.x;
    const float* Vg = g_qkv + (size_t)((2 * BB + b) * HH + h) * NN * DH;
#pragma unroll
    for (int i = 0; i < 16; ++i) {
        int lin = i * 256 + tid;
        int r = lin >> 6, d = lin & 63;
        t[r][d] = Vg[(size_t)(n0 + r) * 64 + d];
    }
    __syncthreads();
    const int d  = tid >> 2;
    const int qq = tid & 3;
    uint32_t* vh = (uint32_t*)g_vh + ((size_t)bh * 64 + d) * 1024;
    uint32_t* vl = (uint32_t*)g_vl + ((size_t)bh * 64 + d) * 1024;
#pragma unroll
    for (int i = 0; i < 8; ++i) {
        int npl = qq * 8 + i;
        float p0 = t[2 * npl][d];
        float p1 = t[2 * npl + 1][d];
        uint32_t hw, lw;
        split2(p0, p1, hw, lw);
        int npg = (n0 >> 1) + npl;
        int dst = (npg & ~7) + dpos8(npg & 7);
        vh[dst] = hw;
        vl[dst] = lw;
    }
}

// ---------------------------------------------------------------------------
// Causal flash attention: int8x3 QK^T (m16n8k32) + bf16x3 PV (m16n8k16).
// CTA = 256 thr (8 warps), q-tile 128 (16 rows/warp -> warp-local softmax).
// ---------------------------------------------------------------------------
#define ROWKI 20                // b32 per K int8 smem row (16 data + 4 pad)
#define ROWV 68                 // b32 per V smem row (64 data + 4 pad)
#define KSTGI (128 * ROWKI)     // 2560 b32
#define VSTG (64 * ROWV)        // 4352 b32
#define ATT_SMEM_B32 (4 * KSTGI + 4 * VSTG)
#define ATT_SMEM_BYTES (ATT_SMEM_B32 * 4)

__device__ __forceinline__ void attn_load_kv(
    int kt, int s, int tid, uint32_t sbase,
    const int8_t* kag, const int8_t* kbg,
    const __nv_bfloat16* vhg, const __nv_bfloat16* vlg)
{
    const uint32_t oka = (s ? KSTGI : 0) * 4;
    const uint32_t okb = (2 * KSTGI + (s ? KSTGI : 0)) * 4;
    const uint32_t ovh = (4 * KSTGI + (s ? VSTG : 0)) * 4;
    const uint32_t ovl = (4 * KSTGI + 2 * VSTG + (s ? VSTG : 0)) * 4;
#pragma unroll
    for (int it = 0; it < 2; ++it) {
        int idx = it * 256 + tid;
        int row = idx >> 2, ch = idx & 3;
        uint32_t doff = (uint32_t)(row * ROWKI + ch * 4) * 4;
        size_t so = (size_t)(kt * 128 + row) * 64 + ch * 16;
        CP_ASYNC16(sbase + oka + doff, kag + so);
        CP_ASYNC16(sbase + okb + doff, kbg + so);
    }
#pragma unroll
    for (int it = 0; it < 4; ++it) {
        int idx = it * 256 + tid;
        int row = idx >> 4, ch = idx & 15;
        uint32_t doff = (uint32_t)(row * ROWV + ch * 4) * 4;
        size_t so = (size_t)row * NN + kt * 128 + ch * 8;
        CP_ASYNC16(sbase + ovh + doff, vhg + so);
        CP_ASYNC16(sbase + ovl + doff, vlg + so);
    }
}

__global__ __launch_bounds__(256, 1)
void attn_mma(float* __restrict__ out)
{
    extern __shared__ float smf[];
    uint32_t* su = (uint32_t*)smf;
    const uint32_t sbase = smem_u32(smf);
    const int tid  = threadIdx.x;
    const int w    = tid >> 5;
    const int lane = tid & 31;
    const int g    = lane >> 2;
    const int c    = lane & 3;
    const int qb   = (int)gridDim.x - 1 - blockIdx.x;   // heavy tiles first
    const int h    = blockIdx.y;
    const int b    = blockIdx.z;
    const int bh   = b * HH + h;

    const int8_t* kag = g_ka + (size_t)bh * NN * DH;
    const int8_t* kbg = g_kb + (size_t)bh * NN * DH;
    const __nv_bfloat16* vhg = g_vh + (size_t)bh * DH * NN;
    const __nv_bfloat16* vlg = g_vl + (size_t)bh * DH * NN;

    // combined S scale: gq*gk/(16256^2) * (1/sqrt(64))
    const float fs = __int_as_float(g_gqi) * __int_as_float(g_gki) *
                     (1.0f / (16256.0f * 16256.0f)) * 0.125f;

    // Q int8 fragments, register-resident
    uint2 qfa[2][2], qfb[2][2];   // [kd][rowhalf]
    {
        const uint32_t* qa32 = (const uint32_t*)g_qa;
        const uint32_t* qb32 = (const uint32_t*)g_qb;
        size_t r0 = (size_t)bh * NN + qb * 128 + w * 16 + g;
#pragma unroll
        for (int kd = 0; kd < 2; ++kd) {
            qfa[kd][0] = *(const uint2*)&qa32[r0 * 16 + kd * 8 + 2 * c];
            qfa[kd][1] = *(const uint2*)&qa32[(r0 + 8) * 16 + kd * 8 + 2 * c];
            qfb[kd][0] = *(const uint2*)&qb32[r0 * 16 + kd * 8 + 2 * c];
            qfb[kd][1] = *(const uint2*)&qb32[(r0 + 8) * 16 + kd * 8 + 2 * c];
        }
    }

    float oa[8][4];
#pragma unroll
    for (int nt = 0; nt < 8; ++nt)
#pragma unroll
        for (int v = 0; v < 4; ++v) oa[nt][v] = 0.0f;
    float m0 = -1e30f, m1 = -1e30f, l0 = 0.0f, l1 = 0.0f;

    attn_load_kv(0, 0, tid, sbase, kag, kbg, vhg, vlg);
    CP_COMMIT();
    if (qb >= 1) attn_load_kv(1, 1, tid, sbase, kag, kbg, vhg, vlg);
    CP_COMMIT();

    for (int kt = 0; kt <= qb; ++kt) {
        if (kt < qb) { CP_WAIT1(); } else { CP_WAIT0(); }
        __syncthreads();
        const int s = kt & 1;
        const uint32_t* KA = su + (s ? KSTGI : 0);
        const uint32_t* KB = su + 2 * KSTGI + (s ? KSTGI : 0);
        const uint32_t* VH = su + 4 * KSTGI + (s ? VSTG : 0);
        const uint32_t* VL = su + 4 * KSTGI + 2 * VSTG + (s ? VSTG : 0);

        // S = Q @ K^T via int8x3 (two 8-nt halves to cap registers)
        float sa[16][4];
#pragma unroll
        for (int hf = 0; hf < 2; ++hf) {
            int accH[8][4], accM[8][4];
#pragma unroll
            for (int nt = 0; nt < 8; ++nt)
#pragma unroll
                for (int v = 0; v < 4; ++v) { accH[nt][v] = 0; accM[nt][v] = 0; }
#pragma unroll
            for (int kd = 0; kd < 2; ++kd) {
#pragma unroll
                for (int nt = 0; nt < 8; ++nt) {
                    int ntg = hf * 8 + nt;
                    int a = (8 * ntg + g) * ROWKI + kd * 8 + 2 * c;
                    uint2 b1 = *(const uint2*)&KA[a];
                    uint2 b2 = *(const uint2*)&KB[a];
                    mma_s8(accH[nt], qfa[kd][0].x, qfa[kd][1].x,
                           qfa[kd][0].y, qfa[kd][1].y, b1.x, b1.y);
                    mma_s8(accM[nt], qfa[kd][0].x, qfa[kd][1].x,
                           qfa[kd][0].y, qfa[kd][1].y, b2.x, b2.y);
                    mma_s8(accM[nt], qfb[kd][0].x, qfb[kd][1].x,
                           qfb[kd][0].y, qfb[kd][1].y, b1.x, b1.y);
                }
            }
#pragma unroll
            for (int nt = 0; nt < 8; ++nt) {
                int ntg = hf * 8 + nt;
#pragma unroll
                for (int v = 0; v < 4; ++v)
                    sa[ntg][v] = ((float)accH[nt][v] * 16384.0f +
                                  (float)accM[nt][v] * 128.0f) * fs;
            }
        }

        // causal mask on the diagonal tile
        if (kt == qb) {
            int r0 = 16 * w + g, r1 = r0 + 8;
#pragma unroll
            for (int nt = 0; nt < 16; ++nt) {
                int c0 = 8 * nt + 2 * c, c1 = c0 + 1;
                if (c0 > r0) sa[nt][0] = -1e30f;
                if (c1 > r0) sa[nt][1] = -1e30f;
                if (c0 > r1) sa[nt][2] = -1e30f;
                if (c1 > r1) sa[nt][3] = -1e30f;
            }
        }

        // warp-local online softmax
        float mx0 = -1e30f, mx1 = -1e30f;
#pragma unroll
        for (int nt = 0; nt < 16; ++nt) {
            mx0 = fmaxf(mx0, fmaxf(sa[nt][0], sa[nt][1]));
            mx1 = fmaxf(mx1, fmaxf(sa[nt][2], sa[nt][3]));
        }
        mx0 = fmaxf(mx0, __shfl_xor_sync(0xffffffffu, mx0, 1));
        mx0 = fmaxf(mx0, __shfl_xor_sync(0xffffffffu, mx0, 2));
        mx1 = fmaxf(mx1, __shfl_xor_sync(0xffffffffu, mx1, 1));
        mx1 = fmaxf(mx1, __shfl_xor_sync(0xffffffffu, mx1, 2));
        float mn0 = fmaxf(m0, mx0), mn1 = fmaxf(m1, mx1);
        float cr0 = __expf(m0 - mn0), cr1 = __expf(m1 - mn1);
        m0 = mn0; m1 = mn1;
        float rs0 = 0.0f, rs1 = 0.0f;
#pragma unroll
        for (int nt = 0; nt < 16; ++nt) {
            sa[nt][0] = __expf(sa[nt][0] - mn0); rs0 += sa[nt][0];
            sa[nt][1] = __expf(sa[nt][1] - mn0); rs0 += sa[nt][1];
            sa[nt][2] = __expf(sa[nt][2] - mn1); rs1 += sa[nt][2];
            sa[nt][3] = __expf(sa[nt][3] - mn1); rs1 += sa[nt][3];
        }
        rs0 += __shfl_xor_sync(0xffffffffu, rs0, 1);
        rs0 += __shfl_xor_sync(0xffffffffu, rs0, 2);
        rs1 += __shfl_xor_sync(0xffffffffu, rs1, 1);
        rs1 += __shfl_xor_sync(0xffffffffu, rs1, 2);
        l0 = l0 * cr0 + rs0;
        l1 = l1 * cr1 + rs1;
#pragma unroll
        for (int nt = 0; nt < 8; ++nt) {
            oa[nt][0] *= cr0; oa[nt][1] *= cr0;
            oa[nt][2] *= cr1; oa[nt][3] *= cr1;
        }

        // O += P @ V (bf16x3); P fragments packed straight from sa registers
#pragma unroll
        for (int kb = 0; kb < 8; ++kb) {
            uint32_t ah0, ah1, ah2, ah3, al0, al1, al2, al3;
            split2(sa[2 * kb][0],     sa[2 * kb][1],     ah0, al0);
            split2(sa[2 * kb][2],     sa[2 * kb][3],     ah1, al1);
            split2(sa[2 * kb + 1][0], sa[2 * kb + 1][1], ah2, al2);
            split2(sa[2 * kb + 1][2], sa[2 * kb + 1][3], ah3, al3);
#pragma unroll
            for (int nt = 0; nt < 8; ++nt) {
                int a = (8 * nt + g) * ROWV + 8 * kb + 2 * c;
                uint2 vh2 = *(const uint2*)&VH[a];
                uint2 vl2 = *(const uint2*)&VL[a];
                mma_bf16(oa[nt], ah0, ah1, ah2, ah3, vh2.x, vh2.y);
                mma_bf16(oa[nt], al0, al1, al2, al3, vh2.x, vh2.y);
                mma_bf16(oa[nt], ah0, ah1, ah2, ah3, vl2.x, vl2.y);
            }
        }

        __syncthreads();
        if (kt + 2 <= qb) {
            attn_load_kv(kt + 2, s, tid, sbase, kag, kbg, vhg, vlg);
            CP_COMMIT();
        }
    }

    // epilogue: out[b][n][h*64 + d]
    float i0 = 1.0f / l0, i1 = 1.0f / l1;
    int r0 = qb * 128 + 16 * w + g;
    float* o0 = out + ((size_t)b * NN + r0) * DD + h * 64;
    float* o1 = o0 + (size_t)8 * DD;
#pragma unroll
    for (int nt = 0; nt < 8; ++nt) {
        *(float2*)&o0[8 * nt + 2 * c] = make_float2(oa[nt][0] * i0, oa[nt][1] * i0);
        *(float2*)&o1[8 * nt + 2 * c] = make_float2(oa[nt][2] * i1, oa[nt][3] * i1);
    }
}

// ---------------------------------------------------------------------------
extern "C" void kernel_launch(void* const* d_in, const int* in_sizes, int n_in,
                              void* d_out, int out_size)
{
    const float* x = (const float*)d_in[0];   // [2,2048,1024] fp32
    const float* w = (const float*)d_in[1];   // [1024,3072] fp32
    float* out = (float*)d_out;               // [2,2048,1024] fp32
    (void)in_sizes; (void)n_in; (void)out_size;

    // int8 GEMM operand prep
    prep_xi<<<MM, 256>>>(x);
    w_absmax<<<D3 / 256, 256>>>(w);
    prep_wq<<<dim3(D3 / 32, DD / 32), dim3(32, 8)>>>(w);

    // int8x3 IMMA QKV GEMM (512 threads / CTA)
    cudaFuncSetAttribute(qkv_gemm_imma,
                         cudaFuncAttributeMaxDynamicSharedMemorySize,
                         GEMM_SMEM_TOTAL);
    qkv_gemm_imma<<<dim3(D3 / 128, MM / 128), 512, GEMM_SMEM_TOTAL>>>();

    // attention operand prep: global scales, int8 Q/K, bf16 V transpose
    qk_absmax<<<2048, 256>>>();
    prep_attn_qki8<<<2048, 256>>>();
    prep_attn_v<<<dim3(NN / 64, HH, BB), 256>>>();

    // int8 QK^T + bf16x3 PV flash attention
    cudaFuncSetAttribute(attn_mma,
                         cudaFuncAttributeMaxDynamicSharedMemorySize,
                         ATT_SMEM_BYTES);
    attn_mma<<<dim3(NN / 128, HH, BB), 256, ATT_SMEM_BYTES>>>(out);
}

// round 15
// speedup vs baseline: 1.3490x; 1.0040x over previous
#include <cuda_runtime.h>
#include <cuda_bf16.h>
#include <cstdint>

// Problem constants
#define BB 2
#define NN 2048
#define HH 16
#define DH 64
#define DD 1024          // HH*DH
#define D3 3072          // 3*DD
#define MM 4096          // BB*NN
#define BHND ((size_t)BB * HH * NN * DH)

// Scratch: QKV laid out [part(q/k/v)][B][H][N][Dh], fp32
__device__ float g_qkv[3u * BB * HH * NN * DH];
// int8 GEMM operands
__device__ float  g_sx[MM];
__device__ float  g_sw[D3];
__device__ int8_t g_xa[(size_t)MM * DD];
__device__ int8_t g_xb[(size_t)MM * DD];
__device__ int8_t g_wa[(size_t)D3 * DD];
__device__ int8_t g_wb[(size_t)D3 * DD];
// global absmax of Q/K/V (float bits), computed in GEMM epilogue
__device__ int    g_gi[3];
// int8 attention operands (2-word, quad-permuted)
__device__ int8_t g_qa[BHND];                // [bh][n][d]
__device__ int8_t g_qb[BHND];
__device__ int8_t g_ka[BHND];
__device__ int8_t g_kb[BHND];
__device__ int8_t g_va[BHND];                // [bh][d][n] transposed
__device__ int8_t g_vb[BHND];

// ---------------------------------------------------------------------------
// helpers
// ---------------------------------------------------------------------------
#define CP_ASYNC16(dst_u32, gptr)                                              \
    asm volatile("cp.async.cg.shared.global [%0], [%1], 16;"                    \
                 :: "r"(dst_u32), "l"(__cvta_generic_to_global(gptr)))
#define CP_COMMIT() asm volatile("cp.async.commit_group;" ::: "memory")
#define CP_WAIT1()  asm volatile("cp.async.wait_group 1;" ::: "memory")
#define CP_WAIT0()  asm volatile("cp.async.wait_group 0;" ::: "memory")

__device__ __forceinline__ uint32_t smem_u32(const void* p) {
    uint32_t a;
    asm("{ .reg .u64 t; cvta.to.shared.u64 t, %1; cvt.u32.u64 %0, t; }"
        : "=r"(a) : "l"(p));
    return a;
}

// mma.sync m16n8k32 s8: d += a * b  (exact s32 accumulate)
__device__ __forceinline__ void mma_s8(int* d,
                                       uint32_t a0, uint32_t a1, uint32_t a2, uint32_t a3,
                                       uint32_t b0, uint32_t b1) {
    asm volatile(
        "mma.sync.aligned.m16n8k32.row.col.s32.s8.s8.s32 "
        "{%0,%1,%2,%3}, {%4,%5,%6,%7}, {%8,%9}, {%0,%1,%2,%3};"
        : "+r"(d[0]), "+r"(d[1]), "+r"(d[2]), "+r"(d[3])
        : "r"(a0), "r"(a1), "r"(a2), "r"(a3), "r"(b0), "r"(b1));
}

__device__ __forceinline__ int dpos8(int p) {   // dest slot of source quad p
    return ((p & 3) << 1) | (p >> 2);
}

// quantize x*inv_s into 2 int8 words: A = rn(x*inv_s) = 128*a1 + a2
__device__ __forceinline__ void quant2(float x, float inv_s, int& a1, int& a2) {
    int A = __float2int_rn(x * inv_s);
    a1 = __float2int_rn((float)A * (1.0f / 128.0f));
    a2 = A - (a1 << 7);
}

__device__ __forceinline__ uint32_t packq(int a0, int a1, int a2, int a3) {
    return (uint32_t)(uint8_t)(int8_t)a0 | ((uint32_t)(uint8_t)(int8_t)a1 << 8) |
           ((uint32_t)(uint8_t)(int8_t)a2 << 16) | ((uint32_t)(uint8_t)(int8_t)a3 << 24);
}

// ---------------------------------------------------------------------------
// prep kernels
// ---------------------------------------------------------------------------
__global__ void zero_gi()
{
    if (threadIdx.x < 3) g_gi[threadIdx.x] = 0;
}

__global__ __launch_bounds__(256)
void prep_xi(const float* __restrict__ X)
{
    __shared__ float red[8];
    __shared__ float s_sh;
    const int row = blockIdx.x;
    const int t   = threadIdx.x;
    float4 v = *(const float4*)(X + (size_t)row * DD + t * 4);
    float mx = fmaxf(fmaxf(fabsf(v.x), fabsf(v.y)), fmaxf(fabsf(v.z), fabsf(v.w)));
#pragma unroll
    for (int o = 16; o > 0; o >>= 1)
        mx = fmaxf(mx, __shfl_xor_sync(0xffffffffu, mx, o));
    if ((t & 31) == 0) red[t >> 5] = mx;
    __syncthreads();
    if (t == 0) {
        float m = red[0];
#pragma unroll
        for (int i = 1; i < 8; ++i) m = fmaxf(m, red[i]);
        s_sh = fmaxf(m, 1e-20f);
        g_sx[row] = s_sh;
    }
    __syncthreads();
    const float inv_s = 16256.0f / s_sh;

    int a1[4], a2[4];
    quant2(v.x, inv_s, a1[0], a2[0]);
    quant2(v.y, inv_s, a1[1], a2[1]);
    quant2(v.z, inv_s, a1[2], a2[2]);
    quant2(v.w, inv_s, a1[3], a2[3]);
    int widx = row * 256 + (t & ~7) + dpos8(t & 7);
    ((uint32_t*)g_xa)[widx] = packq(a1[0], a1[1], a1[2], a1[3]);
    ((uint32_t*)g_xb)[widx] = packq(a2[0], a2[1], a2[2], a2[3]);
}

__global__ __launch_bounds__(256)
void w_absmax(const float* __restrict__ W)
{
    int n = blockIdx.x * 256 + threadIdx.x;
    float m = 0.0f;
    for (int k = 0; k < DD; ++k)
        m = fmaxf(m, fabsf(W[(size_t)k * D3 + n]));
    g_sw[n] = fmaxf(m, 1e-20f);
}

__device__ __forceinline__ int kpermq(int k) {   // k in 0..31
    return ((dpos8((k >> 2) & 7)) << 2) | (k & 3);
}

__global__ __launch_bounds__(256)
void prep_wq(const float* __restrict__ W)
{
    __shared__ float t[32][33];
    const int n0 = blockIdx.x * 32;
    const int k0 = blockIdx.y * 32;
    const int tx = threadIdx.x, ty = threadIdx.y;   // (32, 8)
#pragma unroll
    for (int rr = 0; rr < 32; rr += 8)
        t[ty + rr][tx] = W[(size_t)(k0 + ty + rr) * D3 + n0 + tx];
    __syncthreads();
#pragma unroll
    for (int rr = 0; rr < 32; rr += 8) {
        int n = n0 + ty + rr;
        float inv_s = 16256.0f / g_sw[n];
        float v = t[tx][ty + rr];
        int b1, b2;
        quant2(v, inv_s, b1, b2);
        size_t base = (size_t)n * DD + k0 + kpermq(tx);
        g_wa[base] = (int8_t)b1;
        g_wb[base] = (int8_t)b2;
    }
}

// ---------------------------------------------------------------------------
// int8x3 QKV GEMM via mma.sync m16n8k32 (R13 256-thread config, proven 227us)
// + fused Q/K/V absmax in the epilogue.
// ---------------------------------------------------------------------------
#define ROWW 20
#define OA1 0
#define OA2 2560
#define OB1 5120
#define OB2 7680
#define ST_B32 10240
#define GEMM_SMEM_TOTAL (2 * ST_B32 * 4)

__device__ __forceinline__ void gemm_load(int kt, uint32_t st_u32,
                                          int m0, int n0, int tid)
{
    const int k0 = kt * 64;
#pragma unroll
    for (int it = 0; it < 2; ++it) {
        int j   = it * 256 + tid;
        int row = j >> 2;
        int ch  = (j & 3);
        uint32_t doff = (uint32_t)(row * ROWW + ch * 4) * 4;
        CP_ASYNC16(st_u32 + OA1 * 4 + doff, g_xa + (size_t)(m0 + row) * DD + k0 + ch * 16);
        CP_ASYNC16(st_u32 + OA2 * 4 + doff, g_xb + (size_t)(m0 + row) * DD + k0 + ch * 16);
        CP_ASYNC16(st_u32 + OB1 * 4 + doff, g_wa + (size_t)(n0 + row) * DD + k0 + ch * 16);
        CP_ASYNC16(st_u32 + OB2 * 4 + doff, g_wb + (size_t)(n0 + row) * DD + k0 + ch * 16);
    }
}

__global__ __launch_bounds__(256, 1)
void qkv_gemm_imma()
{
    extern __shared__ float sm[];
    const int tid   = threadIdx.x;
    const int wid   = tid >> 5;
    const int lane  = tid & 31;
    const int warpm = wid & 3;
    const int warpn = wid >> 2;
    const int c     = lane & 3;
    const int g     = lane >> 2;
    const int n0    = blockIdx.x * 128;
    const int m0    = blockIdx.y * 128;

    const uint32_t* st[2] = {(const uint32_t*)sm, (const uint32_t*)sm + ST_B32};
    uint32_t stu[2] = {smem_u32(sm), smem_u32(sm + ST_B32)};

    int accH[2][8][4];
    int accM[2][8][4];
#pragma unroll
    for (int mt = 0; mt < 2; ++mt)
#pragma unroll
        for (int nt = 0; nt < 8; ++nt)
#pragma unroll
            for (int v = 0; v < 4; ++v) { accH[mt][nt][v] = 0; accM[mt][nt][v] = 0; }

    gemm_load(0, stu[0], m0, n0, tid); CP_COMMIT();
    gemm_load(1, stu[1], m0, n0, tid); CP_COMMIT();

    for (int kt = 0; kt < 16; ++kt) {
        const int buf = kt & 1;
        if (kt < 14) { CP_WAIT1(); } else { CP_WAIT0(); }
        __syncthreads();

        const uint32_t* S = st[buf];
#pragma unroll
        for (int ks = 0; ks < 2; ++ks) {
            const int kc = ks * 8 + 2 * c;
            uint2 a1f[2][2], a2f[2][2];
#pragma unroll
            for (int mt = 0; mt < 2; ++mt) {
                int rbase = warpm * 32 + mt * 16 + g;
                a1f[mt][0] = *(const uint2*)&S[OA1 + rbase * ROWW + kc];
                a1f[mt][1] = *(const uint2*)&S[OA1 + (rbase + 8) * ROWW + kc];
                a2f[mt][0] = *(const uint2*)&S[OA2 + rbase * ROWW + kc];
                a2f[mt][1] = *(const uint2*)&S[OA2 + (rbase + 8) * ROWW + kc];
            }
#pragma unroll
            for (int nt = 0; nt < 8; ++nt) {
                int nb = (warpn * 64 + nt * 8 + g) * ROWW + kc;
                uint2 b1 = *(const uint2*)&S[OB1 + nb];
                uint2 b2 = *(const uint2*)&S[OB2 + nb];
#pragma unroll
                for (int mt = 0; mt < 2; ++mt) {
                    mma_s8(accH[mt][nt], a1f[mt][0].x, a1f[mt][1].x,
                           a1f[mt][0].y, a1f[mt][1].y, b1.x, b1.y);
                    mma_s8(accM[mt][nt], a1f[mt][0].x, a1f[mt][1].x,
                           a1f[mt][0].y, a1f[mt][1].y, b2.x, b2.y);
                    mma_s8(accM[mt][nt], a2f[mt][0].x, a2f[mt][1].x,
                           a2f[mt][0].y, a2f[mt][1].y, b1.x, b1.y);
                }
            }
        }
        __syncthreads();
        if (kt + 2 < 16) {
            gemm_load(kt + 2, stu[buf], m0, n0, tid);
            CP_COMMIT();
        }
    }

    // epilogue: rescale, scatter into g_qkv, and track |max| for this part
    const float qs = 1.0f / (16256.0f * 16256.0f);
    const int part = n0 >> 10;
    float lmax = 0.0f;
#pragma unroll
    for (int mt = 0; mt < 2; ++mt) {
        int mg0 = m0 + warpm * 32 + mt * 16 + g;
        float sx0 = g_sx[mg0] * qs;
        float sx1 = g_sx[mg0 + 8] * qs;
#pragma unroll
        for (int nt = 0; nt < 8; ++nt) {
            int colg = n0 + warpn * 64 + nt * 8 + 2 * c;
            float sw0 = g_sw[colg];
            float sw1 = g_sw[colg + 1];
            float r0 = ((float)accH[mt][nt][0] * 16384.0f + (float)accM[mt][nt][0] * 128.0f) * sx0 * sw0;
            float r1 = ((float)accH[mt][nt][1] * 16384.0f + (float)accM[mt][nt][1] * 128.0f) * sx0 * sw1;
            float r2 = ((float)accH[mt][nt][2] * 16384.0f + (float)accM[mt][nt][2] * 128.0f) * sx1 * sw0;
            float r3 = ((float)accH[mt][nt][3] * 16384.0f + (float)accM[mt][nt][3] * 128.0f) * sx1 * sw1;
            lmax = fmaxf(lmax, fmaxf(fmaxf(fabsf(r0), fabsf(r1)),
                                     fmaxf(fabsf(r2), fabsf(r3))));
            int pc   = colg & 1023;
            int h    = pc >> 6;
            int dh   = pc & 63;
            int b    = mg0 >> 11;
            int seq  = mg0 & 2047;
            float* dst = g_qkv + ((size_t)((part * BB + b) * HH + h) * NN + seq) * DH + dh;
            *(float2*)dst = make_float2(r0, r1);
            *(float2*)(dst + (size_t)8 * DH) = make_float2(r2, r3);
        }
    }
    // block absmax -> g_gi[part]
#pragma unroll
    for (int o = 16; o > 0; o >>= 1)
        lmax = fmaxf(lmax, __shfl_xor_sync(0xffffffffu, lmax, o));
    __syncthreads();
    if (lane == 0) sm[wid] = lmax;
    __syncthreads();
    if (tid == 0) {
        float m = sm[0];
#pragma unroll
        for (int i = 1; i < 8; ++i) m = fmaxf(m, sm[i]);
        atomicMax(&g_gi[part], __float_as_int(m));
    }
}

// ---------------------------------------------------------------------------
// Attention prep: int8 2-word quantize Q/K (quad-permuted), int8 V transposed
// ---------------------------------------------------------------------------
__global__ __launch_bounds__(256)
void prep_attn_qki8()
{
    int cidx = blockIdx.x * 256 + threadIdx.x;       // 0..524287
    int row  = cidx >> 2;                            // Q rows then K rows
    int ch   = cidx & 3;
    int part = row >> 16;                            // 0 = Q, 1 = K
    float gs = __int_as_float(g_gi[part]);
    float inv_s = 16256.0f / fmaxf(gs, 1e-20f);
    const float* src = g_qkv + (size_t)row * 64 + ch * 16;
    float s[16];
    *(float4*)(s)      = ((const float4*)src)[0];
    *(float4*)(s + 4)  = ((const float4*)src)[1];
    *(float4*)(s + 8)  = ((const float4*)src)[2];
    *(float4*)(s + 12) = ((const float4*)src)[3];
    uint32_t* da = (part ? (uint32_t*)g_ka : (uint32_t*)g_qa);
    uint32_t* db = (part ? (uint32_t*)g_kb : (uint32_t*)g_qb);
    int rbase = (row & 65535) * 16 + (ch >> 1) * 8 + (ch & 1);
#pragma unroll
    for (int i = 0; i < 4; ++i) {
        int a1[4], a2[4];
        quant2(s[4 * i + 0], inv_s, a1[0], a2[0]);
        quant2(s[4 * i + 1], inv_s, a1[1], a2[1]);
        quant2(s[4 * i + 2], inv_s, a1[2], a2[2]);
        quant2(s[4 * i + 3], inv_s, a1[3], a2[3]);
        int dst = rbase + 2 * i;
        da[dst] = packq(a1[0], a1[1], a1[2], a1[3]);
        db[dst] = packq(a2[0], a2[1], a2[2], a2[3]);
    }
}

__global__ __launch_bounds__(256)
void prep_attn_vi8()
{
    __shared__ float t[64][65];
    const int n0 = blockIdx.x * 64;
    const int h  = blockIdx.y;
    const int b  = blockIdx.z;
    const int bh = b * HH + h;
    const int tid = threadIdx.x;
    const float* Vg = g_qkv + (size_t)((2 * BB + b) * HH + h) * NN * DH;
#pragma unroll
    for (int i = 0; i < 16; ++i) {
        int lin = i * 256 + tid;
        int r = lin >> 6, d = lin & 63;
        t[r][d] = Vg[(size_t)(n0 + r) * 64 + d];
    }
    __syncthreads();
    const float gv = __int_as_float(g_gi[2]);
    const float inv_s = 16256.0f / fmaxf(gv, 1e-20f);
    const int d  = tid >> 2;
    const int qq = tid & 3;
    uint32_t* va = (uint32_t*)g_va + ((size_t)bh * 64 + d) * 512;
    uint32_t* vb = (uint32_t*)g_vb + ((size_t)bh * 64 + d) * 512;
#pragma unroll
    for (int i = 0; i < 4; ++i) {
        int ql = qq * 4 + i;              // local quad (keys 4ql..4ql+3)
        int a1[4], a2[4];
#pragma unroll
        for (int j = 0; j < 4; ++j)
            quant2(t[4 * ql + j][d], inv_s, a1[j], a2[j]);
        int qg  = (n0 >> 2) + ql;
        int dst = (qg & ~7) + dpos8(qg & 7);
        va[dst] = packq(a1[0], a1[1], a1[2], a1[3]);
        vb[dst] = packq(a2[0], a2[1], a2[2], a2[3]);
    }
}

// ---------------------------------------------------------------------------
// Causal flash attention: int8x3 QK^T + int8x3 PV (all m16n8k32).
// CTA = 256 thr (8 warps), q-tile 128; smem 76KB -> 2 CTAs/SM.
// ---------------------------------------------------------------------------
#define ROWKI 20                // b32 per K int8 smem row
#define ROWVI 36                // b32 per V int8 smem row (32 data + 4 pad)
#define KSTGI (128 * ROWKI)     // 2560 b32
#define VSTGI (64 * ROWVI)      // 2304 b32
#define ATT_SMEM_B32 (4 * KSTGI + 4 * VSTGI)
#define ATT_SMEM_BYTES (ATT_SMEM_B32 * 4)

__device__ __forceinline__ void attn_load_kv(
    int kt, int s, int tid, uint32_t sbase,
    const int8_t* kag, const int8_t* kbg,
    const uint32_t* vag, const uint32_t* vbg)
{
    const uint32_t oka = (s ? KSTGI : 0) * 4;
    const uint32_t okb = (2 * KSTGI + (s ? KSTGI : 0)) * 4;
    const uint32_t ova = (4 * KSTGI + (s ? VSTGI : 0)) * 4;
    const uint32_t ovb = (4 * KSTGI + 2 * VSTGI + (s ? VSTGI : 0)) * 4;
#pragma unroll
    for (int it = 0; it < 2; ++it) {
        int idx = it * 256 + tid;
        int row = idx >> 2, ch = idx & 3;
        uint32_t doff = (uint32_t)(row * ROWKI + ch * 4) * 4;
        size_t so = (size_t)(kt * 128 + row) * 64 + ch * 16;
        CP_ASYNC16(sbase + oka + doff, kag + so);
        CP_ASYNC16(sbase + okb + doff, kbg + so);
    }
#pragma unroll
    for (int it = 0; it < 2; ++it) {
        int idx = it * 256 + tid;
        int row = idx >> 3, ch = idx & 7;
        uint32_t doff = (uint32_t)(row * ROWVI + ch * 4) * 4;
        size_t so = (size_t)row * 512 + kt * 32 + ch * 4;   // b32 units
        CP_ASYNC16(sbase + ova + doff, vag + so);
        CP_ASYNC16(sbase + ovb + doff, vbg + so);
    }
}

__global__ __launch_bounds__(256, 2)
void attn_mma(float* __restrict__ out)
{
    extern __shared__ float smf[];
    uint32_t* su = (uint32_t*)smf;
    const uint32_t sbase = smem_u32(smf);
    const int tid  = threadIdx.x;
    const int w    = tid >> 5;
    const int lane = tid & 31;
    const int g    = lane >> 2;
    const int c    = lane & 3;
    const int qb   = (int)gridDim.x - 1 - blockIdx.x;   // heavy tiles first
    const int h    = blockIdx.y;
    const int b    = blockIdx.z;
    const int bh   = b * HH + h;

    const int8_t* kag = g_ka + (size_t)bh * NN * DH;
    const int8_t* kbg = g_kb + (size_t)bh * NN * DH;
    const uint32_t* vag = (const uint32_t*)g_va + (size_t)bh * 64 * 512;
    const uint32_t* vbg = (const uint32_t*)g_vb + (size_t)bh * 64 * 512;

    const float fs = __int_as_float(g_gi[0]) * __int_as_float(g_gi[1]) *
                     (1.0f / (16256.0f * 16256.0f)) * 0.125f;
    const float pvs = __int_as_float(g_gi[2]) / (16256.0f * 16256.0f);

    // Q int8 fragments, register-resident
    uint2 qfa[2][2], qfb[2][2];
    {
        const uint32_t* qa32 = (const uint32_t*)g_qa;
        const uint32_t* qb32 = (const uint32_t*)g_qb;
        size_t r0 = (size_t)bh * NN + qb * 128 + w * 16 + g;
#pragma unroll
        for (int kd = 0; kd < 2; ++kd) {
            qfa[kd][0] = *(const uint2*)&qa32[r0 * 16 + kd * 8 + 2 * c];
            qfa[kd][1] = *(const uint2*)&qa32[(r0 + 8) * 16 + kd * 8 + 2 * c];
            qfb[kd][0] = *(const uint2*)&qb32[r0 * 16 + kd * 8 + 2 * c];
            qfb[kd][1] = *(const uint2*)&qb32[(r0 + 8) * 16 + kd * 8 + 2 * c];
        }
    }

    float oa[8][4];
#pragma unroll
    for (int nt = 0; nt < 8; ++nt)
#pragma unroll
        for (int v = 0; v < 4; ++v) oa[nt][v] = 0.0f;
    float m0 = -1e30f, m1 = -1e30f, l0 = 0.0f, l1 = 0.0f;

    const int srcA = (lane & ~3) | ((2 * c) & 3);
    const int srcB = (lane & ~3) | ((2 * c + 1) & 3);
    const bool selhi = (c >> 1);

    attn_load_kv(0, 0, tid, sbase, kag, kbg, vag, vbg);
    CP_COMMIT();
    if (qb >= 1) attn_load_kv(1, 1, tid, sbase, kag, kbg, vag, vbg);
    CP_COMMIT();

    for (int kt = 0; kt <= qb; ++kt) {
        if (kt < qb) { CP_WAIT1(); } else { CP_WAIT0(); }
        __syncthreads();
        const int s = kt & 1;
        const uint32_t* KA = su + (s ? KSTGI : 0);
        const uint32_t* KB = su + 2 * KSTGI + (s ? KSTGI : 0);
        const uint32_t* VA = su + 4 * KSTGI + (s ? VSTGI : 0);
        const uint32_t* VB = su + 4 * KSTGI + 2 * VSTGI + (s ? VSTGI : 0);

        // S = Q @ K^T via int8x3 (two 8-nt halves)
        float sa[16][4];
#pragma unroll
        for (int hf = 0; hf < 2; ++hf) {
            int accH[8][4], accM[8][4];
#pragma unroll
            for (int nt = 0; nt < 8; ++nt)
#pragma unroll
                for (int v = 0; v < 4; ++v) { accH[nt][v] = 0; accM[nt][v] = 0; }
#pragma unroll
            for (int kd = 0; kd < 2; ++kd) {
#pragma unroll
                for (int nt = 0; nt < 8; ++nt) {
                    int ntg = hf * 8 + nt;
                    int a = (8 * ntg + g) * ROWKI + kd * 8 + 2 * c;
                    uint2 b1 = *(const uint2*)&KA[a];
                    uint2 b2 = *(const uint2*)&KB[a];
                    mma_s8(accH[nt], qfa[kd][0].x, qfa[kd][1].x,
                           qfa[kd][0].y, qfa[kd][1].y, b1.x, b1.y);
                    mma_s8(accM[nt], qfa[kd][0].x, qfa[kd][1].x,
                           qfa[kd][0].y, qfa[kd][1].y, b2.x, b2.y);
                    mma_s8(accM[nt], qfb[kd][0].x, qfb[kd][1].x,
                           qfb[kd][0].y, qfb[kd][1].y, b1.x, b1.y);
                }
            }
#pragma unroll
            for (int nt = 0; nt < 8; ++nt) {
                int ntg = hf * 8 + nt;
#pragma unroll
                for (int v = 0; v < 4; ++v)
                    sa[ntg][v] = ((float)accH[nt][v] * 16384.0f +
                                  (float)accM[nt][v] * 128.0f) * fs;
            }
        }

        // causal mask on the diagonal tile
        if (kt == qb) {
            int r0 = 16 * w + g, r1 = r0 + 8;
#pragma unroll
            for (int nt = 0; nt < 16; ++nt) {
                int c0 = 8 * nt + 2 * c, c1 = c0 + 1;
                if (c0 > r0) sa[nt][0] = -1e30f;
                if (c1 > r0) sa[nt][1] = -1e30f;
                if (c0 > r1) sa[nt][2] = -1e30f;
                if (c1 > r1) sa[nt][3] = -1e30f;
            }
        }

        // warp-local online softmax with fused P quantization
        float mx0 = -1e30f, mx1 = -1e30f;
#pragma unroll
        for (int nt = 0; nt < 16; ++nt) {
            mx0 = fmaxf(mx0, fmaxf(sa[nt][0], sa[nt][1]));
            mx1 = fmaxf(mx1, fmaxf(sa[nt][2], sa[nt][3]));
        }
        mx0 = fmaxf(mx0, __shfl_xor_sync(0xffffffffu, mx0, 1));
        mx0 = fmaxf(mx0, __shfl_xor_sync(0xffffffffu, mx0, 2));
        mx1 = fmaxf(mx1, __shfl_xor_sync(0xffffffffu, mx1, 1));
        mx1 = fmaxf(mx1, __shfl_xor_sync(0xffffffffu, mx1, 2));
        float mn0 = fmaxf(m0, mx0), mn1 = fmaxf(m1, mx1);
        float cr0 = __expf(m0 - mn0), cr1 = __expf(m1 - mn1);
        m0 = mn0; m1 = mn1;
        float rs0 = 0.0f, rs1 = 0.0f;
        // vq[rh][nt]: bytes (a1_even, a2_even, a1_odd, a2_odd)
        uint32_t vq[2][16];
#pragma unroll
        for (int nt = 0; nt < 16; ++nt) {
            float e0 = __expf(sa[nt][0] - mn0); rs0 += e0;
            float e1 = __expf(sa[nt][1] - mn0); rs0 += e1;
            float e2 = __expf(sa[nt][2] - mn1); rs1 += e2;
            float e3 = __expf(sa[nt][3] - mn1); rs1 += e3;
            int p1, p2, q1, q2;
            quant2(e0, 16256.0f, p1, p2);
            quant2(e1, 16256.0f, q1, q2);
            vq[0][nt] = packq(p1, p2, q1, q2);
            quant2(e2, 16256.0f, p1, p2);
            quant2(e3, 16256.0f, q1, q2);
            vq[1][nt] = packq(p1, p2, q1, q2);
        }
        rs0 += __shfl_xor_sync(0xffffffffu, rs0, 1);
        rs0 += __shfl_xor_sync(0xffffffffu, rs0, 2);
        rs1 += __shfl_xor_sync(0xffffffffu, rs1, 1);
        rs1 += __shfl_xor_sync(0xffffffffu, rs1, 2);
        l0 = l0 * cr0 + rs0;
        l1 = l1 * cr1 + rs1;
#pragma unroll
        for (int nt = 0; nt < 8; ++nt) {
            oa[nt][0] *= cr0; oa[nt][1] *= cr0;
            oa[nt][2] *= cr1; oa[nt][3] *= cr1;
        }

        // build P fragments for m16n8k32 (keys quad 4c.., 16+4c..)
        uint32_t pf1[4][4], pf2[4][4];
#pragma unroll
        for (int kb = 0; kb < 4; ++kb) {
#pragma unroll
            for (int rh = 0; rh < 2; ++rh) {
                uint32_t rA0 = __shfl_sync(0xffffffffu, vq[rh][4 * kb + 0], srcA);
                uint32_t rA1 = __shfl_sync(0xffffffffu, vq[rh][4 * kb + 1], srcA);
                uint32_t rB0 = __shfl_sync(0xffffffffu, vq[rh][4 * kb + 0], srcB);
                uint32_t rB1 = __shfl_sync(0xffffffffu, vq[rh][4 * kb + 1], srcB);
                uint32_t rA = selhi ? rA1 : rA0;
                uint32_t rB = selhi ? rB1 : rB0;
                pf1[kb][rh]     = __byte_perm(rA, rB, 0x6420);
                pf2[kb][rh]     = __byte_perm(rA, rB, 0x7531);
                uint32_t rA2 = __shfl_sync(0xffffffffu, vq[rh][4 * kb + 2], srcA);
                uint32_t rA3 = __shfl_sync(0xffffffffu, vq[rh][4 * kb + 3], srcA);
                uint32_t rB2 = __shfl_sync(0xffffffffu, vq[rh][4 * kb + 2], srcB);
                uint32_t rB3 = __shfl_sync(0xffffffffu, vq[rh][4 * kb + 3], srcB);
                uint32_t rAh = selhi ? rA3 : rA2;
                uint32_t rBh = selhi ? rB3 : rB2;
                pf1[kb][2 + rh] = __byte_perm(rAh, rBh, 0x6420);
                pf2[kb][2 + rh] = __byte_perm(rAh, rBh, 0x7531);
            }
        }

        // O += P @ V via int8x3, two 4-nt halves
#pragma unroll
        for (int hf = 0; hf < 2; ++hf) {
            int aH[4][4], aM[4][4];
#pragma unroll
            for (int ntl = 0; ntl < 4; ++ntl)
#pragma unroll
                for (int v = 0; v < 4; ++v) { aH[ntl][v] = 0; aM[ntl][v] = 0; }
#pragma unroll
            for (int kb = 0; kb < 4; ++kb) {
#pragma unroll
                for (int ntl = 0; ntl < 4; ++ntl) {
                    int nt = hf * 4 + ntl;
                    int a = (8 * nt + g) * ROWVI + kb * 8 + 2 * c;
                    uint2 b1 = *(const uint2*)&VA[a];
                    uint2 b2 = *(const uint2*)&VB[a];
                    mma_s8(aH[ntl], pf1[kb][0], pf1[kb][1],
                           pf1[kb][2], pf1[kb][3], b1.x, b1.y);
                    mma_s8(aM[ntl], pf1[kb][0], pf1[kb][1],
                           pf1[kb][2], pf1[kb][3], b2.x, b2.y);
                    mma_s8(aM[ntl], pf2[kb][0], pf2[kb][1],
                           pf2[kb][2], pf2[kb][3], b1.x, b1.y);
                }
            }
#pragma unroll
            for (int ntl = 0; ntl < 4; ++ntl) {
                int nt = hf * 4 + ntl;
#pragma unroll
                for (int v = 0; v < 4; ++v)
                    oa[nt][v] += ((float)aH[ntl][v] * 16384.0f +
                                  (float)aM[ntl][v] * 128.0f) * pvs;
            }
        }

        __syncthreads();
        if (kt + 2 <= qb) {
            attn_load_kv(kt + 2, s, tid, sbase, kag, kbg, vag, vbg);
            CP_COMMIT();
        }
    }

    // epilogue: out[b][n][h*64 + d]
    float i0 = 1.0f / l0, i1 = 1.0f / l1;
    int r0 = qb * 128 + 16 * w + g;
    float* o0 = out + ((size_t)b * NN + r0) * DD + h * 64;
    float* o1 = o0 + (size_t)8 * DD;
#pragma unroll
    for (int nt = 0; nt < 8; ++nt) {
        *(float2*)&o0[8 * nt + 2 * c] = make_float2(oa[nt][0] * i0, oa[nt][1] * i0);
        *(float2*)&o1[8 * nt + 2 * c] = make_float2(oa[nt][2] * i1, oa[nt][3] * i1);
    }
}

// ---------------------------------------------------------------------------
extern "C" void kernel_launch(void* const* d_in, const int* in_sizes, int n_in,
                              void* d_out, int out_size)
{
    const float* x = (const float*)d_in[0];   // [2,2048,1024] fp32
    const float* w = (const float*)d_in[1];   // [1024,3072] fp32
    float* out = (float*)d_out;               // [2,2048,1024] fp32
    (void)in_sizes; (void)n_in; (void)out_size;

    zero_gi<<<1, 32>>>();

    // int8 GEMM operand prep
    prep_xi<<<MM, 256>>>(x);
    w_absmax<<<D3 / 256, 256>>>(w);
    prep_wq<<<dim3(D3 / 32, DD / 32), dim3(32, 8)>>>(w);

    // int8x3 IMMA QKV GEMM (R13 config) with fused Q/K/V absmax
    cudaFuncSetAttribute(qkv_gemm_imma,
                         cudaFuncAttributeMaxDynamicSharedMemorySize,
                         GEMM_SMEM_TOTAL);
    qkv_gemm_imma<<<dim3(D3 / 128, MM / 128), 256, GEMM_SMEM_TOTAL>>>();

    // attention operand prep: int8 Q/K, int8 V transpose
    prep_attn_qki8<<<2048, 256>>>();
    prep_attn_vi8<<<dim3(NN / 64, HH, BB), 256>>>();

    // int8 QK^T + int8 PV flash attention (2 CTAs/SM)
    cudaFuncSetAttribute(attn_mma,
                         cudaFuncAttributeMaxDynamicSharedMemorySize,
                         ATT_SMEM_BYTES);
    attn_mma<<<dim3(NN / 128, HH, BB), 256, ATT_SMEM_BYTES>>>(out);
}

// round 16
// speedup vs baseline: 1.4465x; 1.0722x over previous
#include <cuda_runtime.h>
#include <cuda_bf16.h>
#include <cstdint>

// Problem constants
#define BB 2
#define NN 2048
#define HH 16
#define DH 64
#define DD 1024          // HH*DH
#define D3 3072          // 3*DD
#define MM 4096          // BB*NN
#define BHND ((size_t)BB * HH * NN * DH)

// Scratch: QKV laid out [part(q/k/v)][B][H][N][Dh], fp32
__device__ float g_qkv[3u * BB * HH * NN * DH];
// int8 GEMM operands
__device__ float  g_sx[MM];
__device__ float  g_sw[D3];
__device__ int8_t g_xa[(size_t)MM * DD];
__device__ int8_t g_xb[(size_t)MM * DD];
__device__ int8_t g_wa[(size_t)D3 * DD];
__device__ int8_t g_wb[(size_t)D3 * DD];
// global absmax of Q/K/V (float bits), computed in GEMM epilogue
__device__ int    g_gi[3];
// int8 attention operands (2-word, quad-permuted)
__device__ int8_t g_qa[BHND];                // [bh][n][d]
__device__ int8_t g_qb[BHND];
__device__ int8_t g_ka[BHND];
__device__ int8_t g_kb[BHND];
__device__ int8_t g_va[BHND];                // [bh][d][n] transposed
__device__ int8_t g_vb[BHND];

// ---------------------------------------------------------------------------
// helpers
// ---------------------------------------------------------------------------
#define CP_ASYNC16(dst_u32, gptr)                                              \
    asm volatile("cp.async.cg.shared.global [%0], [%1], 16;"                    \
                 :: "r"(dst_u32), "l"(__cvta_generic_to_global(gptr)))
#define CP_COMMIT() asm volatile("cp.async.commit_group;" ::: "memory")
#define CP_WAIT1()  asm volatile("cp.async.wait_group 1;" ::: "memory")
#define CP_WAIT0()  asm volatile("cp.async.wait_group 0;" ::: "memory")

__device__ __forceinline__ uint32_t smem_u32(const void* p) {
    uint32_t a;
    asm("{ .reg .u64 t; cvta.to.shared.u64 t, %1; cvt.u32.u64 %0, t; }"
        : "=r"(a) : "l"(p));
    return a;
}

// mma.sync m16n8k32 s8: d += a * b  (exact s32 accumulate)
__device__ __forceinline__ void mma_s8(int* d,
                                       uint32_t a0, uint32_t a1, uint32_t a2, uint32_t a3,
                                       uint32_t b0, uint32_t b1) {
    asm volatile(
        "mma.sync.aligned.m16n8k32.row.col.s32.s8.s8.s32 "
        "{%0,%1,%2,%3}, {%4,%5,%6,%7}, {%8,%9}, {%0,%1,%2,%3};"
        : "+r"(d[0]), "+r"(d[1]), "+r"(d[2]), "+r"(d[3])
        : "r"(a0), "r"(a1), "r"(a2), "r"(a3), "r"(b0), "r"(b1));
}

__device__ __forceinline__ int dpos8(int p) {   // dest slot of source quad p
    return ((p & 3) << 1) | (p >> 2);
}

// quantize x*inv_s into 2 int8 words: A = rn(x*inv_s) = 128*a1 + a2
__device__ __forceinline__ void quant2(float x, float inv_s, int& a1, int& a2) {
    int A = __float2int_rn(x * inv_s);
    a1 = __float2int_rn((float)A * (1.0f / 128.0f));
    a2 = A - (a1 << 7);
}

__device__ __forceinline__ uint32_t packq(int a0, int a1, int a2, int a3) {
    return (uint32_t)(uint8_t)(int8_t)a0 | ((uint32_t)(uint8_t)(int8_t)a1 << 8) |
           ((uint32_t)(uint8_t)(int8_t)a2 << 16) | ((uint32_t)(uint8_t)(int8_t)a3 << 24);
}

// ---------------------------------------------------------------------------
// prep kernels
// ---------------------------------------------------------------------------
__global__ __launch_bounds__(256)
void prep_xi(const float* __restrict__ X)
{
    __shared__ float red[8];
    __shared__ float s_sh;
    const int row = blockIdx.x;
    const int t   = threadIdx.x;
    if (row == 0 && t < 3) g_gi[t] = 0;   // reset global absmax (pre-GEMM)
    float4 v = *(const float4*)(X + (size_t)row * DD + t * 4);
    float mx = fmaxf(fmaxf(fabsf(v.x), fabsf(v.y)), fmaxf(fabsf(v.z), fabsf(v.w)));
#pragma unroll
    for (int o = 16; o > 0; o >>= 1)
        mx = fmaxf(mx, __shfl_xor_sync(0xffffffffu, mx, o));
    if ((t & 31) == 0) red[t >> 5] = mx;
    __syncthreads();
    if (t == 0) {
        float m = red[0];
#pragma unroll
        for (int i = 1; i < 8; ++i) m = fmaxf(m, red[i]);
        s_sh = fmaxf(m, 1e-20f);
        g_sx[row] = s_sh;
    }
    __syncthreads();
    const float inv_s = 16256.0f / s_sh;

    int a1[4], a2[4];
    quant2(v.x, inv_s, a1[0], a2[0]);
    quant2(v.y, inv_s, a1[1], a2[1]);
    quant2(v.z, inv_s, a1[2], a2[2]);
    quant2(v.w, inv_s, a1[3], a2[3]);
    int widx = row * 256 + (t & ~7) + dpos8(t & 7);
    ((uint32_t*)g_xa)[widx] = packq(a1[0], a1[1], a1[2], a1[3]);
    ((uint32_t*)g_xb)[widx] = packq(a2[0], a2[1], a2[2], a2[3]);
}

__global__ __launch_bounds__(256)
void w_absmax(const float* __restrict__ W)
{
    int n = blockIdx.x * 256 + threadIdx.x;
    float m = 0.0f;
    for (int k = 0; k < DD; ++k)
        m = fmaxf(m, fabsf(W[(size_t)k * D3 + n]));
    g_sw[n] = fmaxf(m, 1e-20f);
}

__device__ __forceinline__ int kpermq(int k) {   // k in 0..31
    return ((dpos8((k >> 2) & 7)) << 2) | (k & 3);
}

__global__ __launch_bounds__(256)
void prep_wq(const float* __restrict__ W)
{
    __shared__ float t[32][33];
    const int n0 = blockIdx.x * 32;
    const int k0 = blockIdx.y * 32;
    const int tx = threadIdx.x, ty = threadIdx.y;   // (32, 8)
#pragma unroll
    for (int rr = 0; rr < 32; rr += 8)
        t[ty + rr][tx] = W[(size_t)(k0 + ty + rr) * D3 + n0 + tx];
    __syncthreads();
#pragma unroll
    for (int rr = 0; rr < 32; rr += 8) {
        int n = n0 + ty + rr;
        float inv_s = 16256.0f / g_sw[n];
        float v = t[tx][ty + rr];
        int b1, b2;
        quant2(v, inv_s, b1, b2);
        size_t base = (size_t)n * DD + k0 + kpermq(tx);
        g_wa[base] = (int8_t)b1;
        g_wb[base] = (int8_t)b2;
    }
}

// ---------------------------------------------------------------------------
// int8x3 QKV GEMM via mma.sync m16n8k32 (R13 256-thread config, proven 227us)
// + fused Q/K/V absmax in the epilogue.
// ---------------------------------------------------------------------------
#define ROWW 20
#define OA1 0
#define OA2 2560
#define OB1 5120
#define OB2 7680
#define ST_B32 10240
#define GEMM_SMEM_TOTAL (2 * ST_B32 * 4)

__device__ __forceinline__ void gemm_load(int kt, uint32_t st_u32,
                                          int m0, int n0, int tid)
{
    const int k0 = kt * 64;
#pragma unroll
    for (int it = 0; it < 2; ++it) {
        int j   = it * 256 + tid;
        int row = j >> 2;
        int ch  = (j & 3);
        uint32_t doff = (uint32_t)(row * ROWW + ch * 4) * 4;
        CP_ASYNC16(st_u32 + OA1 * 4 + doff, g_xa + (size_t)(m0 + row) * DD + k0 + ch * 16);
        CP_ASYNC16(st_u32 + OA2 * 4 + doff, g_xb + (size_t)(m0 + row) * DD + k0 + ch * 16);
        CP_ASYNC16(st_u32 + OB1 * 4 + doff, g_wa + (size_t)(n0 + row) * DD + k0 + ch * 16);
        CP_ASYNC16(st_u32 + OB2 * 4 + doff, g_wb + (size_t)(n0 + row) * DD + k0 + ch * 16);
    }
}

__global__ __launch_bounds__(256, 1)
void qkv_gemm_imma()
{
    extern __shared__ float sm[];
    const int tid   = threadIdx.x;
    const int wid   = tid >> 5;
    const int lane  = tid & 31;
    const int warpm = wid & 3;
    const int warpn = wid >> 2;
    const int c     = lane & 3;
    const int g     = lane >> 2;
    const int n0    = blockIdx.x * 128;
    const int m0    = blockIdx.y * 128;

    const uint32_t* st[2] = {(const uint32_t*)sm, (const uint32_t*)sm + ST_B32};
    uint32_t stu[2] = {smem_u32(sm), smem_u32(sm + ST_B32)};

    int accH[2][8][4];
    int accM[2][8][4];
#pragma unroll
    for (int mt = 0; mt < 2; ++mt)
#pragma unroll
        for (int nt = 0; nt < 8; ++nt)
#pragma unroll
            for (int v = 0; v < 4; ++v) { accH[mt][nt][v] = 0; accM[mt][nt][v] = 0; }

    gemm_load(0, stu[0], m0, n0, tid); CP_COMMIT();
    gemm_load(1, stu[1], m0, n0, tid); CP_COMMIT();

    for (int kt = 0; kt < 16; ++kt) {
        const int buf = kt & 1;
        if (kt < 14) { CP_WAIT1(); } else { CP_WAIT0(); }
        __syncthreads();

        const uint32_t* S = st[buf];
#pragma unroll
        for (int ks = 0; ks < 2; ++ks) {
            const int kc = ks * 8 + 2 * c;
            uint2 a1f[2][2], a2f[2][2];
#pragma unroll
            for (int mt = 0; mt < 2; ++mt) {
                int rbase = warpm * 32 + mt * 16 + g;
                a1f[mt][0] = *(const uint2*)&S[OA1 + rbase * ROWW + kc];
                a1f[mt][1] = *(const uint2*)&S[OA1 + (rbase + 8) * ROWW + kc];
                a2f[mt][0] = *(const uint2*)&S[OA2 + rbase * ROWW + kc];
                a2f[mt][1] = *(const uint2*)&S[OA2 + (rbase + 8) * ROWW + kc];
            }
#pragma unroll
            for (int nt = 0; nt < 8; ++nt) {
                int nb = (warpn * 64 + nt * 8 + g) * ROWW + kc;
                uint2 b1 = *(const uint2*)&S[OB1 + nb];
                uint2 b2 = *(const uint2*)&S[OB2 + nb];
#pragma unroll
                for (int mt = 0; mt < 2; ++mt) {
                    mma_s8(accH[mt][nt], a1f[mt][0].x, a1f[mt][1].x,
                           a1f[mt][0].y, a1f[mt][1].y, b1.x, b1.y);
                    mma_s8(accM[mt][nt], a1f[mt][0].x, a1f[mt][1].x,
                           a1f[mt][0].y, a1f[mt][1].y, b2.x, b2.y);
                    mma_s8(accM[mt][nt], a2f[mt][0].x, a2f[mt][1].x,
                           a2f[mt][0].y, a2f[mt][1].y, b1.x, b1.y);
                }
            }
        }
        __syncthreads();
        if (kt + 2 < 16) {
            gemm_load(kt + 2, stu[buf], m0, n0, tid);
            CP_COMMIT();
        }
    }

    // epilogue: rescale, scatter into g_qkv, and track |max| for this part
    const float qs = 128.0f / (16256.0f * 16256.0f);   // pre-merged (<<7) scale
    const int part = n0 >> 10;
    float lmax = 0.0f;
#pragma unroll
    for (int mt = 0; mt < 2; ++mt) {
        int mg0 = m0 + warpm * 32 + mt * 16 + g;
        float sx0 = g_sx[mg0] * qs;
        float sx1 = g_sx[mg0 + 8] * qs;
#pragma unroll
        for (int nt = 0; nt < 8; ++nt) {
            int colg = n0 + warpn * 64 + nt * 8 + 2 * c;
            float sw0 = g_sw[colg];
            float sw1 = g_sw[colg + 1];
            float r0 = (float)((accH[mt][nt][0] << 7) + accM[mt][nt][0]) * sx0 * sw0;
            float r1 = (float)((accH[mt][nt][1] << 7) + accM[mt][nt][1]) * sx0 * sw1;
            float r2 = (float)((accH[mt][nt][2] << 7) + accM[mt][nt][2]) * sx1 * sw0;
            float r3 = (float)((accH[mt][nt][3] << 7) + accM[mt][nt][3]) * sx1 * sw1;
            lmax = fmaxf(lmax, fmaxf(fmaxf(fabsf(r0), fabsf(r1)),
                                     fmaxf(fabsf(r2), fabsf(r3))));
            int pc   = colg & 1023;
            int h    = pc >> 6;
            int dh   = pc & 63;
            int b    = mg0 >> 11;
            int seq  = mg0 & 2047;
            float* dst = g_qkv + ((size_t)((part * BB + b) * HH + h) * NN + seq) * DH + dh;
            *(float2*)dst = make_float2(r0, r1);
            *(float2*)(dst + (size_t)8 * DH) = make_float2(r2, r3);
        }
    }
    // block absmax -> g_gi[part]
#pragma unroll
    for (int o = 16; o > 0; o >>= 1)
        lmax = fmaxf(lmax, __shfl_xor_sync(0xffffffffu, lmax, o));
    __syncthreads();
    if (lane == 0) sm[wid] = lmax;
    __syncthreads();
    if (tid == 0) {
        float m = sm[0];
#pragma unroll
        for (int i = 1; i < 8; ++i) m = fmaxf(m, sm[i]);
        atomicMax(&g_gi[part], __float_as_int(m));
    }
}

// ---------------------------------------------------------------------------
// Attention prep: int8 2-word quantize Q/K (quad-permuted), int8 V transposed
// ---------------------------------------------------------------------------
__global__ __launch_bounds__(256)
void prep_attn_qki8()
{
    int cidx = blockIdx.x * 256 + threadIdx.x;       // 0..524287
    int row  = cidx >> 2;                            // Q rows then K rows
    int ch   = cidx & 3;
    int part = row >> 16;                            // 0 = Q, 1 = K
    float gs = __int_as_float(g_gi[part]);
    float inv_s = 16256.0f / fmaxf(gs, 1e-20f);
    const float* src = g_qkv + (size_t)row * 64 + ch * 16;
    float s[16];
    *(float4*)(s)      = ((const float4*)src)[0];
    *(float4*)(s + 4)  = ((const float4*)src)[1];
    *(float4*)(s + 8)  = ((const float4*)src)[2];
    *(float4*)(s + 12) = ((const float4*)src)[3];
    uint32_t* da = (part ? (uint32_t*)g_ka : (uint32_t*)g_qa);
    uint32_t* db = (part ? (uint32_t*)g_kb : (uint32_t*)g_qb);
    int rbase = (row & 65535) * 16 + (ch >> 1) * 8 + (ch & 1);
#pragma unroll
    for (int i = 0; i < 4; ++i) {
        int a1[4], a2[4];
        quant2(s[4 * i + 0], inv_s, a1[0], a2[0]);
        quant2(s[4 * i + 1], inv_s, a1[1], a2[1]);
        quant2(s[4 * i + 2], inv_s, a1[2], a2[2]);
        quant2(s[4 * i + 3], inv_s, a1[3], a2[3]);
        int dst = rbase + 2 * i;
        da[dst] = packq(a1[0], a1[1], a1[2], a1[3]);
        db[dst] = packq(a2[0], a2[1], a2[2], a2[3]);
    }
}

__global__ __launch_bounds__(256)
void prep_attn_vi8()
{
    __shared__ float t[64][65];
    const int n0 = blockIdx.x * 64;
    const int h  = blockIdx.y;
    const int b  = blockIdx.z;
    const int bh = b * HH + h;
    const int tid = threadIdx.x;
    const float* Vg = g_qkv + (size_t)((2 * BB + b) * HH + h) * NN * DH;
#pragma unroll
    for (int i = 0; i < 16; ++i) {
        int lin = i * 256 + tid;
        int r = lin >> 6, d = lin & 63;
        t[r][d] = Vg[(size_t)(n0 + r) * 64 + d];
    }
    __syncthreads();
    const float gv = __int_as_float(g_gi[2]);
    const float inv_s = 16256.0f / fmaxf(gv, 1e-20f);
    const int d  = tid >> 2;
    const int qq = tid & 3;
    uint32_t* va = (uint32_t*)g_va + ((size_t)bh * 64 + d) * 512;
    uint32_t* vb = (uint32_t*)g_vb + ((size_t)bh * 64 + d) * 512;
#pragma unroll
    for (int i = 0; i < 4; ++i) {
        int ql = qq * 4 + i;              // local quad (keys 4ql..4ql+3)
        int a1[4], a2[4];
#pragma unroll
        for (int j = 0; j < 4; ++j)
            quant2(t[4 * ql + j][d], inv_s, a1[j], a2[j]);
        int qg  = (n0 >> 2) + ql;
        int dst = (qg & ~7) + dpos8(qg & 7);
        va[dst] = packq(a1[0], a1[1], a1[2], a1[3]);
        vb[dst] = packq(a2[0], a2[1], a2[2], a2[3]);
    }
}

// ---------------------------------------------------------------------------
// Causal flash attention: int8x3 QK^T + int8x3 PV (all m16n8k32).
// CTA = 256 thr (8 warps), q-tile 128; smem 76KB -> 2 CTAs/SM.
// ---------------------------------------------------------------------------
#define ROWKI 20                // b32 per K int8 smem row
#define ROWVI 36                // b32 per V int8 smem row (32 data + 4 pad)
#define KSTGI (128 * ROWKI)     // 2560 b32
#define VSTGI (64 * ROWVI)      // 2304 b32
#define ATT_SMEM_B32 (4 * KSTGI + 4 * VSTGI)
#define ATT_SMEM_BYTES (ATT_SMEM_B32 * 4)

__device__ __forceinline__ void attn_load_kv(
    int kt, int s, int tid, uint32_t sbase,
    const int8_t* kag, const int8_t* kbg,
    const uint32_t* vag, const uint32_t* vbg)
{
    const uint32_t oka = (s ? KSTGI : 0) * 4;
    const uint32_t okb = (2 * KSTGI + (s ? KSTGI : 0)) * 4;
    const uint32_t ova = (4 * KSTGI + (s ? VSTGI : 0)) * 4;
    const uint32_t ovb = (4 * KSTGI + 2 * VSTGI + (s ? VSTGI : 0)) * 4;
#pragma unroll
    for (int it = 0; it < 2; ++it) {
        int idx = it * 256 + tid;
        int row = idx >> 2, ch = idx & 3;
        uint32_t doff = (uint32_t)(row * ROWKI + ch * 4) * 4;
        size_t so = (size_t)(kt * 128 + row) * 64 + ch * 16;
        CP_ASYNC16(sbase + oka + doff, kag + so);
        CP_ASYNC16(sbase + okb + doff, kbg + so);
    }
#pragma unroll
    for (int it = 0; it < 2; ++it) {
        int idx = it * 256 + tid;
        int row = idx >> 3, ch = idx & 7;
        uint32_t doff = (uint32_t)(row * ROWVI + ch * 4) * 4;
        size_t so = (size_t)row * 512 + kt * 32 + ch * 4;   // b32 units
        CP_ASYNC16(sbase + ova + doff, vag + so);
        CP_ASYNC16(sbase + ovb + doff, vbg + so);
    }
}

__global__ __launch_bounds__(256, 2)
void attn_mma(float* __restrict__ out)
{
    extern __shared__ float smf[];
    uint32_t* su = (uint32_t*)smf;
    const uint32_t sbase = smem_u32(smf);
    const int tid  = threadIdx.x;
    const int w    = tid >> 5;
    const int lane = tid & 31;
    const int g    = lane >> 2;
    const int c    = lane & 3;
    const int qb   = (int)gridDim.x - 1 - blockIdx.x;   // heavy tiles first
    const int h    = blockIdx.y;
    const int b    = blockIdx.z;
    const int bh   = b * HH + h;

    const int8_t* kag = g_ka + (size_t)bh * NN * DH;
    const int8_t* kbg = g_kb + (size_t)bh * NN * DH;
    const uint32_t* vag = (const uint32_t*)g_va + (size_t)bh * 64 * 512;
    const uint32_t* vbg = (const uint32_t*)g_vb + (size_t)bh * 64 * 512;

    // pre-merged (<<7) scales
    const float fs = __int_as_float(g_gi[0]) * __int_as_float(g_gi[1]) *
                     (128.0f / (16256.0f * 16256.0f)) * 0.125f;
    const float pvs = __int_as_float(g_gi[2]) * 128.0f / (16256.0f * 16256.0f);

    // Q int8 fragments, register-resident
    uint2 qfa[2][2], qfb[2][2];
    {
        const uint32_t* qa32 = (const uint32_t*)g_qa;
        const uint32_t* qb32 = (const uint32_t*)g_qb;
        size_t r0 = (size_t)bh * NN + qb * 128 + w * 16 + g;
#pragma unroll
        for (int kd = 0; kd < 2; ++kd) {
            qfa[kd][0] = *(const uint2*)&qa32[r0 * 16 + kd * 8 + 2 * c];
            qfa[kd][1] = *(const uint2*)&qa32[(r0 + 8) * 16 + kd * 8 + 2 * c];
            qfb[kd][0] = *(const uint2*)&qb32[r0 * 16 + kd * 8 + 2 * c];
            qfb[kd][1] = *(const uint2*)&qb32[(r0 + 8) * 16 + kd * 8 + 2 * c];
        }
    }

    float oa[8][4];
#pragma unroll
    for (int nt = 0; nt < 8; ++nt)
#pragma unroll
        for (int v = 0; v < 4; ++v) oa[nt][v] = 0.0f;
    float m0 = -1e30f, m1 = -1e30f, l0 = 0.0f, l1 = 0.0f;

    const int srcA = (lane & ~3) | ((2 * c) & 3);
    const int srcB = (lane & ~3) | ((2 * c + 1) & 3);
    const bool selhi = (c >> 1);

    attn_load_kv(0, 0, tid, sbase, kag, kbg, vag, vbg);
    CP_COMMIT();
    if (qb >= 1) attn_load_kv(1, 1, tid, sbase, kag, kbg, vag, vbg);
    CP_COMMIT();

    for (int kt = 0; kt <= qb; ++kt) {
        if (kt < qb) { CP_WAIT1(); } else { CP_WAIT0(); }
        __syncthreads();
        const int s = kt & 1;
        const uint32_t* KA = su + (s ? KSTGI : 0);
        const uint32_t* KB = su + 2 * KSTGI + (s ? KSTGI : 0);
        const uint32_t* VA = su + 4 * KSTGI + (s ? VSTGI : 0);
        const uint32_t* VB = su + 4 * KSTGI + 2 * VSTGI + (s ? VSTGI : 0);

        // S = Q @ K^T via int8x3 (two 8-nt halves), integer-merged rescale
        float sa[16][4];
#pragma unroll
        for (int hf = 0; hf < 2; ++hf) {
            int accH[8][4], accM[8][4];
#pragma unroll
            for (int nt = 0; nt < 8; ++nt)
#pragma unroll
                for (int v = 0; v < 4; ++v) { accH[nt][v] = 0; accM[nt][v] = 0; }
#pragma unroll
            for (int kd = 0; kd < 2; ++kd) {
#pragma unroll
                for (int nt = 0; nt < 8; ++nt) {
                    int ntg = hf * 8 + nt;
                    int a = (8 * ntg + g) * ROWKI + kd * 8 + 2 * c;
                    uint2 b1 = *(const uint2*)&KA[a];
                    uint2 b2 = *(const uint2*)&KB[a];
                    mma_s8(accH[nt], qfa[kd][0].x, qfa[kd][1].x,
                           qfa[kd][0].y, qfa[kd][1].y, b1.x, b1.y);
                    mma_s8(accM[nt], qfa[kd][0].x, qfa[kd][1].x,
                           qfa[kd][0].y, qfa[kd][1].y, b2.x, b2.y);
                    mma_s8(accM[nt], qfb[kd][0].x, qfb[kd][1].x,
                           qfb[kd][0].y, qfb[kd][1].y, b1.x, b1.y);
                }
            }
#pragma unroll
            for (int nt = 0; nt < 8; ++nt) {
                int ntg = hf * 8 + nt;
#pragma unroll
                for (int v = 0; v < 4; ++v)
                    sa[ntg][v] = (float)((accH[nt][v] << 7) + accM[nt][v]) * fs;
            }
        }

        // causal mask on the diagonal tile
        if (kt == qb) {
            int r0 = 16 * w + g, r1 = r0 + 8;
#pragma unroll
            for (int nt = 0; nt < 16; ++nt) {
                int c0 = 8 * nt + 2 * c, c1 = c0 + 1;
                if (c0 > r0) sa[nt][0] = -1e30f;
                if (c1 > r0) sa[nt][1] = -1e30f;
                if (c0 > r1) sa[nt][2] = -1e30f;
                if (c1 > r1) sa[nt][3] = -1e30f;
            }
        }

        // warp-local online softmax with fused fast P quantization
        float mx0 = -1e30f, mx1 = -1e30f;
#pragma unroll
        for (int nt = 0; nt < 16; ++nt) {
            mx0 = fmaxf(mx0, fmaxf(sa[nt][0], sa[nt][1]));
            mx1 = fmaxf(mx1, fmaxf(sa[nt][2], sa[nt][3]));
        }
        mx0 = fmaxf(mx0, __shfl_xor_sync(0xffffffffu, mx0, 1));
        mx0 = fmaxf(mx0, __shfl_xor_sync(0xffffffffu, mx0, 2));
        mx1 = fmaxf(mx1, __shfl_xor_sync(0xffffffffu, mx1, 1));
        mx1 = fmaxf(mx1, __shfl_xor_sync(0xffffffffu, mx1, 2));
        float mn0 = fmaxf(m0, mx0), mn1 = fmaxf(m1, mx1);
        float cr0 = __expf(m0 - mn0), cr1 = __expf(m1 - mn1);
        m0 = mn0; m1 = mn1;
        float rs0 = 0.0f, rs1 = 0.0f;
        // vq[rh][nt]: bytes (p1_even, p2_even, p1_odd, p2_odd); e>=0 so
        // A = rz(e*16256), p1 = A>>7, p2 = A&127 (exact split, both in [0,127])
        uint32_t vq[2][16];
#pragma unroll
        for (int nt = 0; nt < 16; ++nt) {
            float e0 = __expf(sa[nt][0] - mn0); rs0 += e0;
            float e1 = __expf(sa[nt][1] - mn0); rs0 += e1;
            float e2 = __expf(sa[nt][2] - mn1); rs1 += e2;
            float e3 = __expf(sa[nt][3] - mn1); rs1 += e3;
            int A0 = __float2int_rz(e0 * 16256.0f);
            int A1 = __float2int_rz(e1 * 16256.0f);
            int A2 = __float2int_rz(e2 * 16256.0f);
            int A3 = __float2int_rz(e3 * 16256.0f);
            vq[0][nt] = (uint32_t)(A0 >> 7) | ((uint32_t)(A0 & 127) << 8) |
                        ((uint32_t)(A1 >> 7) << 16) | ((uint32_t)(A1 & 127) << 24);
            vq[1][nt] = (uint32_t)(A2 >> 7) | ((uint32_t)(A2 & 127) << 8) |
                        ((uint32_t)(A3 >> 7) << 16) | ((uint32_t)(A3 & 127) << 24);
        }
        rs0 += __shfl_xor_sync(0xffffffffu, rs0, 1);
        rs0 += __shfl_xor_sync(0xffffffffu, rs0, 2);
        rs1 += __shfl_xor_sync(0xffffffffu, rs1, 1);
        rs1 += __shfl_xor_sync(0xffffffffu, rs1, 2);
        l0 = l0 * cr0 + rs0;
        l1 = l1 * cr1 + rs1;
#pragma unroll
        for (int nt = 0; nt < 8; ++nt) {
            oa[nt][0] *= cr0; oa[nt][1] *= cr0;
            oa[nt][2] *= cr1; oa[nt][3] *= cr1;
        }

        // build P fragments for m16n8k32 (keys quad 4c.., 16+4c..)
        uint32_t pf1[4][4], pf2[4][4];
#pragma unroll
        for (int kb = 0; kb < 4; ++kb) {
#pragma unroll
            for (int rh = 0; rh < 2; ++rh) {
                uint32_t rA0 = __shfl_sync(0xffffffffu, vq[rh][4 * kb + 0], srcA);
                uint32_t rA1 = __shfl_sync(0xffffffffu, vq[rh][4 * kb + 1], srcA);
                uint32_t rB0 = __shfl_sync(0xffffffffu, vq[rh][4 * kb + 0], srcB);
                uint32_t rB1 = __shfl_sync(0xffffffffu, vq[rh][4 * kb + 1], srcB);
                uint32_t rA = selhi ? rA1 : rA0;
                uint32_t rB = selhi ? rB1 : rB0;
                pf1[kb][rh]     = __byte_perm(rA, rB, 0x6420);
                pf2[kb][rh]     = __byte_perm(rA, rB, 0x7531);
                uint32_t rA2 = __shfl_sync(0xffffffffu, vq[rh][4 * kb + 2], srcA);
                uint32_t rA3 = __shfl_sync(0xffffffffu, vq[rh][4 * kb + 3], srcA);
                uint32_t rB2 = __shfl_sync(0xffffffffu, vq[rh][4 * kb + 2], srcB);
                uint32_t rB3 = __shfl_sync(0xffffffffu, vq[rh][4 * kb + 3], srcB);
                uint32_t rAh = selhi ? rA3 : rA2;
                uint32_t rBh = selhi ? rB3 : rB2;
                pf1[kb][2 + rh] = __byte_perm(rAh, rBh, 0x6420);
                pf2[kb][2 + rh] = __byte_perm(rAh, rBh, 0x7531);
            }
        }

        // O += P @ V via int8x3, two 4-nt halves, integer-merged rescale
#pragma unroll
        for (int hf = 0; hf < 2; ++hf) {
            int aH[4][4], aM[4][4];
#pragma unroll
            for (int ntl = 0; ntl < 4; ++ntl)
#pragma unroll
                for (int v = 0; v < 4; ++v) { aH[ntl][v] = 0; aM[ntl][v] = 0; }
#pragma unroll
            for (int kb = 0; kb < 4; ++kb) {
#pragma unroll
                for (int ntl = 0; ntl < 4; ++ntl) {
                    int nt = hf * 4 + ntl;
                    int a = (8 * nt + g) * ROWVI + kb * 8 + 2 * c;
                    uint2 b1 = *(const uint2*)&VA[a];
                    uint2 b2 = *(const uint2*)&VB[a];
                    mma_s8(aH[ntl], pf1[kb][0], pf1[kb][1],
                           pf1[kb][2], pf1[kb][3], b1.x, b1.y);
                    mma_s8(aM[ntl], pf1[kb][0], pf1[kb][1],
                           pf1[kb][2], pf1[kb][3], b2.x, b2.y);
                    mma_s8(aM[ntl], pf2[kb][0], pf2[kb][1],
                           pf2[kb][2], pf2[kb][3], b1.x, b1.y);
                }
            }
#pragma unroll
            for (int ntl = 0; ntl < 4; ++ntl) {
                int nt = hf * 4 + ntl;
#pragma unroll
                for (int v = 0; v < 4; ++v)
                    oa[nt][v] += (float)((aH[ntl][v] << 7) + aM[ntl][v]) * pvs;
            }
        }

        __syncthreads();
        if (kt + 2 <= qb) {
            attn_load_kv(kt + 2, s, tid, sbase, kag, kbg, vag, vbg);
            CP_COMMIT();
        }
    }

    // epilogue: out[b][n][h*64 + d]
    float i0 = 1.0f / l0, i1 = 1.0f / l1;
    int r0 = qb * 128 + 16 * w + g;
    float* o0 = out + ((size_t)b * NN + r0) * DD + h * 64;
    float* o1 = o0 + (size_t)8 * DD;
#pragma unroll
    for (int nt = 0; nt < 8; ++nt) {
        *(float2*)&o0[8 * nt + 2 * c] = make_float2(oa[nt][0] * i0, oa[nt][1] * i0);
        *(float2*)&o1[8 * nt + 2 * c] = make_float2(oa[nt][2] * i1, oa[nt][3] * i1);
    }
}

// ---------------------------------------------------------------------------
extern "C" void kernel_launch(void* const* d_in, const int* in_sizes, int n_in,
                              void* d_out, int out_size)
{
    const float* x = (const float*)d_in[0];   // [2,2048,1024] fp32
    const float* w = (const float*)d_in[1];   // [1024,3072] fp32
    float* out = (float*)d_out;               // [2,2048,1024] fp32
    (void)in_sizes; (void)n_in; (void)out_size;

    // int8 GEMM operand prep (prep_xi also resets g_gi)
    prep_xi<<<MM, 256>>>(x);
    w_absmax<<<D3 / 256, 256>>>(w);
    prep_wq<<<dim3(D3 / 32, DD / 32), dim3(32, 8)>>>(w);

    // int8x3 IMMA QKV GEMM (R13 config) with fused Q/K/V absmax
    cudaFuncSetAttribute(qkv_gemm_imma,
                         cudaFuncAttributeMaxDynamicSharedMemorySize,
                         GEMM_SMEM_TOTAL);
    qkv_gemm_imma<<<dim3(D3 / 128, MM / 128), 256, GEMM_SMEM_TOTAL>>>();

    // attention operand prep: int8 Q/K, int8 V transpose
    prep_attn_qki8<<<2048, 256>>>();
    prep_attn_vi8<<<dim3(NN / 64, HH, BB), 256>>>();

    // int8 QK^T + int8 PV flash attention (2 CTAs/SM)
    cudaFuncSetAttribute(attn_mma,
                         cudaFuncAttributeMaxDynamicSharedMemorySize,
                         ATT_SMEM_BYTES);
    attn_mma<<<dim3(NN / 128, HH, BB), 256, ATT_SMEM_BYTES>>>(out);
}

// round 17
// speedup vs baseline: 1.4597x; 1.0091x over previous
#include <cuda_runtime.h>
#include <cuda_bf16.h>
#include <cstdint>

// Problem constants
#define BB 2
#define NN 2048
#define HH 16
#define DH 64
#define DD 1024          // HH*DH
#define D3 3072          // 3*DD
#define MM 4096          // BB*NN
#define BHND ((size_t)BB * HH * NN * DH)

// Scratch: QKV laid out [part(q/k/v)][B][H][N][Dh], fp32
__device__ float g_qkv[3u * BB * HH * NN * DH];
// int8 GEMM operands
__device__ float  g_sx[MM];
__device__ float  g_sw[D3];
__device__ int8_t g_xa[(size_t)MM * DD];
__device__ int8_t g_xb[(size_t)MM * DD];
__device__ int8_t g_wa[(size_t)D3 * DD];
__device__ int8_t g_wb[(size_t)D3 * DD];
// global absmax of Q/K/V (float bits), computed in GEMM epilogue
__device__ int    g_gi[3];
// int8 attention operands (2-word, quad-permuted)
__device__ int8_t g_qa[BHND];                // [bh][n][d]
__device__ int8_t g_qb[BHND];
__device__ int8_t g_ka[BHND];
__device__ int8_t g_kb[BHND];
__device__ int8_t g_va[BHND];                // [bh][d][n] transposed
__device__ int8_t g_vb[BHND];

// ---------------------------------------------------------------------------
// helpers
// ---------------------------------------------------------------------------
#define CP_ASYNC16(dst_u32, gptr)                                              \
    asm volatile("cp.async.cg.shared.global [%0], [%1], 16;"                    \
                 :: "r"(dst_u32), "l"(__cvta_generic_to_global(gptr)))
#define CP_COMMIT() asm volatile("cp.async.commit_group;" ::: "memory")
#define CP_WAIT1()  asm volatile("cp.async.wait_group 1;" ::: "memory")
#define CP_WAIT0()  asm volatile("cp.async.wait_group 0;" ::: "memory")

__device__ __forceinline__ uint32_t smem_u32(const void* p) {
    uint32_t a;
    asm("{ .reg .u64 t; cvta.to.shared.u64 t, %1; cvt.u32.u64 %0, t; }"
        : "=r"(a) : "l"(p));
    return a;
}

// mma.sync m16n8k32 s8: d += a * b  (exact s32 accumulate)
__device__ __forceinline__ void mma_s8(int* d,
                                       uint32_t a0, uint32_t a1, uint32_t a2, uint32_t a3,
                                       uint32_t b0, uint32_t b1) {
    asm volatile(
        "mma.sync.aligned.m16n8k32.row.col.s32.s8.s8.s32 "
        "{%0,%1,%2,%3}, {%4,%5,%6,%7}, {%8,%9}, {%0,%1,%2,%3};"
        : "+r"(d[0]), "+r"(d[1]), "+r"(d[2]), "+r"(d[3])
        : "r"(a0), "r"(a1), "r"(a2), "r"(a3), "r"(b0), "r"(b1));
}

__device__ __forceinline__ int dpos8(int p) {   // dest slot of source quad p
    return ((p & 3) << 1) | (p >> 2);
}

// quantize x*inv_s into 2 int8 words: A = rn(x*inv_s) = 128*a1 + a2
__device__ __forceinline__ void quant2(float x, float inv_s, int& a1, int& a2) {
    int A = __float2int_rn(x * inv_s);
    a1 = __float2int_rn((float)A * (1.0f / 128.0f));
    a2 = A - (a1 << 7);
}

__device__ __forceinline__ uint32_t packq(int a0, int a1, int a2, int a3) {
    return (uint32_t)(uint8_t)(int8_t)a0 | ((uint32_t)(uint8_t)(int8_t)a1 << 8) |
           ((uint32_t)(uint8_t)(int8_t)a2 << 16) | ((uint32_t)(uint8_t)(int8_t)a3 << 24);
}

// ---------------------------------------------------------------------------
// prep kernels (unchanged, proven)
// ---------------------------------------------------------------------------
__global__ __launch_bounds__(256)
void prep_xi(const float* __restrict__ X)
{
    __shared__ float red[8];
    __shared__ float s_sh;
    const int row = blockIdx.x;
    const int t   = threadIdx.x;
    if (row == 0 && t < 3) g_gi[t] = 0;   // reset global absmax (pre-GEMM)
    float4 v = *(const float4*)(X + (size_t)row * DD + t * 4);
    float mx = fmaxf(fmaxf(fabsf(v.x), fabsf(v.y)), fmaxf(fabsf(v.z), fabsf(v.w)));
#pragma unroll
    for (int o = 16; o > 0; o >>= 1)
        mx = fmaxf(mx, __shfl_xor_sync(0xffffffffu, mx, o));
    if ((t & 31) == 0) red[t >> 5] = mx;
    __syncthreads();
    if (t == 0) {
        float m = red[0];
#pragma unroll
        for (int i = 1; i < 8; ++i) m = fmaxf(m, red[i]);
        s_sh = fmaxf(m, 1e-20f);
        g_sx[row] = s_sh;
    }
    __syncthreads();
    const float inv_s = 16256.0f / s_sh;

    int a1[4], a2[4];
    quant2(v.x, inv_s, a1[0], a2[0]);
    quant2(v.y, inv_s, a1[1], a2[1]);
    quant2(v.z, inv_s, a1[2], a2[2]);
    quant2(v.w, inv_s, a1[3], a2[3]);
    int widx = row * 256 + (t & ~7) + dpos8(t & 7);
    ((uint32_t*)g_xa)[widx] = packq(a1[0], a1[1], a1[2], a1[3]);
    ((uint32_t*)g_xb)[widx] = packq(a2[0], a2[1], a2[2], a2[3]);
}

__global__ __launch_bounds__(256)
void w_absmax(const float* __restrict__ W)
{
    int n = blockIdx.x * 256 + threadIdx.x;
    float m = 0.0f;
    for (int k = 0; k < DD; ++k)
        m = fmaxf(m, fabsf(W[(size_t)k * D3 + n]));
    g_sw[n] = fmaxf(m, 1e-20f);
}

__device__ __forceinline__ int kpermq(int k) {   // k in 0..31
    return ((dpos8((k >> 2) & 7)) << 2) | (k & 3);
}

__global__ __launch_bounds__(256)
void prep_wq(const float* __restrict__ W)
{
    __shared__ float t[32][33];
    const int n0 = blockIdx.x * 32;
    const int k0 = blockIdx.y * 32;
    const int tx = threadIdx.x, ty = threadIdx.y;   // (32, 8)
#pragma unroll
    for (int rr = 0; rr < 32; rr += 8)
        t[ty + rr][tx] = W[(size_t)(k0 + ty + rr) * D3 + n0 + tx];
    __syncthreads();
#pragma unroll
    for (int rr = 0; rr < 32; rr += 8) {
        int n = n0 + ty + rr;
        float inv_s = 16256.0f / g_sw[n];
        float v = t[tx][ty + rr];
        int b1, b2;
        quant2(v, inv_s, b1, b2);
        size_t base = (size_t)n * DD + k0 + kpermq(tx);
        g_wa[base] = (int8_t)b1;
        g_wb[base] = (int8_t)b2;
    }
}

// ---------------------------------------------------------------------------
// int8x3 QKV GEMM via mma.sync m16n8k32.
// CTA tile 128x64, 256 threads (warps 4m x 2n, warp tile 32x32), k-chunk 32,
// cp.async double buffer. Stage 18KB x2 = 36KB/CTA -> 2 CTAs/SM so one CTA's
// mma phase overlaps the other's barrier/load phase.
// ROWG=12 b32 rows: 16B-aligned cp.async dsts + 2-phase bank tiling (6g+c).
// ---------------------------------------------------------------------------
#define ROWG 12                 // b32 per int8 row (32 data + 16 pad bytes)
#define GOA1 0
#define GOA2 1536
#define GOB1 3072
#define GOB2 3840
#define GST_B32 4608            // 18KB per stage
#define GEMM_SMEM_TOTAL (2 * GST_B32 * 4)

__device__ __forceinline__ void gemm_load(int kt, uint32_t st_u32,
                                          int m0, int n0, int tid)
{
    const int k0 = kt * 32;
    // A: 128 rows x 32B x 2 halves; 256 threads -> 1 chunk per half each
    int row = tid >> 1;
    int ch  = tid & 1;
    uint32_t doff = (uint32_t)(row * ROWG + ch * 4) * 4;
    CP_ASYNC16(st_u32 + GOA1 * 4 + doff, g_xa + (size_t)(m0 + row) * DD + k0 + ch * 16);
    CP_ASYNC16(st_u32 + GOA2 * 4 + doff, g_xb + (size_t)(m0 + row) * DD + k0 + ch * 16);
    // B: 64 rows x 32B x 2 halves; 256 threads -> 1 chunk each
    int half = tid >> 7;
    int j    = tid & 127;
    int brow = j >> 1;
    int bch  = j & 1;
    uint32_t bdoff = (uint32_t)(brow * ROWG + bch * 4) * 4;
    const int8_t* src = half ? g_wb : g_wa;
    uint32_t ob = (half ? GOB2 : GOB1) * 4;
    CP_ASYNC16(st_u32 + ob + bdoff, src + (size_t)(n0 + brow) * DD + k0 + bch * 16);
}

__global__ __launch_bounds__(256, 2)
void qkv_gemm_imma()
{
    extern __shared__ float sm[];
    const int tid   = threadIdx.x;
    const int wid   = tid >> 5;
    const int lane  = tid & 31;
    const int warpm = wid & 3;        // 4 warps over m (32 rows each)
    const int warpn = wid >> 2;       // 2 warps over n (32 cols each)
    const int c     = lane & 3;
    const int g     = lane >> 2;
    const int n0    = blockIdx.x * 64;
    const int m0    = blockIdx.y * 128;

    const uint32_t* st[2] = {(const uint32_t*)sm, (const uint32_t*)sm + GST_B32};
    uint32_t stu[2] = {smem_u32(sm), smem_u32(sm + GST_B32)};

    int accH[2][4][4];   // a1*b1 (scale 16384)
    int accM[2][4][4];   // a1*b2 + a2*b1 (scale 128)
#pragma unroll
    for (int mt = 0; mt < 2; ++mt)
#pragma unroll
        for (int nt = 0; nt < 4; ++nt)
#pragma unroll
            for (int v = 0; v < 4; ++v) { accH[mt][nt][v] = 0; accM[mt][nt][v] = 0; }

    gemm_load(0, stu[0], m0, n0, tid); CP_COMMIT();
    gemm_load(1, stu[1], m0, n0, tid); CP_COMMIT();

    const int kc = 2 * c;
    for (int kt = 0; kt < 32; ++kt) {
        const int buf = kt & 1;
        if (kt < 30) { CP_WAIT1(); } else { CP_WAIT0(); }
        __syncthreads();

        const uint32_t* S = st[buf];
        uint2 a1f[2][2], a2f[2][2];
#pragma unroll
        for (int mt = 0; mt < 2; ++mt) {
            int rbase = warpm * 32 + mt * 16 + g;
            a1f[mt][0] = *(const uint2*)&S[GOA1 + rbase * ROWG + kc];
            a1f[mt][1] = *(const uint2*)&S[GOA1 + (rbase + 8) * ROWG + kc];
            a2f[mt][0] = *(const uint2*)&S[GOA2 + rbase * ROWG + kc];
            a2f[mt][1] = *(const uint2*)&S[GOA2 + (rbase + 8) * ROWG + kc];
        }
#pragma unroll
        for (int nt = 0; nt < 4; ++nt) {
            int nb = (warpn * 32 + nt * 8 + g) * ROWG + kc;
            uint2 b1 = *(const uint2*)&S[GOB1 + nb];
            uint2 b2 = *(const uint2*)&S[GOB2 + nb];
#pragma unroll
            for (int mt = 0; mt < 2; ++mt) {
                mma_s8(accH[mt][nt], a1f[mt][0].x, a1f[mt][1].x,
                       a1f[mt][0].y, a1f[mt][1].y, b1.x, b1.y);
                mma_s8(accM[mt][nt], a1f[mt][0].x, a1f[mt][1].x,
                       a1f[mt][0].y, a1f[mt][1].y, b2.x, b2.y);
                mma_s8(accM[mt][nt], a2f[mt][0].x, a2f[mt][1].x,
                       a2f[mt][0].y, a2f[mt][1].y, b1.x, b1.y);
            }
        }
        __syncthreads();
        if (kt + 2 < 32) {
            gemm_load(kt + 2, stu[buf], m0, n0, tid);
            CP_COMMIT();
        }
    }

    // epilogue: rescale, scatter into g_qkv, and track |max| for this part
    const float qs = 128.0f / (16256.0f * 16256.0f);   // pre-merged (<<7) scale
    const int part = n0 >> 10;
    float lmax = 0.0f;
#pragma unroll
    for (int mt = 0; mt < 2; ++mt) {
        int mg0 = m0 + warpm * 32 + mt * 16 + g;
        float sx0 = g_sx[mg0] * qs;
        float sx1 = g_sx[mg0 + 8] * qs;
#pragma unroll
        for (int nt = 0; nt < 4; ++nt) {
            int colg = n0 + warpn * 32 + nt * 8 + 2 * c;
            float sw0 = g_sw[colg];
            float sw1 = g_sw[colg + 1];
            float r0 = (float)((accH[mt][nt][0] << 7) + accM[mt][nt][0]) * sx0 * sw0;
            float r1 = (float)((accH[mt][nt][1] << 7) + accM[mt][nt][1]) * sx0 * sw1;
            float r2 = (float)((accH[mt][nt][2] << 7) + accM[mt][nt][2]) * sx1 * sw0;
            float r3 = (float)((accH[mt][nt][3] << 7) + accM[mt][nt][3]) * sx1 * sw1;
            lmax = fmaxf(lmax, fmaxf(fmaxf(fabsf(r0), fabsf(r1)),
                                     fmaxf(fabsf(r2), fabsf(r3))));
            int pc   = colg & 1023;
            int h    = pc >> 6;
            int dh   = pc & 63;
            int b    = mg0 >> 11;
            int seq  = mg0 & 2047;
            float* dst = g_qkv + ((size_t)((part * BB + b) * HH + h) * NN + seq) * DH + dh;
            *(float2*)dst = make_float2(r0, r1);
            *(float2*)(dst + (size_t)8 * DH) = make_float2(r2, r3);
        }
    }
    // block absmax -> g_gi[part]
#pragma unroll
    for (int o = 16; o > 0; o >>= 1)
        lmax = fmaxf(lmax, __shfl_xor_sync(0xffffffffu, lmax, o));
    __syncthreads();
    if (lane == 0) sm[wid] = lmax;
    __syncthreads();
    if (tid == 0) {
        float m = sm[0];
#pragma unroll
        for (int i = 1; i < 8; ++i) m = fmaxf(m, sm[i]);
        atomicMax(&g_gi[part], __float_as_int(m));
    }
}

// ---------------------------------------------------------------------------
// Attention prep: int8 2-word quantize Q/K (quad-permuted), int8 V transposed
// ---------------------------------------------------------------------------
__global__ __launch_bounds__(256)
void prep_attn_qki8()
{
    int cidx = blockIdx.x * 256 + threadIdx.x;       // 0..524287
    int row  = cidx >> 2;                            // Q rows then K rows
    int ch   = cidx & 3;
    int part = row >> 16;                            // 0 = Q, 1 = K
    float gs = __int_as_float(g_gi[part]);
    float inv_s = 16256.0f / fmaxf(gs, 1e-20f);
    const float* src = g_qkv + (size_t)row * 64 + ch * 16;
    float s[16];
    *(float4*)(s)      = ((const float4*)src)[0];
    *(float4*)(s + 4)  = ((const float4*)src)[1];
    *(float4*)(s + 8)  = ((const float4*)src)[2];
    *(float4*)(s + 12) = ((const float4*)src)[3];
    uint32_t* da = (part ? (uint32_t*)g_ka : (uint32_t*)g_qa);
    uint32_t* db = (part ? (uint32_t*)g_kb : (uint32_t*)g_qb);
    int rbase = (row & 65535) * 16 + (ch >> 1) * 8 + (ch & 1);
#pragma unroll
    for (int i = 0; i < 4; ++i) {
        int a1[4], a2[4];
        quant2(s[4 * i + 0], inv_s, a1[0], a2[0]);
        quant2(s[4 * i + 1], inv_s, a1[1], a2[1]);
        quant2(s[4 * i + 2], inv_s, a1[2], a2[2]);
        quant2(s[4 * i + 3], inv_s, a1[3], a2[3]);
        int dst = rbase + 2 * i;
        da[dst] = packq(a1[0], a1[1], a1[2], a1[3]);
        db[dst] = packq(a2[0], a2[1], a2[2], a2[3]);
    }
}

__global__ __launch_bounds__(256)
void prep_attn_vi8()
{
    __shared__ float t[64][65];
    const int n0 = blockIdx.x * 64;
    const int h  = blockIdx.y;
    const int b  = blockIdx.z;
    const int bh = b * HH + h;
    const int tid = threadIdx.x;
    const float* Vg = g_qkv + (size_t)((2 * BB + b) * HH + h) * NN * DH;
#pragma unroll
    for (int i = 0; i < 16; ++i) {
        int lin = i * 256 + tid;
        int r = lin >> 6, d = lin & 63;
        t[r][d] = Vg[(size_t)(n0 + r) * 64 + d];
    }
    __syncthreads();
    const float gv = __int_as_float(g_gi[2]);
    const float inv_s = 16256.0f / fmaxf(gv, 1e-20f);
    const int d  = tid >> 2;
    const int qq = tid & 3;
    uint32_t* va = (uint32_t*)g_va + ((size_t)bh * 64 + d) * 512;
    uint32_t* vb = (uint32_t*)g_vb + ((size_t)bh * 64 + d) * 512;
#pragma unroll
    for (int i = 0; i < 4; ++i) {
        int ql = qq * 4 + i;              // local quad (keys 4ql..4ql+3)
        int a1[4], a2[4];
#pragma unroll
        for (int j = 0; j < 4; ++j)
            quant2(t[4 * ql + j][d], inv_s, a1[j], a2[j]);
        int qg  = (n0 >> 2) + ql;
        int dst = (qg & ~7) + dpos8(qg & 7);
        va[dst] = packq(a1[0], a1[1], a1[2], a1[3]);
        vb[dst] = packq(a2[0], a2[1], a2[2], a2[3]);
    }
}

// ---------------------------------------------------------------------------
// Causal flash attention: int8x3 QK^T + int8x3 PV (all m16n8k32).
// CTA = 256 thr (8 warps), q-tile 128; smem 76KB -> 2 CTAs/SM.
// (Unchanged from R16, proven.)
// ---------------------------------------------------------------------------
#define ROWKI 20                // b32 per K int8 smem row
#define ROWVI 36                // b32 per V int8 smem row (32 data + 4 pad)
#define KSTGI (128 * ROWKI)     // 2560 b32
#define VSTGI (64 * ROWVI)      // 2304 b32
#define ATT_SMEM_B32 (4 * KSTGI + 4 * VSTGI)
#define ATT_SMEM_BYTES (ATT_SMEM_B32 * 4)

__device__ __forceinline__ void attn_load_kv(
    int kt, int s, int tid, uint32_t sbase,
    const int8_t* kag, const int8_t* kbg,
    const uint32_t* vag, const uint32_t* vbg)
{
    const uint32_t oka = (s ? KSTGI : 0) * 4;
    const uint32_t okb = (2 * KSTGI + (s ? KSTGI : 0)) * 4;
    const uint32_t ova = (4 * KSTGI + (s ? VSTGI : 0)) * 4;
    const uint32_t ovb = (4 * KSTGI + 2 * VSTGI + (s ? VSTGI : 0)) * 4;
#pragma unroll
    for (int it = 0; it < 2; ++it) {
        int idx = it * 256 + tid;
        int row = idx >> 2, ch = idx & 3;
        uint32_t doff = (uint32_t)(row * ROWKI + ch * 4) * 4;
        size_t so = (size_t)(kt * 128 + row) * 64 + ch * 16;
        CP_ASYNC16(sbase + oka + doff, kag + so);
        CP_ASYNC16(sbase + okb + doff, kbg + so);
    }
#pragma unroll
    for (int it = 0; it < 2; ++it) {
        int idx = it * 256 + tid;
        int row = idx >> 3, ch = idx & 7;
        uint32_t doff = (uint32_t)(row * ROWVI + ch * 4) * 4;
        size_t so = (size_t)row * 512 + kt * 32 + ch * 4;   // b32 units
        CP_ASYNC16(sbase + ova + doff, vag + so);
        CP_ASYNC16(sbase + ovb + doff, vbg + so);
    }
}

__global__ __launch_bounds__(256, 2)
void attn_mma(float* __restrict__ out)
{
    extern __shared__ float smf[];
    uint32_t* su = (uint32_t*)smf;
    const uint32_t sbase = smem_u32(smf);
    const int tid  = threadIdx.x;
    const int w    = tid >> 5;
    const int lane = tid & 31;
    const int g    = lane >> 2;
    const int c    = lane & 3;
    const int qb   = (int)gridDim.x - 1 - blockIdx.x;   // heavy tiles first
    const int h    = blockIdx.y;
    const int b    = blockIdx.z;
    const int bh   = b * HH + h;

    const int8_t* kag = g_ka + (size_t)bh * NN * DH;
    const int8_t* kbg = g_kb + (size_t)bh * NN * DH;
    const uint32_t* vag = (const uint32_t*)g_va + (size_t)bh * 64 * 512;
    const uint32_t* vbg = (const uint32_t*)g_vb + (size_t)bh * 64 * 512;

    // pre-merged (<<7) scales
    const float fs = __int_as_float(g_gi[0]) * __int_as_float(g_gi[1]) *
                     (128.0f / (16256.0f * 16256.0f)) * 0.125f;
    const float pvs = __int_as_float(g_gi[2]) * 128.0f / (16256.0f * 16256.0f);

    // Q int8 fragments, register-resident
    uint2 qfa[2][2], qfb[2][2];
    {
        const uint32_t* qa32 = (const uint32_t*)g_qa;
        const uint32_t* qb32 = (const uint32_t*)g_qb;
        size_t r0 = (size_t)bh * NN + qb * 128 + w * 16 + g;
#pragma unroll
        for (int kd = 0; kd < 2; ++kd) {
            qfa[kd][0] = *(const uint2*)&qa32[r0 * 16 + kd * 8 + 2 * c];
            qfa[kd][1] = *(const uint2*)&qa32[(r0 + 8) * 16 + kd * 8 + 2 * c];
            qfb[kd][0] = *(const uint2*)&qb32[r0 * 16 + kd * 8 + 2 * c];
            qfb[kd][1] = *(const uint2*)&qb32[(r0 + 8) * 16 + kd * 8 + 2 * c];
        }
    }

    float oa[8][4];
#pragma unroll
    for (int nt = 0; nt < 8; ++nt)
#pragma unroll
        for (int v = 0; v < 4; ++v) oa[nt][v] = 0.0f;
    float m0 = -1e30f, m1 = -1e30f, l0 = 0.0f, l1 = 0.0f;

    const int srcA = (lane & ~3) | ((2 * c) & 3);
    const int srcB = (lane & ~3) | ((2 * c + 1) & 3);
    const bool selhi = (c >> 1);

    attn_load_kv(0, 0, tid, sbase, kag, kbg, vag, vbg);
    CP_COMMIT();
    if (qb >= 1) attn_load_kv(1, 1, tid, sbase, kag, kbg, vag, vbg);
    CP_COMMIT();

    for (int kt = 0; kt <= qb; ++kt) {
        if (kt < qb) { CP_WAIT1(); } else { CP_WAIT0(); }
        __syncthreads();
        const int s = kt & 1;
        const uint32_t* KA = su + (s ? KSTGI : 0);
        const uint32_t* KB = su + 2 * KSTGI + (s ? KSTGI : 0);
        const uint32_t* VA = su + 4 * KSTGI + (s ? VSTGI : 0);
        const uint32_t* VB = su + 4 * KSTGI + 2 * VSTGI + (s ? VSTGI : 0);

        // S = Q @ K^T via int8x3 (two 8-nt halves), integer-merged rescale
        float sa[16][4];
#pragma unroll
        for (int hf = 0; hf < 2; ++hf) {
            int accH[8][4], accM[8][4];
#pragma unroll
            for (int nt = 0; nt < 8; ++nt)
#pragma unroll
                for (int v = 0; v < 4; ++v) { accH[nt][v] = 0; accM[nt][v] = 0; }
#pragma unroll
            for (int kd = 0; kd < 2; ++kd) {
#pragma unroll
                for (int nt = 0; nt < 8; ++nt) {
                    int ntg = hf * 8 + nt;
                    int a = (8 * ntg + g) * ROWKI + kd * 8 + 2 * c;
                    uint2 b1 = *(const uint2*)&KA[a];
                    uint2 b2 = *(const uint2*)&KB[a];
                    mma_s8(accH[nt], qfa[kd][0].x, qfa[kd][1].x,
                           qfa[kd][0].y, qfa[kd][1].y, b1.x, b1.y);
                    mma_s8(accM[nt], qfa[kd][0].x, qfa[kd][1].x,
                           qfa[kd][0].y, qfa[kd][1].y, b2.x, b2.y);
                    mma_s8(accM[nt], qfb[kd][0].x, qfb[kd][1].x,
                           qfb[kd][0].y, qfb[kd][1].y, b1.x, b1.y);
                }
            }
#pragma unroll
            for (int nt = 0; nt < 8; ++nt) {
                int ntg = hf * 8 + nt;
#pragma unroll
                for (int v = 0; v < 4; ++v)
                    sa[ntg][v] = (float)((accH[nt][v] << 7) + accM[nt][v]) * fs;
            }
        }

        // causal mask on the diagonal tile
        if (kt == qb) {
            int r0 = 16 * w + g, r1 = r0 + 8;
#pragma unroll
            for (int nt = 0; nt < 16; ++nt) {
                int c0 = 8 * nt + 2 * c, c1 = c0 + 1;
                if (c0 > r0) sa[nt][0] = -1e30f;
                if (c1 > r0) sa[nt][1] = -1e30f;
                if (c0 > r1) sa[nt][2] = -1e30f;
                if (c1 > r1) sa[nt][3] = -1e30f;
            }
        }

        // warp-local online softmax with fused fast P quantization
        float mx0 = -1e30f, mx1 = -1e30f;
#pragma unroll
        for (int nt = 0; nt < 16; ++nt) {
            mx0 = fmaxf(mx0, fmaxf(sa[nt][0], sa[nt][1]));
            mx1 = fmaxf(mx1, fmaxf(sa[nt][2], sa[nt][3]));
        }
        mx0 = fmaxf(mx0, __shfl_xor_sync(0xffffffffu, mx0, 1));
        mx0 = fmaxf(mx0, __shfl_xor_sync(0xffffffffu, mx0, 2));
        mx1 = fmaxf(mx1, __shfl_xor_sync(0xffffffffu, mx1, 1));
        mx1 = fmaxf(mx1, __shfl_xor_sync(0xffffffffu, mx1, 2));
        float mn0 = fmaxf(m0, mx0), mn1 = fmaxf(m1, mx1);
        float cr0 = __expf(m0 - mn0), cr1 = __expf(m1 - mn1);
        m0 = mn0; m1 = mn1;
        float rs0 = 0.0f, rs1 = 0.0f;
        uint32_t vq[2][16];
#pragma unroll
        for (int nt = 0; nt < 16; ++nt) {
            float e0 = __expf(sa[nt][0] - mn0); rs0 += e0;
            float e1 = __expf(sa[nt][1] - mn0); rs0 += e1;
            float e2 = __expf(sa[nt][2] - mn1); rs1 += e2;
            float e3 = __expf(sa[nt][3] - mn1); rs1 += e3;
            int A0 = __float2int_rz(e0 * 16256.0f);
            int A1 = __float2int_rz(e1 * 16256.0f);
            int A2 = __float2int_rz(e2 * 16256.0f);
            int A3 = __float2int_rz(e3 * 16256.0f);
            vq[0][nt] = (uint32_t)(A0 >> 7) | ((uint32_t)(A0 & 127) << 8) |
                        ((uint32_t)(A1 >> 7) << 16) | ((uint32_t)(A1 & 127) << 24);
            vq[1][nt] = (uint32_t)(A2 >> 7) | ((uint32_t)(A2 & 127) << 8) |
                        ((uint32_t)(A3 >> 7) << 16) | ((uint32_t)(A3 & 127) << 24);
        }
        rs0 += __shfl_xor_sync(0xffffffffu, rs0, 1);
        rs0 += __shfl_xor_sync(0xffffffffu, rs0, 2);
        rs1 += __shfl_xor_sync(0xffffffffu, rs1, 1);
        rs1 += __shfl_xor_sync(0xffffffffu, rs1, 2);
        l0 = l0 * cr0 + rs0;
        l1 = l1 * cr1 + rs1;
#pragma unroll
        for (int nt = 0; nt < 8; ++nt) {
            oa[nt][0] *= cr0; oa[nt][1] *= cr0;
            oa[nt][2] *= cr1; oa[nt][3] *= cr1;
        }

        // build P fragments for m16n8k32 (keys quad 4c.., 16+4c..)
        uint32_t pf1[4][4], pf2[4][4];
#pragma unroll
        for (int kb = 0; kb < 4; ++kb) {
#pragma unroll
            for (int rh = 0; rh < 2; ++rh) {
                uint32_t rA0 = __shfl_sync(0xffffffffu, vq[rh][4 * kb + 0], srcA);
                uint32_t rA1 = __shfl_sync(0xffffffffu, vq[rh][4 * kb + 1], srcA);
                uint32_t rB0 = __shfl_sync(0xffffffffu, vq[rh][4 * kb + 0], srcB);
                uint32_t rB1 = __shfl_sync(0xffffffffu, vq[rh][4 * kb + 1], srcB);
                uint32_t rA = selhi ? rA1 : rA0;
                uint32_t rB = selhi ? rB1 : rB0;
                pf1[kb][rh]     = __byte_perm(rA, rB, 0x6420);
                pf2[kb][rh]     = __byte_perm(rA, rB, 0x7531);
                uint32_t rA2 = __shfl_sync(0xffffffffu, vq[rh][4 * kb + 2], srcA);
                uint32_t rA3 = __shfl_sync(0xffffffffu, vq[rh][4 * kb + 3], srcA);
                uint32_t rB2 = __shfl_sync(0xffffffffu, vq[rh][4 * kb + 2], srcB);
                uint32_t rB3 = __shfl_sync(0xffffffffu, vq[rh][4 * kb + 3], srcB);
                uint32_t rAh = selhi ? rA3 : rA2;
                uint32_t rBh = selhi ? rB3 : rB2;
                pf1[kb][2 + rh] = __byte_perm(rAh, rBh, 0x6420);
                pf2[kb][2 + rh] = __byte_perm(rAh, rBh, 0x7531);
            }
        }

        // O += P @ V via int8x3, two 4-nt halves, integer-merged rescale
#pragma unroll
        for (int hf = 0; hf < 2; ++hf) {
            int aH[4][4], aM[4][4];
#pragma unroll
            for (int ntl = 0; ntl < 4; ++ntl)
#pragma unroll
                for (int v = 0; v < 4; ++v) { aH[ntl][v] = 0; aM[ntl][v] = 0; }
#pragma unroll
            for (int kb = 0; kb < 4; ++kb) {
#pragma unroll
                for (int ntl = 0; ntl < 4; ++ntl) {
                    int nt = hf * 4 + ntl;
                    int a = (8 * nt + g) * ROWVI + kb * 8 + 2 * c;
                    uint2 b1 = *(const uint2*)&VA[a];
                    uint2 b2 = *(const uint2*)&VB[a];
                    mma_s8(aH[ntl], pf1[kb][0], pf1[kb][1],
                           pf1[kb][2], pf1[kb][3], b1.x, b1.y);
                    mma_s8(aM[ntl], pf1[kb][0], pf1[kb][1],
                           pf1[kb][2], pf1[kb][3], b2.x, b2.y);
                    mma_s8(aM[ntl], pf2[kb][0], pf2[kb][1],
                           pf2[kb][2], pf2[kb][3], b1.x, b1.y);
                }
            }
#pragma unroll
            for (int ntl = 0; ntl < 4; ++ntl) {
                int nt = hf * 4 + ntl;
#pragma unroll
                for (int v = 0; v < 4; ++v)
                    oa[nt][v] += (float)((aH[ntl][v] << 7) + aM[ntl][v]) * pvs;
            }
        }

        __syncthreads();
        if (kt + 2 <= qb) {
            attn_load_kv(kt + 2, s, tid, sbase, kag, kbg, vag, vbg);
            CP_COMMIT();
        }
    }

    // epilogue: out[b][n][h*64 + d]
    float i0 = 1.0f / l0, i1 = 1.0f / l1;
    int r0 = qb * 128 + 16 * w + g;
    float* o0 = out + ((size_t)b * NN + r0) * DD + h * 64;
    float* o1 = o0 + (size_t)8 * DD;
#pragma unroll
    for (int nt = 0; nt < 8; ++nt) {
        *(float2*)&o0[8 * nt + 2 * c] = make_float2(oa[nt][0] * i0, oa[nt][1] * i0);
        *(float2*)&o1[8 * nt + 2 * c] = make_float2(oa[nt][2] * i1, oa[nt][3] * i1);
    }
}

// ---------------------------------------------------------------------------
extern "C" void kernel_launch(void* const* d_in, const int* in_sizes, int n_in,
                              void* d_out, int out_size)
{
    const float* x = (const float*)d_in[0];   // [2,2048,1024] fp32
    const float* w = (const float*)d_in[1];   // [1024,3072] fp32
    float* out = (float*)d_out;               // [2,2048,1024] fp32
    (void)in_sizes; (void)n_in; (void)out_size;

    // int8 GEMM operand prep (prep_xi also resets g_gi)
    prep_xi<<<MM, 256>>>(x);
    w_absmax<<<D3 / 256, 256>>>(w);
    prep_wq<<<dim3(D3 / 32, DD / 32), dim3(32, 8)>>>(w);

    // int8x3 IMMA QKV GEMM, CTA 128x64, 2 CTAs/SM, fused Q/K/V absmax
    cudaFuncSetAttribute(qkv_gemm_imma,
                         cudaFuncAttributeMaxDynamicSharedMemorySize,
                         GEMM_SMEM_TOTAL);
    qkv_gemm_imma<<<dim3(D3 / 64, MM / 128), 256, GEMM_SMEM_TOTAL>>>();

    // attention operand prep: int8 Q/K, int8 V transpose
    prep_attn_qki8<<<2048, 256>>>();
    prep_attn_vi8<<<dim3(NN / 64, HH, BB), 256>>>();

    // int8 QK^T + int8 PV flash attention (2 CTAs/SM)
    cudaFuncSetAttribute(attn_mma,
                         cudaFuncAttributeMaxDynamicSharedMemorySize,
                         ATT_SMEM_BYTES);
    attn_mma<<<dim3(NN / 128, HH, BB), 256, ATT_SMEM_BYTES>>>(out);
}